// round 1
// baseline (speedup 1.0000x reference)
#include <cuda_runtime.h>
#include <cuda_bf16.h>
#include <math.h>

// ---------------------------------------------------------------------------
// Problem constants
// ---------------------------------------------------------------------------
#define BATCH 8
#define CIN   512
#define CI    128
#define CK    16
#define NC    19
#define HH    64
#define WW    64
#define NPIX  4096          // 64*64
#define FEAT_ELEMS (BATCH * CI * NPIX)   // 4,194,304

// ---------------------------------------------------------------------------
// Scratch (device globals -- no runtime allocation allowed)
// ---------------------------------------------------------------------------
__device__ float g_featp1[FEAT_ELEMS];
__device__ float g_featc1[FEAT_ELEMS];
__device__ float g_qb[BATCH * CK * NPIX];
__device__ float g_kc[BATCH * CK * NPIX];
__device__ float g_vd[FEAT_ELEMS];
__device__ float g_pam[FEAT_ELEMS];
__device__ float g_cam[FEAT_ELEMS];
__device__ float g_featp2[FEAT_ELEMS];
__device__ float g_featc2[FEAT_ELEMS];
__device__ float g_energy[BATCH * CI * CI];
__device__ float g_attn[BATCH * CI * CI];

__device__ __forceinline__ float sigmoidf_(float x) {
    return 1.0f / (1.0f + __expf(-x));
}

// ---------------------------------------------------------------------------
// conv3x3 (SAME) + folded BN + ReLU.
// grid: (COUT/32, 16 spatial tiles, BATCH); block: 256
// Tile: 32 out channels x (8 rows x 32 cols). ci chunked by 4.
// ---------------------------------------------------------------------------
template<int CIN_T>
__global__ void conv3x3_bnrelu_kernel(const float* __restrict__ x,
                                      const float* __restrict__ Wt,
                                      const float* __restrict__ bn,
                                      float* __restrict__ out) {
    const int co_base = blockIdx.x * 32;
    const int sp      = blockIdx.y;           // 0..15
    const int b       = blockIdx.z;
    const int th0     = (sp >> 1) * 8;        // tile row base
    const int tw0     = (sp & 1) * 32;        // tile col base
    const int tid     = threadIdx.x;
    const int wcol    = tid & 31;             // 0..31  (output column in tile)
    const int cog     = tid >> 5;             // 0..7   (4 out channels each)

    __shared__ __align__(16) float Xs[4][10][34];
    __shared__ __align__(16) float Ws[4][9][32];

    float acc[4][8];
#pragma unroll
    for (int i = 0; i < 4; i++)
#pragma unroll
        for (int r = 0; r < 8; r++) acc[i][r] = 0.0f;

    for (int ci0 = 0; ci0 < CIN_T; ci0 += 4) {
        // ---- load input patch (with halo, zero padded) ----
        for (int idx = tid; idx < 4 * 10 * 34; idx += 256) {
            int ci  = idx / 340;
            int rem = idx % 340;
            int r   = rem / 34;
            int c   = rem % 34;
            int gh  = th0 + r - 1;
            int gw  = tw0 + c - 1;
            float v = 0.0f;
            if ((unsigned)gh < 64u && (unsigned)gw < 64u)
                v = x[(((size_t)b * CIN_T + ci0 + ci) * 64 + gh) * 64 + gw];
            Xs[ci][r][c] = v;
        }
        // ---- load weight chunk (coalesced: 36 contiguous floats per co) ----
        for (int idx = tid; idx < 32 * 36; idx += 256) {
            int co_l = idx / 36;
            int rem  = idx % 36;
            int ci   = rem / 9;
            int k    = rem % 9;
            Ws[ci][k][co_l] =
                Wt[((size_t)(co_base + co_l) * CIN_T + ci0 + ci) * 9 + k];
        }
        __syncthreads();

#pragma unroll
        for (int ci = 0; ci < 4; ci++) {
#pragma unroll
            for (int kh = 0; kh < 3; kh++) {
                float xa[8], xb[8], xc[8];
#pragma unroll
                for (int r = 0; r < 8; r++) {
                    xa[r] = Xs[ci][r + kh][wcol];
                    xb[r] = Xs[ci][r + kh][wcol + 1];
                    xc[r] = Xs[ci][r + kh][wcol + 2];
                }
                const float4 w0 = *(const float4*)&Ws[ci][kh * 3 + 0][cog * 4];
                const float4 w1 = *(const float4*)&Ws[ci][kh * 3 + 1][cog * 4];
                const float4 w2 = *(const float4*)&Ws[ci][kh * 3 + 2][cog * 4];
#pragma unroll
                for (int r = 0; r < 8; r++) {
                    acc[0][r] += w0.x * xa[r] + w1.x * xb[r] + w2.x * xc[r];
                    acc[1][r] += w0.y * xa[r] + w1.y * xb[r] + w2.y * xc[r];
                    acc[2][r] += w0.z * xa[r] + w1.z * xb[r] + w2.z * xc[r];
                    acc[3][r] += w0.w * xa[r] + w1.w * xb[r] + w2.w * xc[r];
                }
            }
        }
        __syncthreads();
    }

    // ---- epilogue: BN + ReLU ----
#pragma unroll
    for (int i = 0; i < 4; i++) {
        int co   = co_base + cog * 4 + i;
        float sc = bn[co];
        float sh = bn[128 + co];
#pragma unroll
        for (int r = 0; r < 8; r++) {
            int h = th0 + r;
            int w = tw0 + wcol;
            float v = acc[i][r] * sc + sh;
            out[(((size_t)b * 128 + co) * 64 + h) * 64 + w] = fmaxf(v, 0.0f);
        }
    }
}

// ---------------------------------------------------------------------------
// PAM query/key projections: b_ = Wb@y + bb, c_ = Wc@y + bc  (16 ch each)
// grid: (32, BATCH); block 128; each thread = 1 pixel
// ---------------------------------------------------------------------------
__global__ void pam_bc_kernel(const float* __restrict__ y,
                              const float* __restrict__ Wb, const float* __restrict__ bb,
                              const float* __restrict__ Wc, const float* __restrict__ bc,
                              float* __restrict__ outb, float* __restrict__ outc) {
    const int b  = blockIdx.y;
    const int n0 = blockIdx.x * 128;
    const int tid = threadIdx.x;

    __shared__ float Wbs[16][128];
    __shared__ float Wcs[16][128];
    for (int i = tid; i < 16 * 128; i += 128) {
        Wbs[i >> 7][i & 127] = Wb[i];
        Wcs[i >> 7][i & 127] = Wc[i];
    }
    __syncthreads();

    float ab[16], ac[16];
#pragma unroll
    for (int o = 0; o < 16; o++) { ab[o] = bb[o]; ac[o] = bc[o]; }

    const float* yp = y + (size_t)b * 128 * NPIX + n0 + tid;
    for (int c = 0; c < 128; c++) {
        float v = yp[(size_t)c * NPIX];
#pragma unroll
        for (int o = 0; o < 16; o++) {
            ab[o] += Wbs[o][c] * v;
            ac[o] += Wcs[o][c] * v;
        }
    }
#pragma unroll
    for (int o = 0; o < 16; o++) {
        outb[((size_t)b * 16 + o) * NPIX + n0 + tid] = ab[o];
        outc[((size_t)b * 16 + o) * NPIX + n0 + tid] = ac[o];
    }
}

// ---------------------------------------------------------------------------
// PAM value projection: d_ = Wd@y + bd  (128 ch)
// grid: (32, BATCH); block 256: (px = tid&127, half = tid>>7 covering 64 ch)
// ---------------------------------------------------------------------------
__global__ void pam_d_kernel(const float* __restrict__ y,
                             const float* __restrict__ Wd,
                             const float* __restrict__ bd,
                             float* __restrict__ outd) {
    __shared__ float Ws[128][32];
    const int tid = threadIdx.x;
    const int b   = blockIdx.y;
    const int n0  = blockIdx.x * 128;
    const int px  = n0 + (tid & 127);
    const int half = (tid >> 7) * 64;

    float acc[64];
#pragma unroll
    for (int o = 0; o < 64; o++) acc[o] = bd[half + o];

    const float* yp = y + (size_t)b * 128 * NPIX + px;
    for (int c0 = 0; c0 < 128; c0 += 32) {
        __syncthreads();
        for (int i = tid; i < 128 * 32; i += 256) {
            int o = i >> 5, cl = i & 31;
            Ws[o][cl] = Wd[o * 128 + c0 + cl];
        }
        __syncthreads();
        for (int cl = 0; cl < 32; cl++) {
            float v = yp[(size_t)(c0 + cl) * NPIX];
#pragma unroll
            for (int o = 0; o < 64; o++) acc[o] += Ws[half + o][cl] * v;
        }
    }
#pragma unroll
    for (int o = 0; o < 64; o++)
        outd[((size_t)b * 128 + half + o) * NPIX + px] = acc[o];
}

// ---------------------------------------------------------------------------
// PAM flash attention: feat[c,n] = sum_m softmax_m(q_n . k_m) * v[c,m]
// out = alpha*feat + y.   grid: (64 query tiles, BATCH); block 256
// Query tile 64, key tile 32; online softmax; V staged in smem.
// ---------------------------------------------------------------------------
__global__ void pam_attn_kernel(const float* __restrict__ qb,
                                const float* __restrict__ kc,
                                const float* __restrict__ vd,
                                const float* __restrict__ y,
                                const float* __restrict__ alpha,
                                float* __restrict__ out) {
    const int b   = blockIdx.y;
    const int n0  = blockIdx.x * 64;
    const int tid = threadIdx.x;
    const int nl  = tid & 63;     // query within tile
    const int cg  = tid >> 6;     // 0..3 -> 32 value channels each

    __shared__ __align__(16) float Qs[16][64];
    __shared__ __align__(16) float Ks[16][32];
    __shared__ __align__(16) float Vs[128][32];
    __shared__ float Ss[64][33];
    __shared__ float msh[64], lsh[64], fsh[64];

    for (int i = tid; i < 16 * 64; i += 256) {
        int k = i >> 6, c = i & 63;
        Qs[k][c] = qb[((size_t)b * 16 + k) * NPIX + n0 + c];
    }
    if (tid < 64) { msh[tid] = -1e30f; lsh[tid] = 0.0f; }

    float acc[32];
#pragma unroll
    for (int i = 0; i < 32; i++) acc[i] = 0.0f;
    __syncthreads();

    for (int m0 = 0; m0 < NPIX; m0 += 32) {
        for (int i = tid; i < 16 * 32; i += 256) {
            int k = i >> 5, m = i & 31;
            Ks[k][m] = kc[((size_t)b * 16 + k) * NPIX + m0 + m];
        }
        for (int i = tid; i < 128 * 32; i += 256) {
            int c = i >> 5, m = i & 31;
            Vs[c][m] = vd[((size_t)b * 128 + c) * NPIX + m0 + m];
        }
        __syncthreads();

        // S[64][32] = Q^T K  (8 entries/thread)
#pragma unroll
        for (int e = 0; e < 8; e++) {
            int flat = tid + 256 * e;
            int sn = flat >> 5, sm = flat & 31;
            float s = 0.0f;
#pragma unroll
            for (int k = 0; k < 16; k++) s += Qs[k][sn] * Ks[k][sm];
            Ss[sn][sm] = s;
        }
        __syncthreads();

        // online softmax per row (64 threads)
        if (tid < 64) {
            float mx = -1e30f;
#pragma unroll
            for (int m = 0; m < 32; m++) mx = fmaxf(mx, Ss[tid][m]);
            float mnew = fmaxf(msh[tid], mx);
            float f = __expf(msh[tid] - mnew);
            float sum = 0.0f;
#pragma unroll
            for (int m = 0; m < 32; m++) {
                float p = __expf(Ss[tid][m] - mnew);
                Ss[tid][m] = p;
                sum += p;
            }
            lsh[tid] = lsh[tid] * f + sum;
            msh[tid] = mnew;
            fsh[tid] = f;
        }
        __syncthreads();

        float f = fsh[nl];
#pragma unroll
        for (int i = 0; i < 32; i++) acc[i] *= f;
#pragma unroll
        for (int m = 0; m < 32; m += 4) {
            float p0 = Ss[nl][m + 0];
            float p1 = Ss[nl][m + 1];
            float p2 = Ss[nl][m + 2];
            float p3 = Ss[nl][m + 3];
#pragma unroll
            for (int i = 0; i < 32; i++) {
                const float4 v = *(const float4*)&Vs[cg * 32 + i][m];
                acc[i] += p0 * v.x + p1 * v.y + p2 * v.z + p3 * v.w;
            }
        }
        __syncthreads();
    }

    const float linv = 1.0f / lsh[nl];
    const float a = alpha[0];
#pragma unroll
    for (int i = 0; i < 32; i++) {
        int c = cg * 32 + i;
        size_t idx = ((size_t)b * 128 + c) * NPIX + n0 + nl;
        out[idx] = a * (acc[i] * linv) + y[idx];
    }
}

// ---------------------------------------------------------------------------
// CAM gram matrix: E[c][d] = sum_n y[c][n]*y[d][n]
// grid: (64 tiles of 16x16, BATCH); block 256 (1 elem/thread)
// ---------------------------------------------------------------------------
__global__ void cam_energy_kernel(const float* __restrict__ y,
                                  float* __restrict__ energy) {
    const int b  = blockIdx.y;
    const int tc = (blockIdx.x / 8) * 16;
    const int td = (blockIdx.x % 8) * 16;
    const int tid = threadIdx.x;
    const int li = tid / 16, lj = tid % 16;

    __shared__ float As[16][65];
    __shared__ float Bs[16][65];

    const float* yb = y + (size_t)b * 128 * NPIX;
    float acc = 0.0f;
    for (int n0 = 0; n0 < NPIX; n0 += 64) {
        for (int i = tid; i < 1024; i += 256) {
            int r = i >> 6, c = i & 63;
            As[r][c] = yb[(size_t)(tc + r) * NPIX + n0 + c];
            Bs[r][c] = yb[(size_t)(td + r) * NPIX + n0 + c];
        }
        __syncthreads();
#pragma unroll 16
        for (int k = 0; k < 64; k++) acc += As[li][k] * Bs[lj][k];
        __syncthreads();
    }
    energy[((size_t)b * 128 + tc + li) * 128 + td + lj] = acc;
}

// ---------------------------------------------------------------------------
// CAM softmax of (rowmax - E) over axis -1.  grid: B*128 rows; block 128
// ---------------------------------------------------------------------------
__global__ void cam_softmax_kernel(const float* __restrict__ energy,
                                   float* __restrict__ attn) {
    const int row = blockIdx.x;
    const int tid = threadIdx.x;
    __shared__ float red[4];

    float e = energy[(size_t)row * 128 + tid];

    float m = e;
#pragma unroll
    for (int off = 16; off; off >>= 1) m = fmaxf(m, __shfl_xor_sync(0xffffffff, m, off));
    if ((tid & 31) == 0) red[tid >> 5] = m;
    __syncthreads();
    float mx = fmaxf(fmaxf(red[0], red[1]), fmaxf(red[2], red[3]));
    float e2 = mx - e;
    __syncthreads();

    float m2 = e2;
#pragma unroll
    for (int off = 16; off; off >>= 1) m2 = fmaxf(m2, __shfl_xor_sync(0xffffffff, m2, off));
    if ((tid & 31) == 0) red[tid >> 5] = m2;
    __syncthreads();
    m2 = fmaxf(fmaxf(red[0], red[1]), fmaxf(red[2], red[3]));
    float p = __expf(e2 - m2);
    __syncthreads();

    float s = p;
#pragma unroll
    for (int off = 16; off; off >>= 1) s += __shfl_xor_sync(0xffffffff, s, off);
    if ((tid & 31) == 0) red[tid >> 5] = s;
    __syncthreads();
    s = red[0] + red[1] + red[2] + red[3];

    attn[(size_t)row * 128 + tid] = p / s;
}

// ---------------------------------------------------------------------------
// CAM feature: out[c][n] = beta * sum_d attn[c][d]*y[d][n] + y[c][n]
// grid: (32, BATCH); block 256 (px = tid&127, half = tid>>7)
// ---------------------------------------------------------------------------
__global__ void cam_feat_kernel(const float* __restrict__ y,
                                const float* __restrict__ attn,
                                const float* __restrict__ beta,
                                float* __restrict__ out) {
    __shared__ float As[128][32];
    const int tid = threadIdx.x;
    const int b   = blockIdx.y;
    const int n0  = blockIdx.x * 128;
    const int px  = n0 + (tid & 127);
    const int half = (tid >> 7) * 64;

    float acc[64];
#pragma unroll
    for (int o = 0; o < 64; o++) acc[o] = 0.0f;

    const float* yp = y + (size_t)b * 128 * NPIX + px;
    const float* ap = attn + (size_t)b * 128 * 128;
    for (int d0 = 0; d0 < 128; d0 += 32) {
        __syncthreads();
        for (int i = tid; i < 128 * 32; i += 256) {
            int c = i >> 5, dl = i & 31;
            As[c][dl] = ap[c * 128 + d0 + dl];
        }
        __syncthreads();
        for (int dl = 0; dl < 32; dl++) {
            float v = yp[(size_t)(d0 + dl) * NPIX];
#pragma unroll
            for (int o = 0; o < 64; o++) acc[o] += As[half + o][dl] * v;
        }
    }
    const float bet = beta[0];
#pragma unroll
    for (int o = 0; o < 64; o++) {
        size_t idx = ((size_t)b * 128 + half + o) * NPIX + px;
        out[idx] = bet * acc[o] + y[idx];
    }
}

// ---------------------------------------------------------------------------
// Final heads: three 1x1 convs (128->19) + sigmoid, fused.
// grid: (16, BATCH); block 256 (1 px/thread)
// ---------------------------------------------------------------------------
__global__ void final_kernel(const float* __restrict__ fp,
                             const float* __restrict__ fc,
                             const float* __restrict__ Wout, const float* __restrict__ bout,
                             const float* __restrict__ Wp3, const float* __restrict__ bp3,
                             const float* __restrict__ Wc3, const float* __restrict__ bc3,
                             float* __restrict__ out) {
    const int b  = blockIdx.y;
    const int px = blockIdx.x * 256 + threadIdx.x;

    __shared__ float Wo[19][128];
    __shared__ float Wp[19][128];
    __shared__ float Wc[19][128];
    for (int i = threadIdx.x; i < 19 * 128; i += 256) {
        Wo[i / 128][i % 128] = Wout[i];
        Wp[i / 128][i % 128] = Wp3[i];
        Wc[i / 128][i % 128] = Wc3[i];
    }
    __syncthreads();

    float am[19], ap[19], ac[19];
#pragma unroll
    for (int o = 0; o < 19; o++) { am[o] = bout[o]; ap[o] = bp3[o]; ac[o] = bc3[o]; }

    for (int c = 0; c < 128; c++) {
        float vp = fp[((size_t)b * 128 + c) * NPIX + px];
        float vc = fc[((size_t)b * 128 + c) * NPIX + px];
        float vf = vp + vc;
#pragma unroll
        for (int o = 0; o < 19; o++) {
            am[o] += Wo[o][c] * vf;
            ap[o] += Wp[o][c] * vp;
            ac[o] += Wc[o][c] * vc;
        }
    }

    const size_t SEG = (size_t)BATCH * NC * NPIX;
#pragma unroll
    for (int o = 0; o < 19; o++) {
        size_t base = ((size_t)b * NC + o) * NPIX + px;
        out[base]           = sigmoidf_(am[o]);
        out[SEG + base]     = sigmoidf_(ap[o]);
        out[2 * SEG + base] = sigmoidf_(ac[o]);
    }
}

// ---------------------------------------------------------------------------
// Launch
// ---------------------------------------------------------------------------
extern "C" void kernel_launch(void* const* d_in, const int* in_sizes, int n_in,
                              void* d_out, int out_size) {
    const float* x    = (const float*)d_in[0];
    const float* Wp1  = (const float*)d_in[1];
    const float* bnp1 = (const float*)d_in[2];
    const float* Wc1  = (const float*)d_in[3];
    const float* bnc1 = (const float*)d_in[4];
    const float* Wb   = (const float*)d_in[5];
    const float* bb   = (const float*)d_in[6];
    const float* Wc   = (const float*)d_in[7];
    const float* bc   = (const float*)d_in[8];
    const float* Wd   = (const float*)d_in[9];
    const float* bd   = (const float*)d_in[10];
    const float* alpha= (const float*)d_in[11];
    const float* beta = (const float*)d_in[12];
    const float* Wp2  = (const float*)d_in[13];
    const float* bnp2 = (const float*)d_in[14];
    const float* Wc2  = (const float*)d_in[15];
    const float* bnc2 = (const float*)d_in[16];
    const float* Wout = (const float*)d_in[17];
    const float* bout = (const float*)d_in[18];
    const float* Wp3  = (const float*)d_in[19];
    const float* bp3  = (const float*)d_in[20];
    const float* Wc3  = (const float*)d_in[21];
    const float* bc3  = (const float*)d_in[22];
    float* out = (float*)d_out;

    float *featp1, *featc1, *qb, *kc, *vd, *pam, *cam, *featp2, *featc2, *energy, *attn;
    cudaGetSymbolAddress((void**)&featp1, g_featp1);
    cudaGetSymbolAddress((void**)&featc1, g_featc1);
    cudaGetSymbolAddress((void**)&qb,     g_qb);
    cudaGetSymbolAddress((void**)&kc,     g_kc);
    cudaGetSymbolAddress((void**)&vd,     g_vd);
    cudaGetSymbolAddress((void**)&pam,    g_pam);
    cudaGetSymbolAddress((void**)&cam,    g_cam);
    cudaGetSymbolAddress((void**)&featp2, g_featp2);
    cudaGetSymbolAddress((void**)&featc2, g_featc2);
    cudaGetSymbolAddress((void**)&energy, g_energy);
    cudaGetSymbolAddress((void**)&attn,   g_attn);

    const dim3 cgrid(4, 16, BATCH);

    // Branch inputs: two big convs
    conv3x3_bnrelu_kernel<512><<<cgrid, 256>>>(x, Wp1, bnp1, featp1);
    conv3x3_bnrelu_kernel<512><<<cgrid, 256>>>(x, Wc1, bnc1, featc1);

    // PAM
    pam_bc_kernel<<<dim3(32, BATCH), 128>>>(featp1, Wb, bb, Wc, bc, qb, kc);
    pam_d_kernel<<<dim3(32, BATCH), 256>>>(featp1, Wd, bd, vd);
    pam_attn_kernel<<<dim3(64, BATCH), 256>>>(qb, kc, vd, featp1, alpha, pam);

    // CAM
    cam_energy_kernel<<<dim3(64, BATCH), 256>>>(featc1, energy);
    cam_softmax_kernel<<<BATCH * 128, 128>>>(energy, attn);
    cam_feat_kernel<<<dim3(32, BATCH), 256>>>(featc1, attn, beta, cam);

    // Second convs
    conv3x3_bnrelu_kernel<128><<<cgrid, 256>>>(pam, Wp2, bnp2, featp2);
    conv3x3_bnrelu_kernel<128><<<cgrid, 256>>>(cam, Wc2, bnc2, featc2);

    // Heads
    final_kernel<<<dim3(16, BATCH), 256>>>(featp2, featc2,
                                           Wout, bout, Wp3, bp3, Wc3, bc3, out);
}

// round 3
// speedup vs baseline: 2.2903x; 2.2903x over previous
#include <cuda_runtime.h>
#include <cuda_bf16.h>
#include <math.h>
#include <cstdint>

// ---------------------------------------------------------------------------
// Problem constants
// ---------------------------------------------------------------------------
#define BATCH 8
#define CIN   512
#define CI    128
#define CK    16
#define NC    19
#define NPIX  4096
#define FEAT_ELEMS (BATCH * CI * NPIX)
#define XP_H 66

// ---------------------------------------------------------------------------
// Scratch (device globals -- no runtime allocation allowed)
// ---------------------------------------------------------------------------
__device__ float g_featp1[FEAT_ELEMS];
__device__ float g_featc1[FEAT_ELEMS];
__device__ float g_qb[BATCH * CK * NPIX];
__device__ float g_kc[BATCH * CK * NPIX];
__device__ float g_vd[FEAT_ELEMS];
__device__ float g_featp2[FEAT_ELEMS];
__device__ float g_featc2[FEAT_ELEMS];
__device__ float g_energy[BATCH * CI * CI];
__device__ float g_attn[BATCH * CI * CI];
__device__ float g_xpad[BATCH * XP_H * XP_H * CIN];   // conv1 input, NHWC padded
__device__ float g_xp2a[BATCH * XP_H * XP_H * CI];    // conv2 input (PAM branch)
__device__ float g_xp2b[BATCH * XP_H * XP_H * CI];    // conv2 input (CAM branch)
__device__ float g_wfrag1[2 * 144 * 4096];            // conv1 weights, frag-packed
__device__ float g_wfrag2[2 * 36 * 4096];             // conv2 weights, frag-packed

__device__ __forceinline__ float sigmoidf_(float x) {
    return 1.0f / (1.0f + __expf(-x));
}
__device__ __forceinline__ float tf32r(float x) {
    uint32_t u;
    asm("cvt.rna.tf32.f32 %0, %1;" : "=r"(u) : "f"(x));
    return __uint_as_float(u);
}
__device__ __forceinline__ uint32_t smem_u32(const void* p) {
    uint32_t a;
    asm("{ .reg .u64 t; cvta.to.shared.u64 t, %1; cvt.u32.u64 %0, t; }" : "=r"(a) : "l"(p));
    return a;
}
__device__ __forceinline__ void mma_tf32(float c[4], const uint32_t a[4], const uint32_t b[2]) {
    asm volatile(
        "mma.sync.aligned.m16n8k8.row.col.f32.tf32.tf32.f32 "
        "{%0,%1,%2,%3}, {%4,%5,%6,%7}, {%8,%9}, {%0,%1,%2,%3};"
        : "+f"(c[0]), "+f"(c[1]), "+f"(c[2]), "+f"(c[3])
        : "r"(a[0]), "r"(a[1]), "r"(a[2]), "r"(a[3]), "r"(b[0]), "r"(b[1]));
}
#define CP_ASYNC16(dst, src) \
    asm volatile("cp.async.ca.shared.global [%0], [%1], 16;" :: "r"(dst), "l"(src))
#define CP_COMMIT() asm volatile("cp.async.commit_group;")
#define CP_WAIT(N)  asm volatile("cp.async.wait_group %0;" :: "n"(N))

// ---------------------------------------------------------------------------
// Pack x: f32 NCHW [8,512,64,64] -> tf32 NHWC padded [8,66,66,512]
// ---------------------------------------------------------------------------
__global__ void pack_x_kernel(const float* __restrict__ x, float* __restrict__ xp) {
    const int h = blockIdx.x, b = blockIdx.y, tid = threadIdx.x;
    __shared__ float s[32][65];
    for (int ci0 = 0; ci0 < CIN; ci0 += 32) {
        for (int idx = tid; idx < 32 * 64; idx += 256) {
            int ci_l = idx >> 6, w = idx & 63;
            s[ci_l][w] = x[(((size_t)b * CIN + ci0 + ci_l) * 64 + h) * 64 + w];
        }
        __syncthreads();
        for (int idx = tid; idx < 64 * 32; idx += 256) {
            int w = idx >> 5, ci_l = idx & 31;
            xp[(((size_t)b * XP_H + h + 1) * XP_H + w + 1) * CIN + ci0 + ci_l] = tf32r(s[ci_l][w]);
        }
        __syncthreads();
    }
}

// Zero padded border for an NHWC buffer of C channels. grid (66, B)
__global__ void zero_border_kernel(float* __restrict__ xp, int C) {
    const int hp = blockIdx.x, b = blockIdx.y, tid = threadIdx.x;
    float* row = xp + ((size_t)b * XP_H + hp) * XP_H * C;
    if (hp == 0 || hp == XP_H - 1) {
        for (int idx = tid; idx < XP_H * C; idx += 256) row[idx] = 0.0f;
    } else {
        for (int idx = tid; idx < C; idx += 256) {
            row[idx] = 0.0f;
            row[(size_t)(XP_H - 1) * C + idx] = 0.0f;
        }
    }
}

// ---------------------------------------------------------------------------
// Pack weights into m16n8k8 tf32 A-fragment order.
// Layout: wf[set][chunk][mt(8)][s(4)][lane(32)][j(4)]  (4096 floats / chunk)
//   chunk = kwh*(CIN/32)+cb ; co = mt*16 + (lane>>2) + ((j&1)<<3)
//   ci = cb*32 + s*8 + (lane&3) + ((j>>1)<<2)
// grid (nchunks, 2 sets), block 256
// ---------------------------------------------------------------------------
__global__ void pack_w_frag(const float* __restrict__ W0, const float* __restrict__ W1,
                            float* __restrict__ wf, int CIN_T) {
    const int cpc = CIN_T / 32;
    const int chunk = blockIdx.x;
    const int kwh = chunk / cpc, cb = chunk % cpc;
    const float* W = blockIdx.y ? W1 : W0;
    float* dst = wf + ((size_t)blockIdx.y * gridDim.x + chunk) * 4096;
    for (int t = 0; t < 16; t++) {
        int idx = threadIdx.x + t * 256;
        int j = idx & 3, lane = (idx >> 2) & 31, s = (idx >> 7) & 3, mt = idx >> 9;
        int co = mt * 16 + (lane >> 2) + ((j & 1) << 3);
        int ci = cb * 32 + s * 8 + (lane & 3) + ((j >> 1) << 2);
        dst[idx] = tf32r(W[((size_t)co * CIN_T + ci) * 9 + kwh]);
    }
}

// ---------------------------------------------------------------------------
// conv3x3 via implicit GEMM on mma.sync tf32 (m16n8k8), fused BN+ReLU.
// CTA: M=128 co x N=128 px (2 rows).  8 warps: 2(M) x 4(N), each 64x32.
// grid (32 px-tiles, 8 batch, 2 sets), block 256, dynamic smem 69632 B.
// ---------------------------------------------------------------------------
#define CONV_SMEM (69632)

template<int CIN_T>
__global__ void __launch_bounds__(256, 2) conv_mma_kernel(
        const float* __restrict__ xpA, const float* __restrict__ xpB,
        const float* __restrict__ wfrag,
        const float* __restrict__ bn0, const float* __restrict__ bn1,
        float* __restrict__ out0, float* __restrict__ out1) {
    constexpr int CPC = CIN_T / 32;
    constexpr int NCHUNK = 9 * CPC;
    extern __shared__ __align__(16) float sm[];
    float* Abuf = sm;            // 2 x 4096 floats
    float* Bbuf = sm + 8192;     // 2 x 4608 floats ([px][36])
    const uint32_t smb = smem_u32(sm);

    const int tid = threadIdx.x, lane = tid & 31, wid = tid >> 5;
    const int warp_m = wid >> 2, warp_n = wid & 3;
    const int b = blockIdx.y, z = blockIdx.z;
    const int pxbase = blockIdx.x * 128;
    const int h0 = pxbase >> 6;
    const float* xp = z ? xpB : xpA;
    const float* Wf = wfrag + (size_t)z * NCHUNK * 4096;
    const float* bn = z ? bn1 : bn0;
    float* out = z ? out1 : out0;

    float acc[4][4][4];
#pragma unroll
    for (int mt = 0; mt < 4; mt++)
#pragma unroll
        for (int nt = 0; nt < 4; nt++)
#pragma unroll
            for (int r = 0; r < 4; r++) acc[mt][nt][r] = 0.0f;

    auto stage = [&](int i, int buf) {
        const int kwh = i / CPC, cb = i % CPC;
        const int kh = kwh / 3, kw = kwh % 3;
        const float* Asrc = Wf + (size_t)i * 4096;
        const uint32_t Adst = smb + buf * 16384;
#pragma unroll
        for (int t = 0; t < 4; t++) {
            int i4 = tid + t * 256;
            CP_ASYNC16(Adst + i4 * 16, Asrc + i4 * 4);
        }
        const float* Bsrc0 = xp + (((size_t)b * XP_H + h0 + kh) * XP_H + kw) * CIN_T + cb * 32;
        const uint32_t Bdst = smb + 32768 + buf * 18432;
#pragma unroll
        for (int t = 0; t < 4; t++) {
            int idx = tid + t * 256;
            int px = idx >> 3, q = idx & 7;
            const float* src = Bsrc0 + (size_t)(px >> 6) * (XP_H * CIN_T) + (px & 63) * CIN_T + q * 4;
            CP_ASYNC16(Bdst + (px * 36 + q * 4) * 4, src);
        }
        CP_COMMIT();
    };

    stage(0, 0);
    for (int i = 0; i < NCHUNK; i++) {
        const int buf = i & 1;
        if (i + 1 < NCHUNK) {
            stage(i + 1, buf ^ 1);
            CP_WAIT(1);
        } else {
            CP_WAIT(0);
        }
        __syncthreads();

        const float* A = Abuf + buf * 4096;
        const float* B = Bbuf + buf * 4608;
#pragma unroll
        for (int s = 0; s < 4; s++) {
            uint32_t afr[4][4];
#pragma unroll
            for (int mt = 0; mt < 4; mt++) {
                const float4 v = *(const float4*)&A[((warp_m * 4 + mt) * 4 + s) * 128 + lane * 4];
                afr[mt][0] = __float_as_uint(v.x);
                afr[mt][1] = __float_as_uint(v.y);
                afr[mt][2] = __float_as_uint(v.z);
                afr[mt][3] = __float_as_uint(v.w);
            }
            uint32_t bfr[4][2];
#pragma unroll
            for (int nt = 0; nt < 4; nt++) {
                const int pxn = warp_n * 32 + nt * 8 + (lane >> 2);
                bfr[nt][0] = __float_as_uint(B[pxn * 36 + s * 8 + (lane & 3)]);
                bfr[nt][1] = __float_as_uint(B[pxn * 36 + s * 8 + (lane & 3) + 4]);
            }
#pragma unroll
            for (int mt = 0; mt < 4; mt++)
#pragma unroll
                for (int nt = 0; nt < 4; nt++)
                    mma_tf32(acc[mt][nt], afr[mt], bfr[nt]);
        }
        __syncthreads();
    }

    // Epilogue: BN + ReLU, NCHW stores
#pragma unroll
    for (int mt = 0; mt < 4; mt++) {
        const int co = warp_m * 64 + mt * 16 + (lane >> 2);
        const float sc0 = bn[co],     sh0 = bn[128 + co];
        const float sc8 = bn[co + 8], sh8 = bn[136 + co];
        float* o0 = out + ((size_t)b * 128 + co) * NPIX;
        float* o8 = o0 + 8 * NPIX;
#pragma unroll
        for (int nt = 0; nt < 4; nt++) {
            const int px = pxbase + warp_n * 32 + nt * 8 + 2 * (lane & 3);
            float2 v0, v1;
            v0.x = fmaxf(acc[mt][nt][0] * sc0 + sh0, 0.0f);
            v0.y = fmaxf(acc[mt][nt][1] * sc0 + sh0, 0.0f);
            v1.x = fmaxf(acc[mt][nt][2] * sc8 + sh8, 0.0f);
            v1.y = fmaxf(acc[mt][nt][3] * sc8 + sh8, 0.0f);
            *(float2*)(o0 + px) = v0;
            *(float2*)(o8 + px) = v1;
        }
    }
}

// ---------------------------------------------------------------------------
// PAM query/key projections
// ---------------------------------------------------------------------------
__global__ void pam_bc_kernel(const float* __restrict__ y,
                              const float* __restrict__ Wb, const float* __restrict__ bb,
                              const float* __restrict__ Wc, const float* __restrict__ bc,
                              float* __restrict__ outb, float* __restrict__ outc) {
    const int b  = blockIdx.y;
    const int n0 = blockIdx.x * 128;
    const int tid = threadIdx.x;

    __shared__ float Wbs[16][128];
    __shared__ float Wcs[16][128];
    for (int i = tid; i < 16 * 128; i += 128) {
        Wbs[i >> 7][i & 127] = Wb[i];
        Wcs[i >> 7][i & 127] = Wc[i];
    }
    __syncthreads();

    float ab[16], ac[16];
#pragma unroll
    for (int o = 0; o < 16; o++) { ab[o] = bb[o]; ac[o] = bc[o]; }

    const float* yp = y + (size_t)b * 128 * NPIX + n0 + tid;
    for (int c = 0; c < 128; c++) {
        float v = yp[(size_t)c * NPIX];
#pragma unroll
        for (int o = 0; o < 16; o++) {
            ab[o] += Wbs[o][c] * v;
            ac[o] += Wcs[o][c] * v;
        }
    }
#pragma unroll
    for (int o = 0; o < 16; o++) {
        outb[((size_t)b * 16 + o) * NPIX + n0 + tid] = ab[o];
        outc[((size_t)b * 16 + o) * NPIX + n0 + tid] = ac[o];
    }
}

// ---------------------------------------------------------------------------
// PAM value projection
// ---------------------------------------------------------------------------
__global__ void pam_d_kernel(const float* __restrict__ y,
                             const float* __restrict__ Wd,
                             const float* __restrict__ bd,
                             float* __restrict__ outd) {
    __shared__ float Ws[128][32];
    const int tid = threadIdx.x;
    const int b   = blockIdx.y;
    const int n0  = blockIdx.x * 128;
    const int px  = n0 + (tid & 127);
    const int half = (tid >> 7) * 64;

    float acc[64];
#pragma unroll
    for (int o = 0; o < 64; o++) acc[o] = bd[half + o];

    const float* yp = y + (size_t)b * 128 * NPIX + px;
    for (int c0 = 0; c0 < 128; c0 += 32) {
        __syncthreads();
        for (int i = tid; i < 128 * 32; i += 256) {
            int o = i >> 5, cl = i & 31;
            Ws[o][cl] = Wd[o * 128 + c0 + cl];
        }
        __syncthreads();
        for (int cl = 0; cl < 32; cl++) {
            float v = yp[(size_t)(c0 + cl) * NPIX];
#pragma unroll
            for (int o = 0; o < 64; o++) acc[o] += Ws[half + o][cl] * v;
        }
    }
#pragma unroll
    for (int o = 0; o < 64; o++)
        outd[((size_t)b * 128 + half + o) * NPIX + px] = acc[o];
}

// ---------------------------------------------------------------------------
// PAM flash attention -> writes alpha*feat + y into padded NHWC conv2 input.
// ---------------------------------------------------------------------------
__global__ void pam_attn_kernel(const float* __restrict__ qb,
                                const float* __restrict__ kc,
                                const float* __restrict__ vd,
                                const float* __restrict__ y,
                                const float* __restrict__ alpha,
                                float* __restrict__ xp2) {
    const int b   = blockIdx.y;
    const int n0  = blockIdx.x * 64;
    const int tid = threadIdx.x;
    const int nl  = tid & 63;
    const int cg  = tid >> 6;

    __shared__ __align__(16) float Qs[16][64];
    __shared__ __align__(16) float Ks[16][32];
    __shared__ __align__(16) float Vs[128][32];
    __shared__ float Ss[64][33];
    __shared__ float msh[64], lsh[64], fsh[64];

    for (int i = tid; i < 16 * 64; i += 256) {
        int k = i >> 6, c = i & 63;
        Qs[k][c] = qb[((size_t)b * 16 + k) * NPIX + n0 + c];
    }
    if (tid < 64) { msh[tid] = -1e30f; lsh[tid] = 0.0f; }

    float acc[32];
#pragma unroll
    for (int i = 0; i < 32; i++) acc[i] = 0.0f;
    __syncthreads();

    for (int m0 = 0; m0 < NPIX; m0 += 32) {
        for (int i = tid; i < 16 * 32; i += 256) {
            int k = i >> 5, m = i & 31;
            Ks[k][m] = kc[((size_t)b * 16 + k) * NPIX + m0 + m];
        }
        for (int i = tid; i < 128 * 32; i += 256) {
            int c = i >> 5, m = i & 31;
            Vs[c][m] = vd[((size_t)b * 128 + c) * NPIX + m0 + m];
        }
        __syncthreads();

#pragma unroll
        for (int e = 0; e < 8; e++) {
            int flat = tid + 256 * e;
            int sn = flat >> 5, sm2 = flat & 31;
            float s = 0.0f;
#pragma unroll
            for (int k = 0; k < 16; k++) s += Qs[k][sn] * Ks[k][sm2];
            Ss[sn][sm2] = s;
        }
        __syncthreads();

        if (tid < 64) {
            float mx = -1e30f;
#pragma unroll
            for (int m = 0; m < 32; m++) mx = fmaxf(mx, Ss[tid][m]);
            float mnew = fmaxf(msh[tid], mx);
            float f = __expf(msh[tid] - mnew);
            float sum = 0.0f;
#pragma unroll
            for (int m = 0; m < 32; m++) {
                float p = __expf(Ss[tid][m] - mnew);
                Ss[tid][m] = p;
                sum += p;
            }
            lsh[tid] = lsh[tid] * f + sum;
            msh[tid] = mnew;
            fsh[tid] = f;
        }
        __syncthreads();

        float f = fsh[nl];
#pragma unroll
        for (int i = 0; i < 32; i++) acc[i] *= f;
#pragma unroll
        for (int m = 0; m < 32; m += 4) {
            float p0 = Ss[nl][m + 0];
            float p1 = Ss[nl][m + 1];
            float p2 = Ss[nl][m + 2];
            float p3 = Ss[nl][m + 3];
#pragma unroll
            for (int i = 0; i < 32; i++) {
                const float4 v = *(const float4*)&Vs[cg * 32 + i][m];
                acc[i] += p0 * v.x + p1 * v.y + p2 * v.z + p3 * v.w;
            }
        }
        __syncthreads();
    }

    const float linv = 1.0f / lsh[nl];
    const float a = alpha[0];
    const int px = n0 + nl;
    float* dst = xp2 + (((size_t)b * XP_H + (px >> 6) + 1) * XP_H + (px & 63) + 1) * CI + cg * 32;
    const float* ys = y + ((size_t)b * 128 + cg * 32) * NPIX + px;
#pragma unroll
    for (int i = 0; i < 32; i += 4) {
        float4 v;
        v.x = tf32r(a * (acc[i + 0] * linv) + ys[(size_t)(i + 0) * NPIX]);
        v.y = tf32r(a * (acc[i + 1] * linv) + ys[(size_t)(i + 1) * NPIX]);
        v.z = tf32r(a * (acc[i + 2] * linv) + ys[(size_t)(i + 2) * NPIX]);
        v.w = tf32r(a * (acc[i + 3] * linv) + ys[(size_t)(i + 3) * NPIX]);
        *(float4*)(dst + i) = v;
    }
}

// ---------------------------------------------------------------------------
// CAM gram matrix
// ---------------------------------------------------------------------------
__global__ void cam_energy_kernel(const float* __restrict__ y,
                                  float* __restrict__ energy) {
    const int b  = blockIdx.y;
    const int tc = (blockIdx.x / 8) * 16;
    const int td = (blockIdx.x % 8) * 16;
    const int tid = threadIdx.x;
    const int li = tid / 16, lj = tid % 16;

    __shared__ float As[16][65];
    __shared__ float Bs[16][65];

    const float* yb = y + (size_t)b * 128 * NPIX;
    float acc = 0.0f;
    for (int n0 = 0; n0 < NPIX; n0 += 64) {
        for (int i = tid; i < 1024; i += 256) {
            int r = i >> 6, c = i & 63;
            As[r][c] = yb[(size_t)(tc + r) * NPIX + n0 + c];
            Bs[r][c] = yb[(size_t)(td + r) * NPIX + n0 + c];
        }
        __syncthreads();
#pragma unroll 16
        for (int k = 0; k < 64; k++) acc += As[li][k] * Bs[lj][k];
        __syncthreads();
    }
    energy[((size_t)b * 128 + tc + li) * 128 + td + lj] = acc;
}

// ---------------------------------------------------------------------------
// CAM softmax of (rowmax - E)
// ---------------------------------------------------------------------------
__global__ void cam_softmax_kernel(const float* __restrict__ energy,
                                   float* __restrict__ attn) {
    const int row = blockIdx.x;
    const int tid = threadIdx.x;
    __shared__ float red[4];

    float e = energy[(size_t)row * 128 + tid];

    float m = e;
#pragma unroll
    for (int off = 16; off; off >>= 1) m = fmaxf(m, __shfl_xor_sync(0xffffffff, m, off));
    if ((tid & 31) == 0) red[tid >> 5] = m;
    __syncthreads();
    float mx = fmaxf(fmaxf(red[0], red[1]), fmaxf(red[2], red[3]));
    float e2 = mx - e;
    __syncthreads();

    float m2 = e2;
#pragma unroll
    for (int off = 16; off; off >>= 1) m2 = fmaxf(m2, __shfl_xor_sync(0xffffffff, m2, off));
    if ((tid & 31) == 0) red[tid >> 5] = m2;
    __syncthreads();
    m2 = fmaxf(fmaxf(red[0], red[1]), fmaxf(red[2], red[3]));
    float p = __expf(e2 - m2);
    __syncthreads();

    float s = p;
#pragma unroll
    for (int off = 16; off; off >>= 1) s += __shfl_xor_sync(0xffffffff, s, off);
    if ((tid & 31) == 0) red[tid >> 5] = s;
    __syncthreads();
    s = red[0] + red[1] + red[2] + red[3];

    attn[(size_t)row * 128 + tid] = p / s;
}

// ---------------------------------------------------------------------------
// CAM feature -> writes beta*feat + y into padded NHWC conv2 input.
// ---------------------------------------------------------------------------
__global__ void cam_feat_kernel(const float* __restrict__ y,
                                const float* __restrict__ attn,
                                const float* __restrict__ beta,
                                float* __restrict__ xp2) {
    __shared__ float As[128][32];
    const int tid = threadIdx.x;
    const int b   = blockIdx.y;
    const int n0  = blockIdx.x * 128;
    const int px  = n0 + (tid & 127);
    const int half = (tid >> 7) * 64;

    float acc[64];
#pragma unroll
    for (int o = 0; o < 64; o++) acc[o] = 0.0f;

    const float* yp = y + (size_t)b * 128 * NPIX + px;
    const float* ap = attn + (size_t)b * 128 * 128;
    for (int d0 = 0; d0 < 128; d0 += 32) {
        __syncthreads();
        for (int i = tid; i < 128 * 32; i += 256) {
            int c = i >> 5, dl = i & 31;
            As[c][dl] = ap[c * 128 + d0 + dl];
        }
        __syncthreads();
        for (int dl = 0; dl < 32; dl++) {
            float v = yp[(size_t)(d0 + dl) * NPIX];
#pragma unroll
            for (int o = 0; o < 64; o++) acc[o] += As[half + o][dl] * v;
        }
    }
    const float bet = beta[0];
    float* dst = xp2 + (((size_t)b * XP_H + (px >> 6) + 1) * XP_H + (px & 63) + 1) * CI + half;
#pragma unroll
    for (int o = 0; o < 64; o += 4) {
        float4 v;
        v.x = tf32r(bet * acc[o + 0] + yp[(size_t)(half + o + 0) * NPIX]);
        v.y = tf32r(bet * acc[o + 1] + yp[(size_t)(half + o + 1) * NPIX]);
        v.z = tf32r(bet * acc[o + 2] + yp[(size_t)(half + o + 2) * NPIX]);
        v.w = tf32r(bet * acc[o + 3] + yp[(size_t)(half + o + 3) * NPIX]);
        *(float4*)(dst + o) = v;
    }
}

// ---------------------------------------------------------------------------
// Final heads: three 1x1 convs (128->19) + sigmoid, fused.
// ---------------------------------------------------------------------------
__global__ void final_kernel(const float* __restrict__ fp,
                             const float* __restrict__ fc,
                             const float* __restrict__ Wout, const float* __restrict__ bout,
                             const float* __restrict__ Wp3, const float* __restrict__ bp3,
                             const float* __restrict__ Wc3, const float* __restrict__ bc3,
                             float* __restrict__ out) {
    const int b  = blockIdx.y;
    const int px = blockIdx.x * 256 + threadIdx.x;

    __shared__ float Wo[19][128];
    __shared__ float Wp[19][128];
    __shared__ float Wc[19][128];
    for (int i = threadIdx.x; i < 19 * 128; i += 256) {
        Wo[i / 128][i % 128] = Wout[i];
        Wp[i / 128][i % 128] = Wp3[i];
        Wc[i / 128][i % 128] = Wc3[i];
    }
    __syncthreads();

    float am[19], ap[19], ac[19];
#pragma unroll
    for (int o = 0; o < 19; o++) { am[o] = bout[o]; ap[o] = bp3[o]; ac[o] = bc3[o]; }

    for (int c = 0; c < 128; c++) {
        float vp = fp[((size_t)b * 128 + c) * NPIX + px];
        float vc = fc[((size_t)b * 128 + c) * NPIX + px];
        float vf = vp + vc;
#pragma unroll
        for (int o = 0; o < 19; o++) {
            am[o] += Wo[o][c] * vf;
            ap[o] += Wp[o][c] * vp;
            ac[o] += Wc[o][c] * vc;
        }
    }

    const size_t SEG = (size_t)BATCH * NC * NPIX;
#pragma unroll
    for (int o = 0; o < 19; o++) {
        size_t base = ((size_t)b * NC + o) * NPIX + px;
        out[base]           = sigmoidf_(am[o]);
        out[SEG + base]     = sigmoidf_(ap[o]);
        out[2 * SEG + base] = sigmoidf_(ac[o]);
    }
}

// ---------------------------------------------------------------------------
// Launch
// ---------------------------------------------------------------------------
extern "C" void kernel_launch(void* const* d_in, const int* in_sizes, int n_in,
                              void* d_out, int out_size) {
    const float* x    = (const float*)d_in[0];
    const float* Wp1  = (const float*)d_in[1];
    const float* bnp1 = (const float*)d_in[2];
    const float* Wc1  = (const float*)d_in[3];
    const float* bnc1 = (const float*)d_in[4];
    const float* Wb   = (const float*)d_in[5];
    const float* bb   = (const float*)d_in[6];
    const float* Wc   = (const float*)d_in[7];
    const float* bc   = (const float*)d_in[8];
    const float* Wd   = (const float*)d_in[9];
    const float* bd   = (const float*)d_in[10];
    const float* alpha= (const float*)d_in[11];
    const float* beta = (const float*)d_in[12];
    const float* Wp2  = (const float*)d_in[13];
    const float* bnp2 = (const float*)d_in[14];
    const float* Wc2  = (const float*)d_in[15];
    const float* bnc2 = (const float*)d_in[16];
    const float* Wout = (const float*)d_in[17];
    const float* bout = (const float*)d_in[18];
    const float* Wp3  = (const float*)d_in[19];
    const float* bp3  = (const float*)d_in[20];
    const float* Wc3  = (const float*)d_in[21];
    const float* bc3  = (const float*)d_in[22];
    float* out = (float*)d_out;

    float *featp1, *featc1, *qb, *kc, *vd, *featp2, *featc2, *energy, *attn;
    float *xpad, *xp2a, *xp2b, *wf1, *wf2;
    cudaGetSymbolAddress((void**)&featp1, g_featp1);
    cudaGetSymbolAddress((void**)&featc1, g_featc1);
    cudaGetSymbolAddress((void**)&qb,     g_qb);
    cudaGetSymbolAddress((void**)&kc,     g_kc);
    cudaGetSymbolAddress((void**)&vd,     g_vd);
    cudaGetSymbolAddress((void**)&featp2, g_featp2);
    cudaGetSymbolAddress((void**)&featc2, g_featc2);
    cudaGetSymbolAddress((void**)&energy, g_energy);
    cudaGetSymbolAddress((void**)&attn,   g_attn);
    cudaGetSymbolAddress((void**)&xpad,   g_xpad);
    cudaGetSymbolAddress((void**)&xp2a,   g_xp2a);
    cudaGetSymbolAddress((void**)&xp2b,   g_xp2b);
    cudaGetSymbolAddress((void**)&wf1,    g_wfrag1);
    cudaGetSymbolAddress((void**)&wf2,    g_wfrag2);

    cudaFuncSetAttribute(conv_mma_kernel<512>,
                         cudaFuncAttributeMaxDynamicSharedMemorySize, CONV_SMEM);
    cudaFuncSetAttribute(conv_mma_kernel<128>,
                         cudaFuncAttributeMaxDynamicSharedMemorySize, CONV_SMEM);

    // Packing
    pack_x_kernel<<<dim3(64, BATCH), 256>>>(x, xpad);
    zero_border_kernel<<<dim3(XP_H, BATCH), 256>>>(xpad, CIN);
    zero_border_kernel<<<dim3(XP_H, BATCH), 256>>>(xp2a, CI);
    zero_border_kernel<<<dim3(XP_H, BATCH), 256>>>(xp2b, CI);
    pack_w_frag<<<dim3(144, 2), 256>>>(Wp1, Wc1, wf1, CIN);
    pack_w_frag<<<dim3(36, 2), 256>>>(Wp2, Wc2, wf2, CI);

    // conv1: both 512->128 convs (z selects set)
    conv_mma_kernel<512><<<dim3(32, BATCH, 2), 256, CONV_SMEM>>>(
        xpad, xpad, wf1, bnp1, bnc1, featp1, featc1);

    // PAM
    pam_bc_kernel<<<dim3(32, BATCH), 128>>>(featp1, Wb, bb, Wc, bc, qb, kc);
    pam_d_kernel<<<dim3(32, BATCH), 256>>>(featp1, Wd, bd, vd);
    pam_attn_kernel<<<dim3(64, BATCH), 256>>>(qb, kc, vd, featp1, alpha, xp2a);

    // CAM
    cam_energy_kernel<<<dim3(64, BATCH), 256>>>(featc1, energy);
    cam_softmax_kernel<<<BATCH * 128, 128>>>(energy, attn);
    cam_feat_kernel<<<dim3(32, BATCH), 256>>>(featc1, attn, beta, xp2b);

    // conv2: both 128->128 convs
    conv_mma_kernel<128><<<dim3(32, BATCH, 2), 256, CONV_SMEM>>>(
        xp2a, xp2b, wf2, bnp2, bnc2, featp2, featc2);

    // Heads
    final_kernel<<<dim3(16, BATCH), 256>>>(featp2, featc2,
                                           Wout, bout, Wp3, bp3, Wc3, bc3, out);
}

// round 4
// speedup vs baseline: 3.1538x; 1.3770x over previous
#include <cuda_runtime.h>
#include <cuda_bf16.h>
#include <cuda_fp16.h>
#include <math.h>
#include <cstdint>

// ---------------------------------------------------------------------------
// Problem constants
// ---------------------------------------------------------------------------
#define BATCH 8
#define CIN   512
#define CI    128
#define CK    16
#define NC    19
#define NPIX  4096
#define FEAT_ELEMS (BATCH * CI * NPIX)
#define XP_H 66

// ---------------------------------------------------------------------------
// Scratch (device globals -- no runtime allocation allowed)
// ---------------------------------------------------------------------------
__device__ float  g_featp1[FEAT_ELEMS];
__device__ float  g_featc1[FEAT_ELEMS];
__device__ float  g_qb[BATCH * CK * NPIX];
__device__ float  g_kc[BATCH * CK * NPIX];
__device__ __half g_vd[FEAT_ELEMS];
__device__ float  g_featp2[FEAT_ELEMS];
__device__ float  g_featc2[FEAT_ELEMS];
__device__ float  g_energy[BATCH * CI * CI];
__device__ float  g_attn[BATCH * CI * CI];
__device__ float  g_xpad[BATCH * XP_H * XP_H * CIN];
__device__ float  g_xp2a[BATCH * XP_H * XP_H * CI];
__device__ float  g_xp2b[BATCH * XP_H * XP_H * CI];
__device__ float  g_wfrag1[2 * 144 * 4096];
__device__ float  g_wfrag2[2 * 36 * 4096];

__device__ __forceinline__ float sigmoidf_(float x) {
    return 1.0f / (1.0f + __expf(-x));
}
__device__ __forceinline__ float tf32r(float x) {
    uint32_t u;
    asm("cvt.rna.tf32.f32 %0, %1;" : "=r"(u) : "f"(x));
    return __uint_as_float(u);
}
__device__ __forceinline__ uint32_t smem_u32(const void* p) {
    uint32_t a;
    asm("{ .reg .u64 t; cvta.to.shared.u64 t, %1; cvt.u32.u64 %0, t; }" : "=r"(a) : "l"(p));
    return a;
}
__device__ __forceinline__ void mma_tf32(float c[4], const uint32_t a[4], const uint32_t b[2]) {
    asm volatile(
        "mma.sync.aligned.m16n8k8.row.col.f32.tf32.tf32.f32 "
        "{%0,%1,%2,%3}, {%4,%5,%6,%7}, {%8,%9}, {%0,%1,%2,%3};"
        : "+f"(c[0]), "+f"(c[1]), "+f"(c[2]), "+f"(c[3])
        : "r"(a[0]), "r"(a[1]), "r"(a[2]), "r"(a[3]), "r"(b[0]), "r"(b[1]));
}
__device__ __forceinline__ void mma_f16(float c[4], const uint32_t a[4], const uint32_t b[2]) {
    asm volatile(
        "mma.sync.aligned.m16n8k16.row.col.f32.f16.f16.f32 "
        "{%0,%1,%2,%3}, {%4,%5,%6,%7}, {%8,%9}, {%0,%1,%2,%3};"
        : "+f"(c[0]), "+f"(c[1]), "+f"(c[2]), "+f"(c[3])
        : "r"(a[0]), "r"(a[1]), "r"(a[2]), "r"(a[3]), "r"(b[0]), "r"(b[1]));
}
#define CP_ASYNC16(dst, src) \
    asm volatile("cp.async.ca.shared.global [%0], [%1], 16;" :: "r"(dst), "l"(src))
#define CP_COMMIT() asm volatile("cp.async.commit_group;")
#define CP_WAIT(N)  asm volatile("cp.async.wait_group %0;" :: "n"(N))

// Fast e^x on the FMA pipe (degree-6 2^r Taylor), avoids the MUFU floor.
__device__ __forceinline__ float fexp(float x) {
    x = fmaxf(x * 1.4426950408889634f, -126.0f);
    float fl = floorf(x);
    float r = x - fl;
    float p = 1.5403530e-4f;
    p = fmaf(p, r, 1.3333558e-3f);
    p = fmaf(p, r, 9.6181291e-3f);
    p = fmaf(p, r, 5.5504109e-2f);
    p = fmaf(p, r, 2.4022651e-1f);
    p = fmaf(p, r, 6.9314718e-1f);
    p = fmaf(p, r, 1.0f);
    return __int_as_float(((int)fl + 127) << 23) * p;
}
__device__ __forceinline__ uint32_t ph2(float x, float y) {
    __half2 h = __floats2half2_rn(x, y);
    return *(uint32_t*)&h;
}

// ---------------------------------------------------------------------------
// Pack x: f32 NCHW -> tf32 NHWC padded
// ---------------------------------------------------------------------------
__global__ void pack_x_kernel(const float* __restrict__ x, float* __restrict__ xp) {
    const int h = blockIdx.x, b = blockIdx.y, tid = threadIdx.x;
    __shared__ float s[32][65];
    for (int ci0 = 0; ci0 < CIN; ci0 += 32) {
        for (int idx = tid; idx < 32 * 64; idx += 256) {
            int ci_l = idx >> 6, w = idx & 63;
            s[ci_l][w] = x[(((size_t)b * CIN + ci0 + ci_l) * 64 + h) * 64 + w];
        }
        __syncthreads();
        for (int idx = tid; idx < 64 * 32; idx += 256) {
            int w = idx >> 5, ci_l = idx & 31;
            xp[(((size_t)b * XP_H + h + 1) * XP_H + w + 1) * CIN + ci0 + ci_l] = tf32r(s[ci_l][w]);
        }
        __syncthreads();
    }
}

__global__ void zero_border_kernel(float* __restrict__ xp, int C) {
    const int hp = blockIdx.x, b = blockIdx.y, tid = threadIdx.x;
    float* row = xp + ((size_t)b * XP_H + hp) * XP_H * C;
    if (hp == 0 || hp == XP_H - 1) {
        for (int idx = tid; idx < XP_H * C; idx += 256) row[idx] = 0.0f;
    } else {
        for (int idx = tid; idx < C; idx += 256) {
            row[idx] = 0.0f;
            row[(size_t)(XP_H - 1) * C + idx] = 0.0f;
        }
    }
}

// ---------------------------------------------------------------------------
// Pack weights into m16n8k8 tf32 A-fragment order.
// ---------------------------------------------------------------------------
__global__ void pack_w_frag(const float* __restrict__ W0, const float* __restrict__ W1,
                            float* __restrict__ wf, int CIN_T) {
    const int cpc = CIN_T / 32;
    const int chunk = blockIdx.x;
    const int kwh = chunk / cpc, cb = chunk % cpc;
    const float* W = blockIdx.y ? W1 : W0;
    float* dst = wf + ((size_t)blockIdx.y * gridDim.x + chunk) * 4096;
    for (int t = 0; t < 16; t++) {
        int idx = threadIdx.x + t * 256;
        int j = idx & 3, lane = (idx >> 2) & 31, s = (idx >> 7) & 3, mt = idx >> 9;
        int co = mt * 16 + (lane >> 2) + ((j & 1) << 3);
        int ci = cb * 32 + s * 8 + (lane & 3) + ((j >> 1) << 2);
        dst[idx] = tf32r(W[((size_t)co * CIN_T + ci) * 9 + kwh]);
    }
}

// ---------------------------------------------------------------------------
// conv3x3 via implicit GEMM on mma.sync tf32, fused BN+ReLU.
// ---------------------------------------------------------------------------
#define CONV_SMEM (69632)

template<int CIN_T>
__global__ void __launch_bounds__(256, 2) conv_mma_kernel(
        const float* __restrict__ xpA, const float* __restrict__ xpB,
        const float* __restrict__ wfrag,
        const float* __restrict__ bn0, const float* __restrict__ bn1,
        float* __restrict__ out0, float* __restrict__ out1) {
    constexpr int CPC = CIN_T / 32;
    constexpr int NCHUNK = 9 * CPC;
    extern __shared__ __align__(16) float sm[];
    float* Abuf = sm;
    float* Bbuf = sm + 8192;
    const uint32_t smb = smem_u32(sm);

    const int tid = threadIdx.x, lane = tid & 31, wid = tid >> 5;
    const int warp_m = wid >> 2, warp_n = wid & 3;
    const int b = blockIdx.y, z = blockIdx.z;
    const int pxbase = blockIdx.x * 128;
    const int h0 = pxbase >> 6;
    const float* xp = z ? xpB : xpA;
    const float* Wf = wfrag + (size_t)z * NCHUNK * 4096;
    const float* bn = z ? bn1 : bn0;
    float* out = z ? out1 : out0;

    float acc[4][4][4];
#pragma unroll
    for (int mt = 0; mt < 4; mt++)
#pragma unroll
        for (int nt = 0; nt < 4; nt++)
#pragma unroll
            for (int r = 0; r < 4; r++) acc[mt][nt][r] = 0.0f;

    auto stage = [&](int i, int buf) {
        const int kwh = i / CPC, cb = i % CPC;
        const int kh = kwh / 3, kw = kwh % 3;
        const float* Asrc = Wf + (size_t)i * 4096;
        const uint32_t Adst = smb + buf * 16384;
#pragma unroll
        for (int t = 0; t < 4; t++) {
            int i4 = tid + t * 256;
            CP_ASYNC16(Adst + i4 * 16, Asrc + i4 * 4);
        }
        const float* Bsrc0 = xp + (((size_t)b * XP_H + h0 + kh) * XP_H + kw) * CIN_T + cb * 32;
        const uint32_t Bdst = smb + 32768 + buf * 18432;
#pragma unroll
        for (int t = 0; t < 4; t++) {
            int idx = tid + t * 256;
            int px = idx >> 3, q = idx & 7;
            const float* src = Bsrc0 + (size_t)(px >> 6) * (XP_H * CIN_T) + (px & 63) * CIN_T + q * 4;
            CP_ASYNC16(Bdst + (px * 36 + q * 4) * 4, src);
        }
        CP_COMMIT();
    };

    stage(0, 0);
    for (int i = 0; i < NCHUNK; i++) {
        const int buf = i & 1;
        if (i + 1 < NCHUNK) {
            stage(i + 1, buf ^ 1);
            CP_WAIT(1);
        } else {
            CP_WAIT(0);
        }
        __syncthreads();

        const float* A = Abuf + buf * 4096;
        const float* B = Bbuf + buf * 4608;
#pragma unroll
        for (int s = 0; s < 4; s++) {
            uint32_t afr[4][4];
#pragma unroll
            for (int mt = 0; mt < 4; mt++) {
                const float4 v = *(const float4*)&A[((warp_m * 4 + mt) * 4 + s) * 128 + lane * 4];
                afr[mt][0] = __float_as_uint(v.x);
                afr[mt][1] = __float_as_uint(v.y);
                afr[mt][2] = __float_as_uint(v.z);
                afr[mt][3] = __float_as_uint(v.w);
            }
            uint32_t bfr[4][2];
#pragma unroll
            for (int nt = 0; nt < 4; nt++) {
                const int pxn = warp_n * 32 + nt * 8 + (lane >> 2);
                bfr[nt][0] = __float_as_uint(B[pxn * 36 + s * 8 + (lane & 3)]);
                bfr[nt][1] = __float_as_uint(B[pxn * 36 + s * 8 + (lane & 3) + 4]);
            }
#pragma unroll
            for (int mt = 0; mt < 4; mt++)
#pragma unroll
                for (int nt = 0; nt < 4; nt++)
                    mma_tf32(acc[mt][nt], afr[mt], bfr[nt]);
        }
        __syncthreads();
    }

#pragma unroll
    for (int mt = 0; mt < 4; mt++) {
        const int co = warp_m * 64 + mt * 16 + (lane >> 2);
        const float sc0 = bn[co],     sh0 = bn[128 + co];
        const float sc8 = bn[co + 8], sh8 = bn[136 + co];
        float* o0 = out + ((size_t)b * 128 + co) * NPIX;
        float* o8 = o0 + 8 * NPIX;
#pragma unroll
        for (int nt = 0; nt < 4; nt++) {
            const int px = pxbase + warp_n * 32 + nt * 8 + 2 * (lane & 3);
            float2 v0, v1;
            v0.x = fmaxf(acc[mt][nt][0] * sc0 + sh0, 0.0f);
            v0.y = fmaxf(acc[mt][nt][1] * sc0 + sh0, 0.0f);
            v1.x = fmaxf(acc[mt][nt][2] * sc8 + sh8, 0.0f);
            v1.y = fmaxf(acc[mt][nt][3] * sc8 + sh8, 0.0f);
            *(float2*)(o0 + px) = v0;
            *(float2*)(o8 + px) = v1;
        }
    }
}

// ---------------------------------------------------------------------------
// PAM query/key projections
// ---------------------------------------------------------------------------
__global__ void pam_bc_kernel(const float* __restrict__ y,
                              const float* __restrict__ Wb, const float* __restrict__ bb,
                              const float* __restrict__ Wc, const float* __restrict__ bc,
                              float* __restrict__ outb, float* __restrict__ outc) {
    const int b  = blockIdx.y;
    const int n0 = blockIdx.x * 128;
    const int tid = threadIdx.x;

    __shared__ float Wbs[16][128];
    __shared__ float Wcs[16][128];
    for (int i = tid; i < 16 * 128; i += 128) {
        Wbs[i >> 7][i & 127] = Wb[i];
        Wcs[i >> 7][i & 127] = Wc[i];
    }
    __syncthreads();

    float ab[16], ac[16];
#pragma unroll
    for (int o = 0; o < 16; o++) { ab[o] = bb[o]; ac[o] = bc[o]; }

    const float* yp = y + (size_t)b * 128 * NPIX + n0 + tid;
    for (int c = 0; c < 128; c++) {
        float v = yp[(size_t)c * NPIX];
#pragma unroll
        for (int o = 0; o < 16; o++) {
            ab[o] += Wbs[o][c] * v;
            ac[o] += Wcs[o][c] * v;
        }
    }
#pragma unroll
    for (int o = 0; o < 16; o++) {
        outb[((size_t)b * 16 + o) * NPIX + n0 + tid] = ab[o];
        outc[((size_t)b * 16 + o) * NPIX + n0 + tid] = ac[o];
    }
}

// ---------------------------------------------------------------------------
// PAM value projection -> fp16 output for the MMA attention kernel
// ---------------------------------------------------------------------------
__global__ void pam_d_kernel(const float* __restrict__ y,
                             const float* __restrict__ Wd,
                             const float* __restrict__ bd,
                             __half* __restrict__ outd) {
    __shared__ float Ws[128][32];
    const int tid = threadIdx.x;
    const int b   = blockIdx.y;
    const int n0  = blockIdx.x * 128;
    const int px  = n0 + (tid & 127);
    const int half_ = (tid >> 7) * 64;

    float acc[64];
#pragma unroll
    for (int o = 0; o < 64; o++) acc[o] = bd[half_ + o];

    const float* yp = y + (size_t)b * 128 * NPIX + px;
    for (int c0 = 0; c0 < 128; c0 += 32) {
        __syncthreads();
        for (int i = tid; i < 128 * 32; i += 256) {
            int o = i >> 5, cl = i & 31;
            Ws[o][cl] = Wd[o * 128 + c0 + cl];
        }
        __syncthreads();
        for (int cl = 0; cl < 32; cl++) {
            float v = yp[(size_t)(c0 + cl) * NPIX];
#pragma unroll
            for (int o = 0; o < 64; o++) acc[o] += Ws[half_ + o][cl] * v;
        }
    }
#pragma unroll
    for (int o = 0; o < 64; o++)
        outd[((size_t)b * 128 + half_ + o) * NPIX + px] = __float2half_rn(acc[o]);
}

// ---------------------------------------------------------------------------
// PAM flash attention on mma.sync (tf32 QK^T, fp16 P·V), register-resident.
// grid (32 q-tiles of 128, 8 batch), block 256 (8 warps, 16 queries each).
// Key tiles of 64, cp.async double-buffered K (f32) and V (fp16).
// Epilogue writes alpha*feat + y into padded NHWC conv2 input.
// SMEM: Qd[16][132] f32 @0 (8448B); Kd 2x[16][68] f32 @8448 (4352B each);
//       Vs 2x[128][72] fp16 @17152 (18432B each).  Total 54016 B.
// ---------------------------------------------------------------------------
#define ATT_SMEM 54016

__global__ void __launch_bounds__(256, 1) pam_attn_mma(
        const float* __restrict__ qb, const float* __restrict__ kc,
        const __half* __restrict__ vd, const float* __restrict__ y,
        const float* __restrict__ alpha, float* __restrict__ xp2) {
    extern __shared__ __align__(16) char smc[];
    float* Qd = (float*)smc;
    const uint32_t smb = smem_u32(smc);
    const int tid = threadIdx.x, lane = tid & 31, wid = tid >> 5;
    const int b = blockIdx.y;
    const int n0 = blockIdx.x * 128;
    const int qbase = wid * 16;

    // Load Q tile [16 d][128 q]
    for (int i = tid; i < 2048; i += 256) {
        int d = i >> 7, q = i & 127;
        Qd[d * 132 + q] = qb[((size_t)b * 16 + d) * NPIX + n0 + q];
    }

    auto stageKV = [&](int t, int buf) {
        const int k0 = t * 64;
        {   // K: [16 d][64 k] f32, 256 x 16B
            int d = tid >> 4, c = tid & 15;
            const float* src = kc + ((size_t)b * 16 + d) * NPIX + k0 + c * 4;
            CP_ASYNC16(smb + 8448 + buf * 4352 + d * 272 + c * 16, src);
        }
#pragma unroll
        for (int t4 = 0; t4 < 4; t4++) {   // V: [128 ch][64 k] fp16, 1024 x 16B
            int idx = tid + t4 * 256;
            int ch = idx >> 3, c = idx & 7;
            const __half* src = vd + ((size_t)b * 128 + ch) * NPIX + k0 + c * 8;
            CP_ASYNC16(smb + 17152 + buf * 18432 + ch * 144 + c * 16, src);
        }
        CP_COMMIT();
    };

    stageKV(0, 0);
    __syncthreads();   // Qd visible

    // Q fragments (constant across key tiles): 2 k-steps x 4 regs
    uint32_t qfr[2][4];
#pragma unroll
    for (int s = 0; s < 2; s++) {
        const int r = qbase + (lane >> 2);
        const int d0 = 8 * s + (lane & 3);
        qfr[s][0] = __float_as_uint(Qd[d0 * 132 + r]);
        qfr[s][1] = __float_as_uint(Qd[d0 * 132 + r + 8]);
        qfr[s][2] = __float_as_uint(Qd[(d0 + 4) * 132 + r]);
        qfr[s][3] = __float_as_uint(Qd[(d0 + 4) * 132 + r + 8]);
    }

    float O[16][4];
#pragma unroll
    for (int nc = 0; nc < 16; nc++)
#pragma unroll
        for (int r = 0; r < 4; r++) O[nc][r] = 0.0f;
    float mrun0 = -1e30f, mrun1 = -1e30f, lrun0 = 0.0f, lrun1 = 0.0f;

    for (int t = 0; t < 64; t++) {
        const int buf = t & 1;
        if (t + 1 < 64) { stageKV(t + 1, buf ^ 1); CP_WAIT(1); }
        else            { CP_WAIT(0); }
        __syncthreads();

        const float* Kf = (const float*)(smc + 8448 + buf * 4352);
        const __half* Vf = (const __half*)(smc + 17152 + buf * 18432);

        // S = Q K^T : 16 q x 64 k per warp
        float S[8][4];
#pragma unroll
        for (int nt = 0; nt < 8; nt++) {
            S[nt][0] = S[nt][1] = S[nt][2] = S[nt][3] = 0.0f;
#pragma unroll
            for (int s = 0; s < 2; s++) {
                uint32_t bfr[2];
                const int key = nt * 8 + (lane >> 2);
                bfr[0] = __float_as_uint(Kf[(8 * s + (lane & 3)) * 68 + key]);
                bfr[1] = __float_as_uint(Kf[(8 * s + (lane & 3) + 4) * 68 + key]);
                mma_tf32(S[nt], qfr[s], bfr);
            }
        }

        // Online softmax (rows r0 = qbase+lane>>2, r1 = r0+8)
        float tm0 = -1e30f, tm1 = -1e30f;
#pragma unroll
        for (int nt = 0; nt < 8; nt++) {
            tm0 = fmaxf(tm0, fmaxf(S[nt][0], S[nt][1]));
            tm1 = fmaxf(tm1, fmaxf(S[nt][2], S[nt][3]));
        }
        tm0 = fmaxf(tm0, __shfl_xor_sync(0xffffffffu, tm0, 1));
        tm0 = fmaxf(tm0, __shfl_xor_sync(0xffffffffu, tm0, 2));
        tm1 = fmaxf(tm1, __shfl_xor_sync(0xffffffffu, tm1, 1));
        tm1 = fmaxf(tm1, __shfl_xor_sync(0xffffffffu, tm1, 2));
        const float mn0 = fmaxf(mrun0, tm0), mn1 = fmaxf(mrun1, tm1);
        const float f0 = fexp(mrun0 - mn0), f1 = fexp(mrun1 - mn1);
        mrun0 = mn0; mrun1 = mn1;

        float ts0 = 0.0f, ts1 = 0.0f;
        uint32_t afr[4][4];
#pragma unroll
        for (int j = 0; j < 4; j++) {
            float p00 = fexp(S[2 * j][0] - mn0), p01 = fexp(S[2 * j][1] - mn0);
            float p10 = fexp(S[2 * j][2] - mn1), p11 = fexp(S[2 * j][3] - mn1);
            float q00 = fexp(S[2 * j + 1][0] - mn0), q01 = fexp(S[2 * j + 1][1] - mn0);
            float q10 = fexp(S[2 * j + 1][2] - mn1), q11 = fexp(S[2 * j + 1][3] - mn1);
            ts0 += (p00 + p01) + (q00 + q01);
            ts1 += (p10 + p11) + (q10 + q11);
            afr[j][0] = ph2(p00, p01);
            afr[j][1] = ph2(p10, p11);
            afr[j][2] = ph2(q00, q01);
            afr[j][3] = ph2(q10, q11);
        }
        ts0 += __shfl_xor_sync(0xffffffffu, ts0, 1);
        ts0 += __shfl_xor_sync(0xffffffffu, ts0, 2);
        ts1 += __shfl_xor_sync(0xffffffffu, ts1, 1);
        ts1 += __shfl_xor_sync(0xffffffffu, ts1, 2);
        lrun0 = lrun0 * f0 + ts0;
        lrun1 = lrun1 * f1 + ts1;

#pragma unroll
        for (int nc = 0; nc < 16; nc++) {
            O[nc][0] *= f0; O[nc][1] *= f0;
            O[nc][2] *= f1; O[nc][3] *= f1;
        }

        // O += P V : 16 q x 128 ch, K = 64 keys (4 k-chunks of 16)
#pragma unroll
        for (int nc = 0; nc < 16; nc++) {
            const int chrow = nc * 8 + (lane >> 2);
#pragma unroll
            for (int j = 0; j < 4; j++) {
                uint32_t bfr[2];
                const __half* vp = Vf + chrow * 72 + j * 16 + 2 * (lane & 3);
                bfr[0] = *(const uint32_t*)vp;
                bfr[1] = *(const uint32_t*)(vp + 8);
                mma_f16(O[nc], afr[j], bfr);
            }
        }
        __syncthreads();
    }

    // Epilogue: alpha * (O / l) + y -> padded NHWC
    const float linv0 = 1.0f / lrun0, linv1 = 1.0f / lrun1;
    const float a = alpha[0];
    const int px0 = n0 + qbase + (lane >> 2);
    const int px1 = px0 + 8;
    float* dst0 = xp2 + (((size_t)b * XP_H + (px0 >> 6) + 1) * XP_H + (px0 & 63) + 1) * CI;
    float* dst1 = xp2 + (((size_t)b * XP_H + (px1 >> 6) + 1) * XP_H + (px1 & 63) + 1) * CI;
#pragma unroll
    for (int nc = 0; nc < 16; nc++) {
        const int ch = nc * 8 + 2 * (lane & 3);
        const float* y0 = y + ((size_t)b * 128 + ch) * NPIX;
        float2 v0, v1;
        v0.x = tf32r(fmaf(a, O[nc][0] * linv0, y0[px0]));
        v0.y = tf32r(fmaf(a, O[nc][1] * linv0, y0[NPIX + px0]));
        v1.x = tf32r(fmaf(a, O[nc][2] * linv1, y0[px1]));
        v1.y = tf32r(fmaf(a, O[nc][3] * linv1, y0[NPIX + px1]));
        *(float2*)(dst0 + ch) = v0;
        *(float2*)(dst1 + ch) = v1;
    }
}

// ---------------------------------------------------------------------------
// CAM gram matrix
// ---------------------------------------------------------------------------
__global__ void cam_energy_kernel(const float* __restrict__ y,
                                  float* __restrict__ energy) {
    const int b  = blockIdx.y;
    const int tc = (blockIdx.x / 8) * 16;
    const int td = (blockIdx.x % 8) * 16;
    const int tid = threadIdx.x;
    const int li = tid / 16, lj = tid % 16;

    __shared__ float As[16][65];
    __shared__ float Bs[16][65];

    const float* yb = y + (size_t)b * 128 * NPIX;
    float acc = 0.0f;
    for (int n0 = 0; n0 < NPIX; n0 += 64) {
        for (int i = tid; i < 1024; i += 256) {
            int r = i >> 6, c = i & 63;
            As[r][c] = yb[(size_t)(tc + r) * NPIX + n0 + c];
            Bs[r][c] = yb[(size_t)(td + r) * NPIX + n0 + c];
        }
        __syncthreads();
#pragma unroll 16
        for (int k = 0; k < 64; k++) acc += As[li][k] * Bs[lj][k];
        __syncthreads();
    }
    energy[((size_t)b * 128 + tc + li) * 128 + td + lj] = acc;
}

// ---------------------------------------------------------------------------
// CAM softmax of (rowmax - E)
// ---------------------------------------------------------------------------
__global__ void cam_softmax_kernel(const float* __restrict__ energy,
                                   float* __restrict__ attn) {
    const int row = blockIdx.x;
    const int tid = threadIdx.x;
    __shared__ float red[4];

    float e = energy[(size_t)row * 128 + tid];

    float m = e;
#pragma unroll
    for (int off = 16; off; off >>= 1) m = fmaxf(m, __shfl_xor_sync(0xffffffff, m, off));
    if ((tid & 31) == 0) red[tid >> 5] = m;
    __syncthreads();
    float mx = fmaxf(fmaxf(red[0], red[1]), fmaxf(red[2], red[3]));
    float e2 = mx - e;
    __syncthreads();

    float m2 = e2;
#pragma unroll
    for (int off = 16; off; off >>= 1) m2 = fmaxf(m2, __shfl_xor_sync(0xffffffff, m2, off));
    if ((tid & 31) == 0) red[tid >> 5] = m2;
    __syncthreads();
    m2 = fmaxf(fmaxf(red[0], red[1]), fmaxf(red[2], red[3]));
    float p = __expf(e2 - m2);
    __syncthreads();

    float s = p;
#pragma unroll
    for (int off = 16; off; off >>= 1) s += __shfl_xor_sync(0xffffffff, s, off);
    if ((tid & 31) == 0) red[tid >> 5] = s;
    __syncthreads();
    s = red[0] + red[1] + red[2] + red[3];

    attn[(size_t)row * 128 + tid] = p / s;
}

// ---------------------------------------------------------------------------
// CAM feature -> padded NHWC conv2 input
// ---------------------------------------------------------------------------
__global__ void cam_feat_kernel(const float* __restrict__ y,
                                const float* __restrict__ attn,
                                const float* __restrict__ beta,
                                float* __restrict__ xp2) {
    __shared__ float As[128][32];
    const int tid = threadIdx.x;
    const int b   = blockIdx.y;
    const int n0  = blockIdx.x * 128;
    const int px  = n0 + (tid & 127);
    const int half_ = (tid >> 7) * 64;

    float acc[64];
#pragma unroll
    for (int o = 0; o < 64; o++) acc[o] = 0.0f;

    const float* yp = y + (size_t)b * 128 * NPIX + px;
    const float* ap = attn + (size_t)b * 128 * 128;
    for (int d0 = 0; d0 < 128; d0 += 32) {
        __syncthreads();
        for (int i = tid; i < 128 * 32; i += 256) {
            int c = i >> 5, dl = i & 31;
            As[c][dl] = ap[c * 128 + d0 + dl];
        }
        __syncthreads();
        for (int dl = 0; dl < 32; dl++) {
            float v = yp[(size_t)(d0 + dl) * NPIX];
#pragma unroll
            for (int o = 0; o < 64; o++) acc[o] += As[half_ + o][dl] * v;
        }
    }
    const float bet = beta[0];
    float* dst = xp2 + (((size_t)b * XP_H + (px >> 6) + 1) * XP_H + (px & 63) + 1) * CI + half_;
#pragma unroll
    for (int o = 0; o < 64; o += 4) {
        float4 v;
        v.x = tf32r(bet * acc[o + 0] + yp[(size_t)(half_ + o + 0) * NPIX]);
        v.y = tf32r(bet * acc[o + 1] + yp[(size_t)(half_ + o + 1) * NPIX]);
        v.z = tf32r(bet * acc[o + 2] + yp[(size_t)(half_ + o + 2) * NPIX]);
        v.w = tf32r(bet * acc[o + 3] + yp[(size_t)(half_ + o + 3) * NPIX]);
        *(float4*)(dst + o) = v;
    }
}

// ---------------------------------------------------------------------------
// Final heads: three 1x1 convs (128->19) + sigmoid, fused.
// ---------------------------------------------------------------------------
__global__ void final_kernel(const float* __restrict__ fp,
                             const float* __restrict__ fc,
                             const float* __restrict__ Wout, const float* __restrict__ bout,
                             const float* __restrict__ Wp3, const float* __restrict__ bp3,
                             const float* __restrict__ Wc3, const float* __restrict__ bc3,
                             float* __restrict__ out) {
    const int b  = blockIdx.y;
    const int px = blockIdx.x * 256 + threadIdx.x;

    __shared__ float Wo[19][128];
    __shared__ float Wp[19][128];
    __shared__ float Wc[19][128];
    for (int i = threadIdx.x; i < 19 * 128; i += 256) {
        Wo[i / 128][i % 128] = Wout[i];
        Wp[i / 128][i % 128] = Wp3[i];
        Wc[i / 128][i % 128] = Wc3[i];
    }
    __syncthreads();

    float am[19], ap[19], ac[19];
#pragma unroll
    for (int o = 0; o < 19; o++) { am[o] = bout[o]; ap[o] = bp3[o]; ac[o] = bc3[o]; }

    for (int c = 0; c < 128; c++) {
        float vp = fp[((size_t)b * 128 + c) * NPIX + px];
        float vc = fc[((size_t)b * 128 + c) * NPIX + px];
        float vf = vp + vc;
#pragma unroll
        for (int o = 0; o < 19; o++) {
            am[o] += Wo[o][c] * vf;
            ap[o] += Wp[o][c] * vp;
            ac[o] += Wc[o][c] * vc;
        }
    }

    const size_t SEG = (size_t)BATCH * NC * NPIX;
#pragma unroll
    for (int o = 0; o < 19; o++) {
        size_t base = ((size_t)b * NC + o) * NPIX + px;
        out[base]           = sigmoidf_(am[o]);
        out[SEG + base]     = sigmoidf_(ap[o]);
        out[2 * SEG + base] = sigmoidf_(ac[o]);
    }
}

// ---------------------------------------------------------------------------
// Launch
// ---------------------------------------------------------------------------
extern "C" void kernel_launch(void* const* d_in, const int* in_sizes, int n_in,
                              void* d_out, int out_size) {
    const float* x    = (const float*)d_in[0];
    const float* Wp1  = (const float*)d_in[1];
    const float* bnp1 = (const float*)d_in[2];
    const float* Wc1  = (const float*)d_in[3];
    const float* bnc1 = (const float*)d_in[4];
    const float* Wb   = (const float*)d_in[5];
    const float* bb   = (const float*)d_in[6];
    const float* Wc   = (const float*)d_in[7];
    const float* bc   = (const float*)d_in[8];
    const float* Wd   = (const float*)d_in[9];
    const float* bd   = (const float*)d_in[10];
    const float* alpha= (const float*)d_in[11];
    const float* beta = (const float*)d_in[12];
    const float* Wp2  = (const float*)d_in[13];
    const float* bnp2 = (const float*)d_in[14];
    const float* Wc2  = (const float*)d_in[15];
    const float* bnc2 = (const float*)d_in[16];
    const float* Wout = (const float*)d_in[17];
    const float* bout = (const float*)d_in[18];
    const float* Wp3  = (const float*)d_in[19];
    const float* bp3  = (const float*)d_in[20];
    const float* Wc3  = (const float*)d_in[21];
    const float* bc3  = (const float*)d_in[22];
    float* out = (float*)d_out;

    float *featp1, *featc1, *qb, *kc, *featp2, *featc2, *energy, *attn;
    float *xpad, *xp2a, *xp2b, *wf1, *wf2;
    __half* vd;
    cudaGetSymbolAddress((void**)&featp1, g_featp1);
    cudaGetSymbolAddress((void**)&featc1, g_featc1);
    cudaGetSymbolAddress((void**)&qb,     g_qb);
    cudaGetSymbolAddress((void**)&kc,     g_kc);
    cudaGetSymbolAddress((void**)&vd,     g_vd);
    cudaGetSymbolAddress((void**)&featp2, g_featp2);
    cudaGetSymbolAddress((void**)&featc2, g_featc2);
    cudaGetSymbolAddress((void**)&energy, g_energy);
    cudaGetSymbolAddress((void**)&attn,   g_attn);
    cudaGetSymbolAddress((void**)&xpad,   g_xpad);
    cudaGetSymbolAddress((void**)&xp2a,   g_xp2a);
    cudaGetSymbolAddress((void**)&xp2b,   g_xp2b);
    cudaGetSymbolAddress((void**)&wf1,    g_wfrag1);
    cudaGetSymbolAddress((void**)&wf2,    g_wfrag2);

    cudaFuncSetAttribute(conv_mma_kernel<512>,
                         cudaFuncAttributeMaxDynamicSharedMemorySize, CONV_SMEM);
    cudaFuncSetAttribute(conv_mma_kernel<128>,
                         cudaFuncAttributeMaxDynamicSharedMemorySize, CONV_SMEM);
    cudaFuncSetAttribute(pam_attn_mma,
                         cudaFuncAttributeMaxDynamicSharedMemorySize, ATT_SMEM);

    // Packing
    pack_x_kernel<<<dim3(64, BATCH), 256>>>(x, xpad);
    zero_border_kernel<<<dim3(XP_H, BATCH), 256>>>(xpad, CIN);
    zero_border_kernel<<<dim3(XP_H, BATCH), 256>>>(xp2a, CI);
    zero_border_kernel<<<dim3(XP_H, BATCH), 256>>>(xp2b, CI);
    pack_w_frag<<<dim3(144, 2), 256>>>(Wp1, Wc1, wf1, CIN);
    pack_w_frag<<<dim3(36, 2), 256>>>(Wp2, Wc2, wf2, CI);

    // conv1: both 512->128 convs
    conv_mma_kernel<512><<<dim3(32, BATCH, 2), 256, CONV_SMEM>>>(
        xpad, xpad, wf1, bnp1, bnc1, featp1, featc1);

    // PAM
    pam_bc_kernel<<<dim3(32, BATCH), 128>>>(featp1, Wb, bb, Wc, bc, qb, kc);
    pam_d_kernel<<<dim3(32, BATCH), 256>>>(featp1, Wd, bd, vd);
    pam_attn_mma<<<dim3(32, BATCH), 256, ATT_SMEM>>>(qb, kc, vd, featp1, alpha, xp2a);

    // CAM
    cam_energy_kernel<<<dim3(64, BATCH), 256>>>(featc1, energy);
    cam_softmax_kernel<<<BATCH * 128, 128>>>(energy, attn);
    cam_feat_kernel<<<dim3(32, BATCH), 256>>>(featc1, attn, beta, xp2b);

    // conv2: both 128->128 convs
    conv_mma_kernel<128><<<dim3(32, BATCH, 2), 256, CONV_SMEM>>>(
        xp2a, xp2b, wf2, bnp2, bnc2, featp2, featc2);

    // Heads
    final_kernel<<<dim3(16, BATCH), 256>>>(featp2, featc2,
                                           Wout, bout, Wp3, bp3, Wc3, bc3, out);
}

// round 5
// speedup vs baseline: 5.0967x; 1.6160x over previous
#include <cuda_runtime.h>
#include <cuda_bf16.h>
#include <cuda_fp16.h>
#include <math.h>
#include <cstdint>

// ---------------------------------------------------------------------------
// Problem constants
// ---------------------------------------------------------------------------
#define BATCH 8
#define CIN   512
#define CI    128
#define CK    16
#define NC    19
#define NPIX  4096
#define FEAT_ELEMS (BATCH * CI * NPIX)
#define XP_H 66

// ---------------------------------------------------------------------------
// Scratch (device globals)
// ---------------------------------------------------------------------------
__device__ float  g_featp1[FEAT_ELEMS];
__device__ float  g_featc1[FEAT_ELEMS];
__device__ __half g_qh[BATCH * NPIX * CK];   // [b][n][d] fp16
__device__ __half g_kh[BATCH * NPIX * CK];   // [b][n][d] fp16
__device__ __half g_vd[FEAT_ELEMS];          // [b][ch][n] fp16
__device__ float  g_featp2[FEAT_ELEMS];
__device__ float  g_featc2[FEAT_ELEMS];
__device__ float  g_energy[BATCH * CI * CI];
__device__ float  g_attn[BATCH * CI * CI];
__device__ float  g_xpad[BATCH * XP_H * XP_H * CIN];
__device__ float  g_xp2a[BATCH * XP_H * XP_H * CI];
__device__ float  g_xp2b[BATCH * XP_H * XP_H * CI];
__device__ float  g_wfrag1[2 * 144 * 4096];
__device__ float  g_wfrag2[2 * 36 * 4096];

__device__ __forceinline__ float sigmoidf_(float x) {
    return 1.0f / (1.0f + __expf(-x));
}
__device__ __forceinline__ float tf32r(float x) {
    uint32_t u;
    asm("cvt.rna.tf32.f32 %0, %1;" : "=r"(u) : "f"(x));
    return __uint_as_float(u);
}
__device__ __forceinline__ uint32_t smem_u32(const void* p) {
    uint32_t a;
    asm("{ .reg .u64 t; cvta.to.shared.u64 t, %1; cvt.u32.u64 %0, t; }" : "=r"(a) : "l"(p));
    return a;
}
__device__ __forceinline__ void mma_tf32(float c[4], const uint32_t a[4], const uint32_t b[2]) {
    asm volatile(
        "mma.sync.aligned.m16n8k8.row.col.f32.tf32.tf32.f32 "
        "{%0,%1,%2,%3}, {%4,%5,%6,%7}, {%8,%9}, {%0,%1,%2,%3};"
        : "+f"(c[0]), "+f"(c[1]), "+f"(c[2]), "+f"(c[3])
        : "r"(a[0]), "r"(a[1]), "r"(a[2]), "r"(a[3]), "r"(b[0]), "r"(b[1]));
}
__device__ __forceinline__ void mma_f16(float c[4], const uint32_t a[4], const uint32_t b0, const uint32_t b1) {
    asm volatile(
        "mma.sync.aligned.m16n8k16.row.col.f32.f16.f16.f32 "
        "{%0,%1,%2,%3}, {%4,%5,%6,%7}, {%8,%9}, {%0,%1,%2,%3};"
        : "+f"(c[0]), "+f"(c[1]), "+f"(c[2]), "+f"(c[3])
        : "r"(a[0]), "r"(a[1]), "r"(a[2]), "r"(a[3]), "r"(b0), "r"(b1));
}
__device__ __forceinline__ void ldsm4(uint32_t r[4], uint32_t addr) {
    asm volatile("ldmatrix.sync.aligned.m8n8.x4.shared.b16 {%0,%1,%2,%3}, [%4];"
                 : "=r"(r[0]), "=r"(r[1]), "=r"(r[2]), "=r"(r[3]) : "r"(addr));
}
#define CP_ASYNC16(dst, src) \
    asm volatile("cp.async.ca.shared.global [%0], [%1], 16;" :: "r"(dst), "l"(src))
#define CP_COMMIT() asm volatile("cp.async.commit_group;")
#define CP_WAIT(N)  asm volatile("cp.async.wait_group %0;" :: "n"(N))

// Fast e^x (x <= 0), magic-number rounding, FMA pipe only.
__device__ __forceinline__ float fexp(float x) {
    float t = fmaxf(x * 1.4426950408889634f, -126.0f);
    float y = t + 12582912.0f;                 // round(t) in mantissa
    int   k = __float_as_int(y);               // 0x4B400000 + round(t)
    float r = t - (y - 12582912.0f);           // r in [-0.5, 0.5]
    float p = 1.3333558e-3f;
    p = fmaf(p, r, 9.6181291e-3f);
    p = fmaf(p, r, 5.5504109e-2f);
    p = fmaf(p, r, 2.4022651e-1f);
    p = fmaf(p, r, 6.9314718e-1f);
    p = fmaf(p, r, 1.0f);
    return __int_as_float((k + (127 - 0x4B400000)) << 23) * p;
}
__device__ __forceinline__ uint32_t ph2(float x, float y) {
    __half2 h = __floats2half2_rn(x, y);
    return *(uint32_t*)&h;
}

// ---------------------------------------------------------------------------
// Pack x: f32 NCHW -> tf32 NHWC padded
// ---------------------------------------------------------------------------
__global__ void pack_x_kernel(const float* __restrict__ x, float* __restrict__ xp) {
    const int h = blockIdx.x, b = blockIdx.y, tid = threadIdx.x;
    __shared__ float s[32][65];
    for (int ci0 = 0; ci0 < CIN; ci0 += 32) {
        for (int idx = tid; idx < 32 * 64; idx += 256) {
            int ci_l = idx >> 6, w = idx & 63;
            s[ci_l][w] = x[(((size_t)b * CIN + ci0 + ci_l) * 64 + h) * 64 + w];
        }
        __syncthreads();
        for (int idx = tid; idx < 64 * 32; idx += 256) {
            int w = idx >> 5, ci_l = idx & 31;
            xp[(((size_t)b * XP_H + h + 1) * XP_H + w + 1) * CIN + ci0 + ci_l] = tf32r(s[ci_l][w]);
        }
        __syncthreads();
    }
}

__global__ void zero_border_kernel(float* __restrict__ xp, int C) {
    const int hp = blockIdx.x, b = blockIdx.y, tid = threadIdx.x;
    float* row = xp + ((size_t)b * XP_H + hp) * XP_H * C;
    if (hp == 0 || hp == XP_H - 1) {
        for (int idx = tid; idx < XP_H * C; idx += 256) row[idx] = 0.0f;
    } else {
        for (int idx = tid; idx < C; idx += 256) {
            row[idx] = 0.0f;
            row[(size_t)(XP_H - 1) * C + idx] = 0.0f;
        }
    }
}

// ---------------------------------------------------------------------------
// Pack weights into m16n8k8 tf32 A-fragment order.
// ---------------------------------------------------------------------------
__global__ void pack_w_frag(const float* __restrict__ W0, const float* __restrict__ W1,
                            float* __restrict__ wf, int CIN_T) {
    const int cpc = CIN_T / 32;
    const int chunk = blockIdx.x;
    const int kwh = chunk / cpc, cb = chunk % cpc;
    const float* W = blockIdx.y ? W1 : W0;
    float* dst = wf + ((size_t)blockIdx.y * gridDim.x + chunk) * 4096;
    for (int t = 0; t < 16; t++) {
        int idx = threadIdx.x + t * 256;
        int j = idx & 3, lane = (idx >> 2) & 31, s = (idx >> 7) & 3, mt = idx >> 9;
        int co = mt * 16 + (lane >> 2) + ((j & 1) << 3);
        int ci = cb * 32 + s * 8 + (lane & 3) + ((j >> 1) << 2);
        dst[idx] = tf32r(W[((size_t)co * CIN_T + ci) * 9 + kwh]);
    }
}

// ---------------------------------------------------------------------------
// conv3x3 via implicit GEMM on mma.sync tf32, fused BN+ReLU.
// ---------------------------------------------------------------------------
#define CONV_SMEM (69632)

template<int CIN_T>
__global__ void __launch_bounds__(256, 2) conv_mma_kernel(
        const float* __restrict__ xpA, const float* __restrict__ xpB,
        const float* __restrict__ wfrag,
        const float* __restrict__ bn0, const float* __restrict__ bn1,
        float* __restrict__ out0, float* __restrict__ out1) {
    constexpr int CPC = CIN_T / 32;
    constexpr int NCHUNK = 9 * CPC;
    extern __shared__ __align__(16) float sm[];
    float* Abuf = sm;
    float* Bbuf = sm + 8192;
    const uint32_t smb = smem_u32(sm);

    const int tid = threadIdx.x, lane = tid & 31, wid = tid >> 5;
    const int warp_m = wid >> 2, warp_n = wid & 3;
    const int b = blockIdx.y, z = blockIdx.z;
    const int pxbase = blockIdx.x * 128;
    const int h0 = pxbase >> 6;
    const float* xp = z ? xpB : xpA;
    const float* Wf = wfrag + (size_t)z * NCHUNK * 4096;
    const float* bn = z ? bn1 : bn0;
    float* out = z ? out1 : out0;

    float acc[4][4][4];
#pragma unroll
    for (int mt = 0; mt < 4; mt++)
#pragma unroll
        for (int nt = 0; nt < 4; nt++)
#pragma unroll
            for (int r = 0; r < 4; r++) acc[mt][nt][r] = 0.0f;

    auto stage = [&](int i, int buf) {
        const int kwh = i / CPC, cb = i % CPC;
        const int kh = kwh / 3, kw = kwh % 3;
        const float* Asrc = Wf + (size_t)i * 4096;
        const uint32_t Adst = smb + buf * 16384;
#pragma unroll
        for (int t = 0; t < 4; t++) {
            int i4 = tid + t * 256;
            CP_ASYNC16(Adst + i4 * 16, Asrc + i4 * 4);
        }
        const float* Bsrc0 = xp + (((size_t)b * XP_H + h0 + kh) * XP_H + kw) * CIN_T + cb * 32;
        const uint32_t Bdst = smb + 32768 + buf * 18432;
#pragma unroll
        for (int t = 0; t < 4; t++) {
            int idx = tid + t * 256;
            int px = idx >> 3, q = idx & 7;
            const float* src = Bsrc0 + (size_t)(px >> 6) * (XP_H * CIN_T) + (px & 63) * CIN_T + q * 4;
            CP_ASYNC16(Bdst + (px * 36 + q * 4) * 4, src);
        }
        CP_COMMIT();
    };

    stage(0, 0);
    for (int i = 0; i < NCHUNK; i++) {
        const int buf = i & 1;
        if (i + 1 < NCHUNK) {
            stage(i + 1, buf ^ 1);
            CP_WAIT(1);
        } else {
            CP_WAIT(0);
        }
        __syncthreads();

        const float* A = Abuf + buf * 4096;
        const float* B = Bbuf + buf * 4608;
#pragma unroll
        for (int s = 0; s < 4; s++) {
            uint32_t afr[4][4];
#pragma unroll
            for (int mt = 0; mt < 4; mt++) {
                const float4 v = *(const float4*)&A[((warp_m * 4 + mt) * 4 + s) * 128 + lane * 4];
                afr[mt][0] = __float_as_uint(v.x);
                afr[mt][1] = __float_as_uint(v.y);
                afr[mt][2] = __float_as_uint(v.z);
                afr[mt][3] = __float_as_uint(v.w);
            }
            uint32_t bfr[4][2];
#pragma unroll
            for (int nt = 0; nt < 4; nt++) {
                const int pxn = warp_n * 32 + nt * 8 + (lane >> 2);
                bfr[nt][0] = __float_as_uint(B[pxn * 36 + s * 8 + (lane & 3)]);
                bfr[nt][1] = __float_as_uint(B[pxn * 36 + s * 8 + (lane & 3) + 4]);
            }
#pragma unroll
            for (int mt = 0; mt < 4; mt++)
#pragma unroll
                for (int nt = 0; nt < 4; nt++)
                    mma_tf32(acc[mt][nt], afr[mt], bfr[nt]);
        }
        __syncthreads();
    }

#pragma unroll
    for (int mt = 0; mt < 4; mt++) {
        const int co = warp_m * 64 + mt * 16 + (lane >> 2);
        const float sc0 = bn[co],     sh0 = bn[128 + co];
        const float sc8 = bn[co + 8], sh8 = bn[136 + co];
        float* o0 = out + ((size_t)b * 128 + co) * NPIX;
        float* o8 = o0 + 8 * NPIX;
#pragma unroll
        for (int nt = 0; nt < 4; nt++) {
            const int px = pxbase + warp_n * 32 + nt * 8 + 2 * (lane & 3);
            float2 v0, v1;
            v0.x = fmaxf(acc[mt][nt][0] * sc0 + sh0, 0.0f);
            v0.y = fmaxf(acc[mt][nt][1] * sc0 + sh0, 0.0f);
            v1.x = fmaxf(acc[mt][nt][2] * sc8 + sh8, 0.0f);
            v1.y = fmaxf(acc[mt][nt][3] * sc8 + sh8, 0.0f);
            *(float2*)(o0 + px) = v0;
            *(float2*)(o8 + px) = v1;
        }
    }
}

// ---------------------------------------------------------------------------
// PAM query/key projections -> fp16 [b][n][d]
// ---------------------------------------------------------------------------
__global__ void pam_bc_kernel(const float* __restrict__ y,
                              const float* __restrict__ Wb, const float* __restrict__ bb,
                              const float* __restrict__ Wc, const float* __restrict__ bc,
                              __half* __restrict__ outq, __half* __restrict__ outk) {
    const int b  = blockIdx.y;
    const int n0 = blockIdx.x * 128;
    const int tid = threadIdx.x;

    __shared__ float Wbs[16][128];
    __shared__ float Wcs[16][128];
    for (int i = tid; i < 16 * 128; i += 128) {
        Wbs[i >> 7][i & 127] = Wb[i];
        Wcs[i >> 7][i & 127] = Wc[i];
    }
    __syncthreads();

    float ab[16], ac[16];
#pragma unroll
    for (int o = 0; o < 16; o++) { ab[o] = bb[o]; ac[o] = bc[o]; }

    const float* yp = y + (size_t)b * 128 * NPIX + n0 + tid;
    for (int c = 0; c < 128; c++) {
        float v = yp[(size_t)c * NPIX];
#pragma unroll
        for (int o = 0; o < 16; o++) {
            ab[o] += Wbs[o][c] * v;
            ac[o] += Wcs[o][c] * v;
        }
    }
    uint32_t pq[8], pk[8];
#pragma unroll
    for (int o = 0; o < 16; o += 2) {
        pq[o >> 1] = ph2(ab[o], ab[o + 1]);
        pk[o >> 1] = ph2(ac[o], ac[o + 1]);
    }
    __half* dq = outq + ((size_t)b * NPIX + n0 + tid) * 16;
    __half* dk = outk + ((size_t)b * NPIX + n0 + tid) * 16;
    ((uint4*)dq)[0] = make_uint4(pq[0], pq[1], pq[2], pq[3]);
    ((uint4*)dq)[1] = make_uint4(pq[4], pq[5], pq[6], pq[7]);
    ((uint4*)dk)[0] = make_uint4(pk[0], pk[1], pk[2], pk[3]);
    ((uint4*)dk)[1] = make_uint4(pk[4], pk[5], pk[6], pk[7]);
}

// ---------------------------------------------------------------------------
// PAM value projection -> fp16 [b][ch][n]
// ---------------------------------------------------------------------------
__global__ void pam_d_kernel(const float* __restrict__ y,
                             const float* __restrict__ Wd,
                             const float* __restrict__ bd,
                             __half* __restrict__ outd) {
    __shared__ float Ws[128][32];
    const int tid = threadIdx.x;
    const int b   = blockIdx.y;
    const int n0  = blockIdx.x * 128;
    const int px  = n0 + (tid & 127);
    const int half_ = (tid >> 7) * 64;

    float acc[64];
#pragma unroll
    for (int o = 0; o < 64; o++) acc[o] = bd[half_ + o];

    const float* yp = y + (size_t)b * 128 * NPIX + px;
    for (int c0 = 0; c0 < 128; c0 += 32) {
        __syncthreads();
        for (int i = tid; i < 128 * 32; i += 256) {
            int o = i >> 5, cl = i & 31;
            Ws[o][cl] = Wd[o * 128 + c0 + cl];
        }
        __syncthreads();
        for (int cl = 0; cl < 32; cl++) {
            float v = yp[(size_t)(c0 + cl) * NPIX];
#pragma unroll
            for (int o = 0; o < 64; o++) acc[o] += Ws[half_ + o][cl] * v;
        }
    }
#pragma unroll
    for (int o = 0; o < 64; o++)
        outd[((size_t)b * 128 + half_ + o) * NPIX + px] = __float2half_rn(acc[o]);
}

// ---------------------------------------------------------------------------
// PAM flash attention: fp16 QK^T (d=16, one m16n8k16 per 16x8) + fp16 P·V,
// all fragments via ldmatrix.x4.  grid (32 q-tiles, 8 batch), block 256.
// SMEM: Q [128][48B] @0 (6144); K 2x[64][48B] @6144; V 2x[128][144B] @12288.
// ---------------------------------------------------------------------------
#define ATT_SMEM 49152

__global__ void __launch_bounds__(256, 1) pam_attn_mma(
        const __half* __restrict__ qh, const __half* __restrict__ kh,
        const __half* __restrict__ vd, const float* __restrict__ y,
        const float* __restrict__ alpha, float* __restrict__ xp2) {
    extern __shared__ __align__(16) char smc[];
    const uint32_t smb = smem_u32(smc);
    const uint32_t Qb  = smb;
    const uint32_t Kb0 = smb + 6144;
    const uint32_t Vb0 = smb + 12288;

    const int tid = threadIdx.x, lane = tid & 31, wid = tid >> 5;
    const int b = blockIdx.y;
    const int n0 = blockIdx.x * 128;
    const int qbase = wid * 16;

    // ldmatrix per-lane offsets
    const int g = lane >> 3, r8 = lane & 7;
    const uint32_t qoff = (uint32_t)(((g & 1) * 8 + r8) * 48 + (g >> 1) * 16);
    const uint32_t koff = (uint32_t)(((g >> 1) * 8 + r8) * 48 + (g & 1) * 16);
    const uint32_t voff = (uint32_t)(((g >> 1) * 8 + r8) * 144 + (g & 1) * 16);

    auto stageKV = [&](int t, int buf) {
        const int k0 = t * 64;
        if (tid < 128) {
            int row = tid >> 1, h = tid & 1;
            CP_ASYNC16(Kb0 + buf * 3072 + row * 48 + h * 16,
                       kh + ((size_t)b * NPIX + k0 + row) * 16 + h * 8);
        }
#pragma unroll
        for (int t4 = 0; t4 < 4; t4++) {
            int idx = tid + t4 * 256;
            int ch = idx >> 3, c = idx & 7;
            CP_ASYNC16(Vb0 + buf * 18432 + ch * 144 + c * 16,
                       vd + ((size_t)b * 128 + ch) * NPIX + k0 + c * 8);
        }
        CP_COMMIT();
    };

    // Stage Q (once) + tile 0 in the first group
    {
        int row = tid >> 1, h = tid & 1;
        CP_ASYNC16(Qb + row * 48 + h * 16,
                   qh + ((size_t)b * NPIX + n0 + row) * 16 + h * 8);
    }
    stageKV(0, 0);

    uint32_t qfr[4];
    float O[16][4];
#pragma unroll
    for (int nc = 0; nc < 16; nc++)
#pragma unroll
        for (int r = 0; r < 4; r++) O[nc][r] = 0.0f;
    float mrun0 = -1e30f, mrun1 = -1e30f, lrun0 = 0.0f, lrun1 = 0.0f;

    for (int t = 0; t < 64; t++) {
        const int buf = t & 1;
        CP_WAIT(0);
        __syncthreads();
        if (t + 1 < 64) stageKV(t + 1, buf ^ 1);
        if (t == 0) ldsm4(qfr, Qb + qbase * 48 + qoff);

        const uint32_t Kb = Kb0 + buf * 3072;
        const uint32_t Vb = Vb0 + buf * 18432;

        // S = Q K^T : 16q x 64k per warp (8 mmas, 4 ldmatrix.x4)
        float S[8][4];
#pragma unroll
        for (int ks = 0; ks < 4; ks++) {
            uint32_t kb[4];
            ldsm4(kb, Kb + ks * 768 + koff);
#pragma unroll
            for (int r = 0; r < 4; r++) { S[2 * ks][r] = 0.0f; S[2 * ks + 1][r] = 0.0f; }
            mma_f16(S[2 * ks],     qfr, kb[0], kb[1]);
            mma_f16(S[2 * ks + 1], qfr, kb[2], kb[3]);
        }

        // Online softmax
        float tm0 = -1e30f, tm1 = -1e30f;
#pragma unroll
        for (int nt = 0; nt < 8; nt++) {
            tm0 = fmaxf(tm0, fmaxf(S[nt][0], S[nt][1]));
            tm1 = fmaxf(tm1, fmaxf(S[nt][2], S[nt][3]));
        }
        tm0 = fmaxf(tm0, __shfl_xor_sync(0xffffffffu, tm0, 1));
        tm0 = fmaxf(tm0, __shfl_xor_sync(0xffffffffu, tm0, 2));
        tm1 = fmaxf(tm1, __shfl_xor_sync(0xffffffffu, tm1, 1));
        tm1 = fmaxf(tm1, __shfl_xor_sync(0xffffffffu, tm1, 2));
        const float mn0 = fmaxf(mrun0, tm0), mn1 = fmaxf(mrun1, tm1);
        const float f0 = fexp(mrun0 - mn0), f1 = fexp(mrun1 - mn1);
        mrun0 = mn0; mrun1 = mn1;

        float ts0 = 0.0f, ts1 = 0.0f;
        uint32_t afr[4][4];
#pragma unroll
        for (int j = 0; j < 4; j++) {
            float p00 = fexp(S[2 * j][0] - mn0), p01 = fexp(S[2 * j][1] - mn0);
            float p10 = fexp(S[2 * j][2] - mn1), p11 = fexp(S[2 * j][3] - mn1);
            float q00 = fexp(S[2 * j + 1][0] - mn0), q01 = fexp(S[2 * j + 1][1] - mn0);
            float q10 = fexp(S[2 * j + 1][2] - mn1), q11 = fexp(S[2 * j + 1][3] - mn1);
            ts0 += (p00 + p01) + (q00 + q01);
            ts1 += (p10 + p11) + (q10 + q11);
            afr[j][0] = ph2(p00, p01);
            afr[j][1] = ph2(p10, p11);
            afr[j][2] = ph2(q00, q01);
            afr[j][3] = ph2(q10, q11);
        }
        ts0 += __shfl_xor_sync(0xffffffffu, ts0, 1);
        ts0 += __shfl_xor_sync(0xffffffffu, ts0, 2);
        ts1 += __shfl_xor_sync(0xffffffffu, ts1, 1);
        ts1 += __shfl_xor_sync(0xffffffffu, ts1, 2);
        lrun0 = lrun0 * f0 + ts0;
        lrun1 = lrun1 * f1 + ts1;

#pragma unroll
        for (int nc = 0; nc < 16; nc++) {
            O[nc][0] *= f0; O[nc][1] *= f0;
            O[nc][2] *= f1; O[nc][3] *= f1;
        }

        // O += P V : 32 ldmatrix.x4 + 64 mmas per tile
#pragma unroll
        for (int j = 0; j < 4; j++) {
            const uint32_t vb_j = Vb + j * 32 + voff;
#pragma unroll
            for (int p = 0; p < 8; p++) {
                uint32_t vb[4];
                ldsm4(vb, vb_j + p * 2304);
                mma_f16(O[2 * p],     afr[j], vb[0], vb[1]);
                mma_f16(O[2 * p + 1], afr[j], vb[2], vb[3]);
            }
        }
    }

    // Epilogue: alpha * (O / l) + y -> padded NHWC
    const float linv0 = 1.0f / lrun0, linv1 = 1.0f / lrun1;
    const float a = alpha[0];
    const int px0 = n0 + qbase + (lane >> 2);
    const int px1 = px0 + 8;
    float* dst0 = xp2 + (((size_t)b * XP_H + (px0 >> 6) + 1) * XP_H + (px0 & 63) + 1) * CI;
    float* dst1 = xp2 + (((size_t)b * XP_H + (px1 >> 6) + 1) * XP_H + (px1 & 63) + 1) * CI;
#pragma unroll
    for (int nc = 0; nc < 16; nc++) {
        const int ch = nc * 8 + 2 * (lane & 3);
        const float* y0 = y + ((size_t)b * 128 + ch) * NPIX;
        float2 v0, v1;
        v0.x = tf32r(fmaf(a, O[nc][0] * linv0, y0[px0]));
        v0.y = tf32r(fmaf(a, O[nc][1] * linv0, y0[NPIX + px0]));
        v1.x = tf32r(fmaf(a, O[nc][2] * linv1, y0[px1]));
        v1.y = tf32r(fmaf(a, O[nc][3] * linv1, y0[NPIX + px1]));
        *(float2*)(dst0 + ch) = v0;
        *(float2*)(dst1 + ch) = v1;
    }
}

// ---------------------------------------------------------------------------
// CAM gram matrix
// ---------------------------------------------------------------------------
__global__ void cam_energy_kernel(const float* __restrict__ y,
                                  float* __restrict__ energy) {
    const int b  = blockIdx.y;
    const int tc = (blockIdx.x / 8) * 16;
    const int td = (blockIdx.x % 8) * 16;
    const int tid = threadIdx.x;
    const int li = tid / 16, lj = tid % 16;

    __shared__ float As[16][65];
    __shared__ float Bs[16][65];

    const float* yb = y + (size_t)b * 128 * NPIX;
    float acc = 0.0f;
    for (int n0 = 0; n0 < NPIX; n0 += 64) {
        for (int i = tid; i < 1024; i += 256) {
            int r = i >> 6, c = i & 63;
            As[r][c] = yb[(size_t)(tc + r) * NPIX + n0 + c];
            Bs[r][c] = yb[(size_t)(td + r) * NPIX + n0 + c];
        }
        __syncthreads();
#pragma unroll 16
        for (int k = 0; k < 64; k++) acc += As[li][k] * Bs[lj][k];
        __syncthreads();
    }
    energy[((size_t)b * 128 + tc + li) * 128 + td + lj] = acc;
}

// ---------------------------------------------------------------------------
// CAM softmax of (rowmax - E)
// ---------------------------------------------------------------------------
__global__ void cam_softmax_kernel(const float* __restrict__ energy,
                                   float* __restrict__ attn) {
    const int row = blockIdx.x;
    const int tid = threadIdx.x;
    __shared__ float red[4];

    float e = energy[(size_t)row * 128 + tid];

    float m = e;
#pragma unroll
    for (int off = 16; off; off >>= 1) m = fmaxf(m, __shfl_xor_sync(0xffffffff, m, off));
    if ((tid & 31) == 0) red[tid >> 5] = m;
    __syncthreads();
    float mx = fmaxf(fmaxf(red[0], red[1]), fmaxf(red[2], red[3]));
    float e2 = mx - e;
    __syncthreads();

    float m2 = e2;
#pragma unroll
    for (int off = 16; off; off >>= 1) m2 = fmaxf(m2, __shfl_xor_sync(0xffffffff, m2, off));
    if ((tid & 31) == 0) red[tid >> 5] = m2;
    __syncthreads();
    m2 = fmaxf(fmaxf(red[0], red[1]), fmaxf(red[2], red[3]));
    float p = __expf(e2 - m2);
    __syncthreads();

    float s = p;
#pragma unroll
    for (int off = 16; off; off >>= 1) s += __shfl_xor_sync(0xffffffff, s, off);
    if ((tid & 31) == 0) red[tid >> 5] = s;
    __syncthreads();
    s = red[0] + red[1] + red[2] + red[3];

    attn[(size_t)row * 128 + tid] = p / s;
}

// ---------------------------------------------------------------------------
// CAM feature -> padded NHWC conv2 input
// ---------------------------------------------------------------------------
__global__ void cam_feat_kernel(const float* __restrict__ y,
                                const float* __restrict__ attn,
                                const float* __restrict__ beta,
                                float* __restrict__ xp2) {
    __shared__ float As[128][32];
    const int tid = threadIdx.x;
    const int b   = blockIdx.y;
    const int n0  = blockIdx.x * 128;
    const int px  = n0 + (tid & 127);
    const int half_ = (tid >> 7) * 64;

    float acc[64];
#pragma unroll
    for (int o = 0; o < 64; o++) acc[o] = 0.0f;

    const float* yp = y + (size_t)b * 128 * NPIX + px;
    const float* ap = attn + (size_t)b * 128 * 128;
    for (int d0 = 0; d0 < 128; d0 += 32) {
        __syncthreads();
        for (int i = tid; i < 128 * 32; i += 256) {
            int c = i >> 5, dl = i & 31;
            As[c][dl] = ap[c * 128 + d0 + dl];
        }
        __syncthreads();
        for (int dl = 0; dl < 32; dl++) {
            float v = yp[(size_t)(d0 + dl) * NPIX];
#pragma unroll
            for (int o = 0; o < 64; o++) acc[o] += As[half_ + o][dl] * v;
        }
    }
    const float bet = beta[0];
    float* dst = xp2 + (((size_t)b * XP_H + (px >> 6) + 1) * XP_H + (px & 63) + 1) * CI + half_;
#pragma unroll
    for (int o = 0; o < 64; o += 4) {
        float4 v;
        v.x = tf32r(bet * acc[o + 0] + yp[(size_t)(half_ + o + 0) * NPIX]);
        v.y = tf32r(bet * acc[o + 1] + yp[(size_t)(half_ + o + 1) * NPIX]);
        v.z = tf32r(bet * acc[o + 2] + yp[(size_t)(half_ + o + 2) * NPIX]);
        v.w = tf32r(bet * acc[o + 3] + yp[(size_t)(half_ + o + 3) * NPIX]);
        *(float4*)(dst + o) = v;
    }
}

// ---------------------------------------------------------------------------
// Final heads: three 1x1 convs (128->19) + sigmoid, fused.
// ---------------------------------------------------------------------------
__global__ void final_kernel(const float* __restrict__ fp,
                             const float* __restrict__ fc,
                             const float* __restrict__ Wout, const float* __restrict__ bout,
                             const float* __restrict__ Wp3, const float* __restrict__ bp3,
                             const float* __restrict__ Wc3, const float* __restrict__ bc3,
                             float* __restrict__ out) {
    const int b  = blockIdx.y;
    const int px = blockIdx.x * 256 + threadIdx.x;

    __shared__ float Wo[19][128];
    __shared__ float Wp[19][128];
    __shared__ float Wc[19][128];
    for (int i = threadIdx.x; i < 19 * 128; i += 256) {
        Wo[i / 128][i % 128] = Wout[i];
        Wp[i / 128][i % 128] = Wp3[i];
        Wc[i / 128][i % 128] = Wc3[i];
    }
    __syncthreads();

    float am[19], ap[19], ac[19];
#pragma unroll
    for (int o = 0; o < 19; o++) { am[o] = bout[o]; ap[o] = bp3[o]; ac[o] = bc3[o]; }

    for (int c = 0; c < 128; c++) {
        float vp = fp[((size_t)b * 128 + c) * NPIX + px];
        float vc = fc[((size_t)b * 128 + c) * NPIX + px];
        float vf = vp + vc;
#pragma unroll
        for (int o = 0; o < 19; o++) {
            am[o] += Wo[o][c] * vf;
            ap[o] += Wp[o][c] * vp;
            ac[o] += Wc[o][c] * vc;
        }
    }

    const size_t SEG = (size_t)BATCH * NC * NPIX;
#pragma unroll
    for (int o = 0; o < 19; o++) {
        size_t base = ((size_t)b * NC + o) * NPIX + px;
        out[base]           = sigmoidf_(am[o]);
        out[SEG + base]     = sigmoidf_(ap[o]);
        out[2 * SEG + base] = sigmoidf_(ac[o]);
    }
}

// ---------------------------------------------------------------------------
// Launch
// ---------------------------------------------------------------------------
extern "C" void kernel_launch(void* const* d_in, const int* in_sizes, int n_in,
                              void* d_out, int out_size) {
    const float* x    = (const float*)d_in[0];
    const float* Wp1  = (const float*)d_in[1];
    const float* bnp1 = (const float*)d_in[2];
    const float* Wc1  = (const float*)d_in[3];
    const float* bnc1 = (const float*)d_in[4];
    const float* Wb   = (const float*)d_in[5];
    const float* bb   = (const float*)d_in[6];
    const float* Wc   = (const float*)d_in[7];
    const float* bc   = (const float*)d_in[8];
    const float* Wd   = (const float*)d_in[9];
    const float* bd   = (const float*)d_in[10];
    const float* alpha= (const float*)d_in[11];
    const float* beta = (const float*)d_in[12];
    const float* Wp2  = (const float*)d_in[13];
    const float* bnp2 = (const float*)d_in[14];
    const float* Wc2  = (const float*)d_in[15];
    const float* bnc2 = (const float*)d_in[16];
    const float* Wout = (const float*)d_in[17];
    const float* bout = (const float*)d_in[18];
    const float* Wp3  = (const float*)d_in[19];
    const float* bp3  = (const float*)d_in[20];
    const float* Wc3  = (const float*)d_in[21];
    const float* bc3  = (const float*)d_in[22];
    float* out = (float*)d_out;

    float *featp1, *featc1, *featp2, *featc2, *energy, *attn;
    float *xpad, *xp2a, *xp2b, *wf1, *wf2;
    __half *qh, *kh, *vd;
    cudaGetSymbolAddress((void**)&featp1, g_featp1);
    cudaGetSymbolAddress((void**)&featc1, g_featc1);
    cudaGetSymbolAddress((void**)&qh,     g_qh);
    cudaGetSymbolAddress((void**)&kh,     g_kh);
    cudaGetSymbolAddress((void**)&vd,     g_vd);
    cudaGetSymbolAddress((void**)&featp2, g_featp2);
    cudaGetSymbolAddress((void**)&featc2, g_featc2);
    cudaGetSymbolAddress((void**)&energy, g_energy);
    cudaGetSymbolAddress((void**)&attn,   g_attn);
    cudaGetSymbolAddress((void**)&xpad,   g_xpad);
    cudaGetSymbolAddress((void**)&xp2a,   g_xp2a);
    cudaGetSymbolAddress((void**)&xp2b,   g_xp2b);
    cudaGetSymbolAddress((void**)&wf1,    g_wfrag1);
    cudaGetSymbolAddress((void**)&wf2,    g_wfrag2);

    cudaFuncSetAttribute(conv_mma_kernel<512>,
                         cudaFuncAttributeMaxDynamicSharedMemorySize, CONV_SMEM);
    cudaFuncSetAttribute(conv_mma_kernel<128>,
                         cudaFuncAttributeMaxDynamicSharedMemorySize, CONV_SMEM);
    cudaFuncSetAttribute(pam_attn_mma,
                         cudaFuncAttributeMaxDynamicSharedMemorySize, ATT_SMEM);

    // Packing
    pack_x_kernel<<<dim3(64, BATCH), 256>>>(x, xpad);
    zero_border_kernel<<<dim3(XP_H, BATCH), 256>>>(xpad, CIN);
    zero_border_kernel<<<dim3(XP_H, BATCH), 256>>>(xp2a, CI);
    zero_border_kernel<<<dim3(XP_H, BATCH), 256>>>(xp2b, CI);
    pack_w_frag<<<dim3(144, 2), 256>>>(Wp1, Wc1, wf1, CIN);
    pack_w_frag<<<dim3(36, 2), 256>>>(Wp2, Wc2, wf2, CI);

    // conv1: both 512->128 convs
    conv_mma_kernel<512><<<dim3(32, BATCH, 2), 256, CONV_SMEM>>>(
        xpad, xpad, wf1, bnp1, bnc1, featp1, featc1);

    // PAM
    pam_bc_kernel<<<dim3(32, BATCH), 128>>>(featp1, Wb, bb, Wc, bc, qh, kh);
    pam_d_kernel<<<dim3(32, BATCH), 256>>>(featp1, Wd, bd, vd);
    pam_attn_mma<<<dim3(32, BATCH), 256, ATT_SMEM>>>(qh, kh, vd, featp1, alpha, xp2a);

    // CAM
    cam_energy_kernel<<<dim3(64, BATCH), 256>>>(featc1, energy);
    cam_softmax_kernel<<<BATCH * 128, 128>>>(energy, attn);
    cam_feat_kernel<<<dim3(32, BATCH), 256>>>(featc1, attn, beta, xp2b);

    // conv2: both 128->128 convs
    conv_mma_kernel<128><<<dim3(32, BATCH, 2), 256, CONV_SMEM>>>(
        xp2a, xp2b, wf2, bnp2, bnc2, featp2, featc2);

    // Heads
    final_kernel<<<dim3(16, BATCH), 256>>>(featp2, featc2,
                                           Wout, bout, Wp3, bp3, Wc3, bc3, out);
}

// round 6
// speedup vs baseline: 7.9049x; 1.5510x over previous
#include <cuda_runtime.h>
#include <cuda_bf16.h>
#include <cuda_fp16.h>
#include <math.h>
#include <cstdint>

// ---------------------------------------------------------------------------
// Problem constants
// ---------------------------------------------------------------------------
#define BATCH 8
#define CIN   512
#define CI    128
#define CK    16
#define NC    19
#define NPIX  4096
#define FEAT_ELEMS (BATCH * CI * NPIX)
#define XP_H 66

// ---------------------------------------------------------------------------
// Scratch (device globals)
// ---------------------------------------------------------------------------
__device__ float  g_featp1[FEAT_ELEMS];
__device__ float  g_featc1[FEAT_ELEMS];
__device__ __half g_featp1h[FEAT_ELEMS];     // fp16 NCHW copy (qkv GEMM B)
__device__ __half g_featc1h[FEAT_ELEMS];     // fp16 NCHW copy (cam_feat B)
__device__ __half g_qh[BATCH * NPIX * CK];   // [b][n][d]
__device__ __half g_kh[BATCH * NPIX * CK];   // [b][n][d]
__device__ __half g_vd[FEAT_ELEMS];          // [b][ch][n]
__device__ float  g_featp2[FEAT_ELEMS];
__device__ float  g_featc2[FEAT_ELEMS];
__device__ float  g_energy[BATCH * CI * CI];
__device__ __half g_attn16[BATCH * CI * CI];
__device__ __half g_xpad[BATCH * XP_H * XP_H * CIN];
__device__ __half g_xp2a[BATCH * XP_H * XP_H * CI];
__device__ __half g_xp2b[BATCH * XP_H * XP_H * CI];
__device__ __half g_wf16_1[2 * 144 * 4096];  // conv1 weights, fragment-packed
__device__ __half g_wf16_2[2 * 36 * 4096];   // conv2 weights
__device__ __half g_wqkv[10 * 8 * 32 * 8];   // [Wd;Wb;Wc] fragment-packed

__device__ __forceinline__ float sigmoidf_(float x) {
    return 1.0f / (1.0f + __expf(-x));
}
__device__ __forceinline__ uint32_t smem_u32(const void* p) {
    uint32_t a;
    asm("{ .reg .u64 t; cvta.to.shared.u64 t, %1; cvt.u32.u64 %0, t; }" : "=r"(a) : "l"(p));
    return a;
}
__device__ __forceinline__ void mma_f16(float c[4], const uint32_t a[4], const uint32_t b0, const uint32_t b1) {
    asm volatile(
        "mma.sync.aligned.m16n8k16.row.col.f32.f16.f16.f32 "
        "{%0,%1,%2,%3}, {%4,%5,%6,%7}, {%8,%9}, {%0,%1,%2,%3};"
        : "+f"(c[0]), "+f"(c[1]), "+f"(c[2]), "+f"(c[3])
        : "r"(a[0]), "r"(a[1]), "r"(a[2]), "r"(a[3]), "r"(b0), "r"(b1));
}
__device__ __forceinline__ void ldsm4(uint32_t r[4], uint32_t addr) {
    asm volatile("ldmatrix.sync.aligned.m8n8.x4.shared.b16 {%0,%1,%2,%3}, [%4];"
                 : "=r"(r[0]), "=r"(r[1]), "=r"(r[2]), "=r"(r[3]) : "r"(addr));
}
__device__ __forceinline__ void ldsm4t(uint32_t r[4], uint32_t addr) {
    asm volatile("ldmatrix.sync.aligned.m8n8.x4.trans.shared.b16 {%0,%1,%2,%3}, [%4];"
                 : "=r"(r[0]), "=r"(r[1]), "=r"(r[2]), "=r"(r[3]) : "r"(addr));
}
#define CP_ASYNC16(dst, src) \
    asm volatile("cp.async.ca.shared.global [%0], [%1], 16;" :: "r"(dst), "l"(src))
#define CP_COMMIT() asm volatile("cp.async.commit_group;")
#define CP_WAIT(N)  asm volatile("cp.async.wait_group %0;" :: "n"(N))

// Fast e^x (x <= 0), FMA pipe only.
__device__ __forceinline__ float fexp(float x) {
    float t = fmaxf(x * 1.4426950408889634f, -126.0f);
    float y = t + 12582912.0f;
    int   k = __float_as_int(y);
    float r = t - (y - 12582912.0f);
    float p = 1.3333558e-3f;
    p = fmaf(p, r, 9.6181291e-3f);
    p = fmaf(p, r, 5.5504109e-2f);
    p = fmaf(p, r, 2.4022651e-1f);
    p = fmaf(p, r, 6.9314718e-1f);
    p = fmaf(p, r, 1.0f);
    return __int_as_float((k + (127 - 0x4B400000)) << 23) * p;
}
__device__ __forceinline__ uint32_t ph2(float x, float y) {
    __half2 h = __floats2half2_rn(x, y);
    return *(uint32_t*)&h;
}

// ---------------------------------------------------------------------------
// Pack x: f32 NCHW -> fp16 NHWC padded [8,66,66,512]
// ---------------------------------------------------------------------------
__global__ void pack_x_kernel(const float* __restrict__ x, __half* __restrict__ xp) {
    const int h = blockIdx.x, b = blockIdx.y, tid = threadIdx.x;
    __shared__ float s[32][65];
    for (int ci0 = 0; ci0 < CIN; ci0 += 32) {
        for (int idx = tid; idx < 32 * 64; idx += 256) {
            int ci_l = idx >> 6, w = idx & 63;
            s[ci_l][w] = x[(((size_t)b * CIN + ci0 + ci_l) * 64 + h) * 64 + w];
        }
        __syncthreads();
        for (int idx = tid; idx < 64 * 32; idx += 256) {
            int w = idx >> 5, ci_l = idx & 31;
            xp[(((size_t)b * XP_H + h + 1) * XP_H + w + 1) * CIN + ci0 + ci_l] =
                __float2half(s[ci_l][w]);
        }
        __syncthreads();
    }
}

__global__ void zero_border_h(__half* __restrict__ xp, int C) {
    const int hp = blockIdx.x, b = blockIdx.y, tid = threadIdx.x;
    __half* row = xp + ((size_t)b * XP_H + hp) * XP_H * C;
    const __half z = __float2half(0.0f);
    if (hp == 0 || hp == XP_H - 1) {
        for (int idx = tid; idx < XP_H * C; idx += 256) row[idx] = z;
    } else {
        for (int idx = tid; idx < C; idx += 256) {
            row[idx] = z;
            row[(size_t)(XP_H - 1) * C + idx] = z;
        }
    }
}

// ---------------------------------------------------------------------------
// Pack conv weights into m16n8k16 fp16 A-fragment order.
// Chunk (kwh, cb of 32ci) -> [mt8][ks2][lane32][8 halves] = 4096 halves.
// ---------------------------------------------------------------------------
__global__ void pack_w16(const float* __restrict__ W0, const float* __restrict__ W1,
                         __half* __restrict__ wf, int CIN_T) {
    const int cpc = CIN_T / 32;
    const int chunk = blockIdx.x;
    const int kwh = chunk / cpc, cb = chunk % cpc;
    const float* W = blockIdx.y ? W1 : W0;
    __half* dst = wf + ((size_t)blockIdx.y * gridDim.x + chunk) * 4096;
    for (int t = 0; t < 16; t++) {
        int idx = threadIdx.x + t * 256;
        int j = idx & 7, lane = (idx >> 3) & 31, ks = (idx >> 8) & 1, mt = idx >> 9;
        int reg = j >> 1, h = j & 1;
        int co = mt * 16 + (lane >> 2) + (reg & 1) * 8;
        int ci = cb * 32 + ks * 16 + (lane & 3) * 2 + (reg >> 1) * 8 + h;
        dst[idx] = __float2half(W[((size_t)co * CIN_T + ci) * 9 + kwh]);
    }
}

// Pack [Wd(128); Wb(16); Wc(16)] -> fragment order [mt10][ks8][lane32][8h]
__global__ void pack_wqkv(const float* __restrict__ Wd, const float* __restrict__ Wb,
                          const float* __restrict__ Wc, __half* __restrict__ dst) {
    for (int idx = threadIdx.x; idx < 20480; idx += 256) {
        int j = idx & 7, lane = (idx >> 3) & 31, ks = (idx >> 8) & 7, mt = idx >> 11;
        int reg = j >> 1, h = j & 1;
        int row = mt * 16 + (lane >> 2) + (reg & 1) * 8;
        int col = ks * 16 + (lane & 3) * 2 + (reg >> 1) * 8 + h;
        float w;
        if (row < 128)      w = Wd[row * 128 + col];
        else if (row < 144) w = Wb[(row - 128) * 128 + col];
        else                w = Wc[(row - 144) * 128 + col];
        dst[idx] = __float2half(w);
    }
}

// ---------------------------------------------------------------------------
// conv3x3 implicit GEMM, fp16 m16n8k16, fused BN+ReLU (+ optional fp16 copy).
// CTA: M=128 co x N=128 px; 8 warps 2(M)x4(N) of 64x32.
// smem: A 2x8192 @0; B 2x10240 @16384.  Total 36864.
// ---------------------------------------------------------------------------
#define CONV_SMEM 36864

template<int CIN_T>
__global__ void __launch_bounds__(256, 2) conv_mma_kernel(
        const __half* __restrict__ xpA, const __half* __restrict__ xpB,
        const __half* __restrict__ wfrag,
        const float* __restrict__ bn0, const float* __restrict__ bn1,
        float* __restrict__ out0, float* __restrict__ out1,
        __half* __restrict__ o16_0, __half* __restrict__ o16_1) {
    constexpr int CPC = CIN_T / 32;
    constexpr int NCHUNK = 9 * CPC;
    extern __shared__ __align__(16) char smc[];
    const uint32_t smb = smem_u32(smc);

    const int tid = threadIdx.x, lane = tid & 31, wid = tid >> 5;
    const int warp_m = wid >> 2, warp_n = wid & 3;
    const int b = blockIdx.y, z = blockIdx.z;
    const int pxbase = blockIdx.x * 128;
    const int h0 = pxbase >> 6;
    const __half* xp = z ? xpB : xpA;
    const __half* Wf = wfrag + (size_t)z * NCHUNK * 4096;
    const float* bn = z ? bn1 : bn0;
    float* out = z ? out1 : out0;
    __half* o16 = z ? o16_1 : o16_0;

    const int g = lane >> 3;

    float acc[4][4][4];
#pragma unroll
    for (int mt = 0; mt < 4; mt++)
#pragma unroll
        for (int nt = 0; nt < 4; nt++)
#pragma unroll
            for (int r = 0; r < 4; r++) acc[mt][nt][r] = 0.0f;

    auto stage = [&](int i, int buf) {
        const int kwh = i / CPC, cb = i % CPC;
        const int kh = kwh / 3, kw = kwh % 3;
        const __half* Asrc = Wf + (size_t)i * 4096;
        const uint32_t Adst = smb + buf * 8192;
#pragma unroll
        for (int t = 0; t < 2; t++) {
            int i16 = tid + t * 256;
            CP_ASYNC16(Adst + i16 * 16, Asrc + i16 * 8);
        }
        const uint32_t Bdst = smb + 16384 + buf * 10240;
#pragma unroll
        for (int t = 0; t < 2; t++) {
            int idx = tid + t * 256;
            int px = idx >> 2, q = idx & 3;
            const __half* src = xp + (((size_t)b * XP_H + h0 + (px >> 6) + kh) * XP_H
                                      + (px & 63) + kw) * CIN_T + cb * 32 + q * 8;
            CP_ASYNC16(Bdst + px * 80 + q * 16, src);
        }
        CP_COMMIT();
    };

    stage(0, 0);
    for (int i = 0; i < NCHUNK; i++) {
        const int buf = i & 1;
        if (i + 1 < NCHUNK) {
            stage(i + 1, buf ^ 1);
            CP_WAIT(1);
        } else {
            CP_WAIT(0);
        }
        __syncthreads();

        const uint32_t Asm = smb + buf * 8192;
        const uint32_t Bsm = smb + 16384 + buf * 10240;
        const char* Aptr = smc + buf * 8192;
#pragma unroll
        for (int ks = 0; ks < 2; ks++) {
            uint32_t afr[4][4];
#pragma unroll
            for (int mt = 0; mt < 4; mt++) {
                uint4 v = *(const uint4*)(Aptr + ((((warp_m * 4 + mt) * 2 + ks) * 32 + lane) << 4));
                afr[mt][0] = v.x; afr[mt][1] = v.y; afr[mt][2] = v.z; afr[mt][3] = v.w;
            }
            uint32_t bfr[2][4];
#pragma unroll
            for (int t16 = 0; t16 < 2; t16++) {
                const int n_row = warp_n * 32 + t16 * 16 + (g >> 1) * 8 + (lane & 7);
                ldsm4(bfr[t16], Bsm + n_row * 80 + ks * 32 + (g & 1) * 16);
            }
#pragma unroll
            for (int mt = 0; mt < 4; mt++)
#pragma unroll
                for (int t16 = 0; t16 < 2; t16++) {
                    mma_f16(acc[mt][2 * t16],     afr[mt], bfr[t16][0], bfr[t16][1]);
                    mma_f16(acc[mt][2 * t16 + 1], afr[mt], bfr[t16][2], bfr[t16][3]);
                }
        }
        __syncthreads();
    }

#pragma unroll
    for (int mt = 0; mt < 4; mt++) {
        const int co = warp_m * 64 + mt * 16 + (lane >> 2);
        const float sc0 = bn[co],     sh0 = bn[128 + co];
        const float sc8 = bn[co + 8], sh8 = bn[136 + co];
        float* o0 = out + ((size_t)b * 128 + co) * NPIX;
        float* o8 = o0 + 8 * NPIX;
#pragma unroll
        for (int nt = 0; nt < 4; nt++) {
            const int px = pxbase + warp_n * 32 + nt * 8 + 2 * (lane & 3);
            float2 v0, v1;
            v0.x = fmaxf(acc[mt][nt][0] * sc0 + sh0, 0.0f);
            v0.y = fmaxf(acc[mt][nt][1] * sc0 + sh0, 0.0f);
            v1.x = fmaxf(acc[mt][nt][2] * sc8 + sh8, 0.0f);
            v1.y = fmaxf(acc[mt][nt][3] * sc8 + sh8, 0.0f);
            *(float2*)(o0 + px) = v0;
            *(float2*)(o8 + px) = v1;
            if (o16) {
                uint32_t h0v = ph2(v0.x, v0.y), h8v = ph2(v1.x, v1.y);
                *(uint32_t*)(o16 + ((size_t)b * 128 + co) * NPIX + px) = h0v;
                *(uint32_t*)(o16 + ((size_t)b * 128 + co + 8) * NPIX + px) = h8v;
            }
        }
    }
}

// ---------------------------------------------------------------------------
// QKV GEMM: [Wd;Wb;Wc](160x128) @ y16(128x4096) + bias.
// grid (64 n-tiles of 64, 8 b), block 320 (10 warps, one m16 tile each).
// smem: A 40960 @0 (fragment-packed weights); B y-tile [128k][72h] @40960.
// ---------------------------------------------------------------------------
#define QKV_SMEM 59392

__global__ void __launch_bounds__(320, 1) qkv_kernel(
        const __half* __restrict__ wq, const __half* __restrict__ y16,
        const float* __restrict__ bd, const float* __restrict__ bb,
        const float* __restrict__ bc,
        __half* __restrict__ vh, __half* __restrict__ qh, __half* __restrict__ kh) {
    extern __shared__ __align__(16) char smc[];
    const uint32_t smb = smem_u32(smc);
    const int tid = threadIdx.x, lane = tid & 31, wid = tid >> 5;
    const int b = blockIdx.y;
    const int n0 = blockIdx.x * 64;
    const int g = lane >> 3;

#pragma unroll
    for (int t = 0; t < 8; t++) {
        int i = tid + t * 320;
        CP_ASYNC16(smb + i * 16, wq + i * 8);
    }
    for (int idx = tid; idx < 1024; idx += 320) {
        int ch = idx >> 3, seg = idx & 7;
        CP_ASYNC16(smb + 40960 + ch * 144 + seg * 16,
                   y16 + ((size_t)b * 128 + ch) * NPIX + n0 + seg * 8);
    }
    CP_COMMIT();
    CP_WAIT(0);
    __syncthreads();

    const int mt = wid;
    float acc[8][4];
#pragma unroll
    for (int nt = 0; nt < 8; nt++)
#pragma unroll
        for (int r = 0; r < 4; r++) acc[nt][r] = 0.0f;

    const char* Aptr = smc;
    const uint32_t Bsm = smb + 40960;
#pragma unroll
    for (int ks = 0; ks < 8; ks++) {
        uint4 v = *(const uint4*)(Aptr + (((mt * 8 + ks) * 32 + lane) << 4));
        uint32_t afr[4] = {v.x, v.y, v.z, v.w};
#pragma unroll
        for (int t16 = 0; t16 < 4; t16++) {
            uint32_t bfr[4];
            ldsm4t(bfr, Bsm + (ks * 16 + (g & 1) * 8 + (lane & 7)) * 144
                       + (t16 * 16 + (g >> 1) * 8) * 2);
            mma_f16(acc[2 * t16],     afr, bfr[0], bfr[1]);
            mma_f16(acc[2 * t16 + 1], afr, bfr[2], bfr[3]);
        }
    }

    const int r0 = mt * 16 + (lane >> 2);
    if (mt < 8) {
        const float b0 = bd[r0], b8 = bd[r0 + 8];
        __half* v0 = vh + ((size_t)b * 128 + r0) * NPIX;
        __half* v8 = vh + ((size_t)b * 128 + r0 + 8) * NPIX;
#pragma unroll
        for (int nt = 0; nt < 8; nt++) {
            const int n = n0 + nt * 8 + 2 * (lane & 3);
            *(uint32_t*)(v0 + n) = ph2(acc[nt][0] + b0, acc[nt][1] + b0);
            *(uint32_t*)(v8 + n) = ph2(acc[nt][2] + b8, acc[nt][3] + b8);
        }
    } else {
        const bool isq = (mt == 8);
        const float* bias = isq ? bb : bc;
        __half* dst = isq ? qh : kh;
        const int d = lane >> 2;
        const float b0 = bias[d], b8 = bias[d + 8];
#pragma unroll
        for (int nt = 0; nt < 8; nt++) {
            const int n = n0 + nt * 8 + 2 * (lane & 3);
            __half* p0 = dst + ((size_t)b * NPIX + n) * 16;
            p0[d]      = __float2half(acc[nt][0] + b0);
            p0[16 + d] = __float2half(acc[nt][1] + b0);
            p0[d + 8]      = __float2half(acc[nt][2] + b8);
            p0[16 + d + 8] = __float2half(acc[nt][3] + b8);
        }
    }
}

// ---------------------------------------------------------------------------
// PAM flash attention (fp16 MMA, ldmatrix), epilogue -> fp16 padded NHWC.
// ---------------------------------------------------------------------------
#define ATT_SMEM 49152

__global__ void __launch_bounds__(256, 1) pam_attn_mma(
        const __half* __restrict__ qh, const __half* __restrict__ kh,
        const __half* __restrict__ vd, const float* __restrict__ y,
        const float* __restrict__ alpha, __half* __restrict__ xp2) {
    extern __shared__ __align__(16) char smc[];
    const uint32_t smb = smem_u32(smc);
    const uint32_t Qb  = smb;
    const uint32_t Kb0 = smb + 6144;
    const uint32_t Vb0 = smb + 12288;

    const int tid = threadIdx.x, lane = tid & 31, wid = tid >> 5;
    const int b = blockIdx.y;
    const int n0 = blockIdx.x * 128;
    const int qbase = wid * 16;

    const int g = lane >> 3, r8 = lane & 7;
    const uint32_t qoff = (uint32_t)(((g & 1) * 8 + r8) * 48 + (g >> 1) * 16);
    const uint32_t koff = (uint32_t)(((g >> 1) * 8 + r8) * 48 + (g & 1) * 16);
    const uint32_t voff = (uint32_t)(((g >> 1) * 8 + r8) * 144 + (g & 1) * 16);

    auto stageKV = [&](int t, int buf) {
        const int k0 = t * 64;
        if (tid < 128) {
            int row = tid >> 1, h = tid & 1;
            CP_ASYNC16(Kb0 + buf * 3072 + row * 48 + h * 16,
                       kh + ((size_t)b * NPIX + k0 + row) * 16 + h * 8);
        }
#pragma unroll
        for (int t4 = 0; t4 < 4; t4++) {
            int idx = tid + t4 * 256;
            int ch = idx >> 3, c = idx & 7;
            CP_ASYNC16(Vb0 + buf * 18432 + ch * 144 + c * 16,
                       vd + ((size_t)b * 128 + ch) * NPIX + k0 + c * 8);
        }
        CP_COMMIT();
    };

    {
        int row = tid >> 1, h = tid & 1;
        CP_ASYNC16(Qb + row * 48 + h * 16,
                   qh + ((size_t)b * NPIX + n0 + row) * 16 + h * 8);
    }
    stageKV(0, 0);

    uint32_t qfr[4];
    float O[16][4];
#pragma unroll
    for (int nc = 0; nc < 16; nc++)
#pragma unroll
        for (int r = 0; r < 4; r++) O[nc][r] = 0.0f;
    float mrun0 = -1e30f, mrun1 = -1e30f, lrun0 = 0.0f, lrun1 = 0.0f;

    for (int t = 0; t < 64; t++) {
        const int buf = t & 1;
        CP_WAIT(0);
        __syncthreads();
        if (t + 1 < 64) stageKV(t + 1, buf ^ 1);
        if (t == 0) ldsm4(qfr, Qb + qbase * 48 + qoff);

        const uint32_t Kb = Kb0 + buf * 3072;
        const uint32_t Vb = Vb0 + buf * 18432;

        float S[8][4];
#pragma unroll
        for (int ks = 0; ks < 4; ks++) {
            uint32_t kb[4];
            ldsm4(kb, Kb + ks * 768 + koff);
#pragma unroll
            for (int r = 0; r < 4; r++) { S[2 * ks][r] = 0.0f; S[2 * ks + 1][r] = 0.0f; }
            mma_f16(S[2 * ks],     qfr, kb[0], kb[1]);
            mma_f16(S[2 * ks + 1], qfr, kb[2], kb[3]);
        }

        float tm0 = -1e30f, tm1 = -1e30f;
#pragma unroll
        for (int nt = 0; nt < 8; nt++) {
            tm0 = fmaxf(tm0, fmaxf(S[nt][0], S[nt][1]));
            tm1 = fmaxf(tm1, fmaxf(S[nt][2], S[nt][3]));
        }
        tm0 = fmaxf(tm0, __shfl_xor_sync(0xffffffffu, tm0, 1));
        tm0 = fmaxf(tm0, __shfl_xor_sync(0xffffffffu, tm0, 2));
        tm1 = fmaxf(tm1, __shfl_xor_sync(0xffffffffu, tm1, 1));
        tm1 = fmaxf(tm1, __shfl_xor_sync(0xffffffffu, tm1, 2));
        const float mn0 = fmaxf(mrun0, tm0), mn1 = fmaxf(mrun1, tm1);
        const float f0 = fexp(mrun0 - mn0), f1 = fexp(mrun1 - mn1);
        mrun0 = mn0; mrun1 = mn1;

        float ts0 = 0.0f, ts1 = 0.0f;
        uint32_t afr[4][4];
#pragma unroll
        for (int j = 0; j < 4; j++) {
            float p00 = fexp(S[2 * j][0] - mn0), p01 = fexp(S[2 * j][1] - mn0);
            float p10 = fexp(S[2 * j][2] - mn1), p11 = fexp(S[2 * j][3] - mn1);
            float q00 = fexp(S[2 * j + 1][0] - mn0), q01 = fexp(S[2 * j + 1][1] - mn0);
            float q10 = fexp(S[2 * j + 1][2] - mn1), q11 = fexp(S[2 * j + 1][3] - mn1);
            ts0 += (p00 + p01) + (q00 + q01);
            ts1 += (p10 + p11) + (q10 + q11);
            afr[j][0] = ph2(p00, p01);
            afr[j][1] = ph2(p10, p11);
            afr[j][2] = ph2(q00, q01);
            afr[j][3] = ph2(q10, q11);
        }
        ts0 += __shfl_xor_sync(0xffffffffu, ts0, 1);
        ts0 += __shfl_xor_sync(0xffffffffu, ts0, 2);
        ts1 += __shfl_xor_sync(0xffffffffu, ts1, 1);
        ts1 += __shfl_xor_sync(0xffffffffu, ts1, 2);
        lrun0 = lrun0 * f0 + ts0;
        lrun1 = lrun1 * f1 + ts1;

#pragma unroll
        for (int nc = 0; nc < 16; nc++) {
            O[nc][0] *= f0; O[nc][1] *= f0;
            O[nc][2] *= f1; O[nc][3] *= f1;
        }

#pragma unroll
        for (int j = 0; j < 4; j++) {
            const uint32_t vb_j = Vb + j * 32 + voff;
#pragma unroll
            for (int p = 0; p < 8; p++) {
                uint32_t vb[4];
                ldsm4(vb, vb_j + p * 2304);
                mma_f16(O[2 * p],     afr[j], vb[0], vb[1]);
                mma_f16(O[2 * p + 1], afr[j], vb[2], vb[3]);
            }
        }
    }

    const float linv0 = 1.0f / lrun0, linv1 = 1.0f / lrun1;
    const float a = alpha[0];
    const int px0 = n0 + qbase + (lane >> 2);
    const int px1 = px0 + 8;
    __half* dst0 = xp2 + (((size_t)b * XP_H + (px0 >> 6) + 1) * XP_H + (px0 & 63) + 1) * CI;
    __half* dst1 = xp2 + (((size_t)b * XP_H + (px1 >> 6) + 1) * XP_H + (px1 & 63) + 1) * CI;
#pragma unroll
    for (int nc = 0; nc < 16; nc++) {
        const int ch = nc * 8 + 2 * (lane & 3);
        const float* y0 = y + ((size_t)b * 128 + ch) * NPIX;
        *(uint32_t*)(dst0 + ch) = ph2(fmaf(a, O[nc][0] * linv0, y0[px0]),
                                      fmaf(a, O[nc][1] * linv0, y0[NPIX + px0]));
        *(uint32_t*)(dst1 + ch) = ph2(fmaf(a, O[nc][2] * linv1, y0[px1]),
                                      fmaf(a, O[nc][3] * linv1, y0[NPIX + px1]));
    }
}

// ---------------------------------------------------------------------------
// CAM gram matrix (f32 SIMT on purpose: energies feed exp, need f32 accuracy)
// ---------------------------------------------------------------------------
__global__ void cam_energy_kernel(const float* __restrict__ y,
                                  float* __restrict__ energy) {
    const int b  = blockIdx.y;
    const int tc = (blockIdx.x / 8) * 16;
    const int td = (blockIdx.x % 8) * 16;
    const int tid = threadIdx.x;
    const int li = tid / 16, lj = tid % 16;

    __shared__ float As[16][65];
    __shared__ float Bs[16][65];

    const float* yb = y + (size_t)b * 128 * NPIX;
    float acc = 0.0f;
    for (int n0 = 0; n0 < NPIX; n0 += 64) {
        for (int i = tid; i < 1024; i += 256) {
            int r = i >> 6, c = i & 63;
            As[r][c] = yb[(size_t)(tc + r) * NPIX + n0 + c];
            Bs[r][c] = yb[(size_t)(td + r) * NPIX + n0 + c];
        }
        __syncthreads();
#pragma unroll 16
        for (int k = 0; k < 64; k++) acc += As[li][k] * Bs[lj][k];
        __syncthreads();
    }
    energy[((size_t)b * 128 + tc + li) * 128 + td + lj] = acc;
}

// ---------------------------------------------------------------------------
// CAM softmax of (rowmax - E) -> fp16 attn
// ---------------------------------------------------------------------------
__global__ void cam_softmax_kernel(const float* __restrict__ energy,
                                   __half* __restrict__ attn) {
    const int row = blockIdx.x;
    const int tid = threadIdx.x;
    __shared__ float red[4];

    float e = energy[(size_t)row * 128 + tid];

    float m = e;
#pragma unroll
    for (int off = 16; off; off >>= 1) m = fmaxf(m, __shfl_xor_sync(0xffffffff, m, off));
    if ((tid & 31) == 0) red[tid >> 5] = m;
    __syncthreads();
    float mx = fmaxf(fmaxf(red[0], red[1]), fmaxf(red[2], red[3]));
    float e2 = mx - e;
    __syncthreads();

    float m2 = e2;
#pragma unroll
    for (int off = 16; off; off >>= 1) m2 = fmaxf(m2, __shfl_xor_sync(0xffffffff, m2, off));
    if ((tid & 31) == 0) red[tid >> 5] = m2;
    __syncthreads();
    m2 = fmaxf(fmaxf(red[0], red[1]), fmaxf(red[2], red[3]));
    float p = __expf(e2 - m2);
    __syncthreads();

    float s = p;
#pragma unroll
    for (int off = 16; off; off >>= 1) s += __shfl_xor_sync(0xffffffff, s, off);
    if ((tid & 31) == 0) red[tid >> 5] = s;
    __syncthreads();
    s = red[0] + red[1] + red[2] + red[3];

    attn[(size_t)row * 128 + tid] = __float2half(p / s);
}

// ---------------------------------------------------------------------------
// CAM feature via fp16 MMA: feat = attn16 @ y16; out = beta*feat + y -> xp2b.
// grid (64 n-tiles of 64, 8 b), block 256 (8 warps, m16 each).
// smem: attn [128][136h] @0 (34816); y tile [128k][72h] @34816 (18432).
// ---------------------------------------------------------------------------
#define CAMF_SMEM 53248

__global__ void __launch_bounds__(256, 1) cam_feat_mma(
        const __half* __restrict__ attn16, const __half* __restrict__ y16,
        const float* __restrict__ yf, const float* __restrict__ beta,
        __half* __restrict__ xp2) {
    extern __shared__ __align__(16) char smc[];
    const uint32_t smb = smem_u32(smc);
    const int tid = threadIdx.x, lane = tid & 31, wid = tid >> 5;
    const int b = blockIdx.y;
    const int n0 = blockIdx.x * 64;
    const int g = lane >> 3;

#pragma unroll
    for (int t = 0; t < 8; t++) {
        int idx = tid + t * 256;
        int c = idx >> 4, seg = idx & 15;
        CP_ASYNC16(smb + c * 272 + seg * 16,
                   attn16 + ((size_t)b * 128 + c) * 128 + seg * 8);
    }
#pragma unroll
    for (int t = 0; t < 4; t++) {
        int idx = tid + t * 256;
        int ch = idx >> 3, seg = idx & 7;
        CP_ASYNC16(smb + 34816 + ch * 144 + seg * 16,
                   y16 + ((size_t)b * 128 + ch) * NPIX + n0 + seg * 8);
    }
    CP_COMMIT();
    CP_WAIT(0);
    __syncthreads();

    const int mt = wid;
    float acc[8][4];
#pragma unroll
    for (int nt = 0; nt < 8; nt++)
#pragma unroll
        for (int r = 0; r < 4; r++) acc[nt][r] = 0.0f;

    const uint32_t Bsm = smb + 34816;
#pragma unroll
    for (int ks = 0; ks < 8; ks++) {
        uint32_t afr[4];
        ldsm4(afr, smb + (mt * 16 + (g & 1) * 8 + (lane & 7)) * 272
                  + ks * 32 + (g >> 1) * 16);
#pragma unroll
        for (int t16 = 0; t16 < 4; t16++) {
            uint32_t bfr[4];
            ldsm4t(bfr, Bsm + (ks * 16 + (g & 1) * 8 + (lane & 7)) * 144
                       + (t16 * 16 + (g >> 1) * 8) * 2);
            mma_f16(acc[2 * t16],     afr, bfr[0], bfr[1]);
            mma_f16(acc[2 * t16 + 1], afr, bfr[2], bfr[3]);
        }
    }

    const float bet = beta[0];
    const int c0 = mt * 16 + (lane >> 2);
#pragma unroll
    for (int nt = 0; nt < 8; nt++) {
        const int n = n0 + nt * 8 + 2 * (lane & 3);
        const float* y0 = yf + ((size_t)b * 128 + c0) * NPIX;
        const float* y8 = y0 + 8 * NPIX;
        __half* p0 = xp2 + (((size_t)b * XP_H + (n >> 6) + 1) * XP_H + (n & 63) + 1) * CI;
        __half* p1 = p0 + CI;   // n+1 is the next pixel in the same row
        p0[c0]     = __float2half(fmaf(bet, acc[nt][0], y0[n]));
        p1[c0]     = __float2half(fmaf(bet, acc[nt][1], y0[n + 1]));
        p0[c0 + 8] = __float2half(fmaf(bet, acc[nt][2], y8[n]));
        p1[c0 + 8] = __float2half(fmaf(bet, acc[nt][3], y8[n + 1]));
    }
}

// ---------------------------------------------------------------------------
// Final heads: three 1x1 convs (128->19) + sigmoid, fused.
// ---------------------------------------------------------------------------
__global__ void final_kernel(const float* __restrict__ fp,
                             const float* __restrict__ fc,
                             const float* __restrict__ Wout, const float* __restrict__ bout,
                             const float* __restrict__ Wp3, const float* __restrict__ bp3,
                             const float* __restrict__ Wc3, const float* __restrict__ bc3,
                             float* __restrict__ out) {
    const int b  = blockIdx.y;
    const int px = blockIdx.x * 256 + threadIdx.x;

    __shared__ float Wo[19][128];
    __shared__ float Wp[19][128];
    __shared__ float Wc[19][128];
    for (int i = threadIdx.x; i < 19 * 128; i += 256) {
        Wo[i / 128][i % 128] = Wout[i];
        Wp[i / 128][i % 128] = Wp3[i];
        Wc[i / 128][i % 128] = Wc3[i];
    }
    __syncthreads();

    float am[19], ap[19], ac[19];
#pragma unroll
    for (int o = 0; o < 19; o++) { am[o] = bout[o]; ap[o] = bp3[o]; ac[o] = bc3[o]; }

    for (int c = 0; c < 128; c++) {
        float vp = fp[((size_t)b * 128 + c) * NPIX + px];
        float vc = fc[((size_t)b * 128 + c) * NPIX + px];
        float vf = vp + vc;
#pragma unroll
        for (int o = 0; o < 19; o++) {
            am[o] += Wo[o][c] * vf;
            ap[o] += Wp[o][c] * vp;
            ac[o] += Wc[o][c] * vc;
        }
    }

    const size_t SEG = (size_t)BATCH * NC * NPIX;
#pragma unroll
    for (int o = 0; o < 19; o++) {
        size_t base = ((size_t)b * NC + o) * NPIX + px;
        out[base]           = sigmoidf_(am[o]);
        out[SEG + base]     = sigmoidf_(ap[o]);
        out[2 * SEG + base] = sigmoidf_(ac[o]);
    }
}

// ---------------------------------------------------------------------------
// Launch
// ---------------------------------------------------------------------------
extern "C" void kernel_launch(void* const* d_in, const int* in_sizes, int n_in,
                              void* d_out, int out_size) {
    const float* x    = (const float*)d_in[0];
    const float* Wp1  = (const float*)d_in[1];
    const float* bnp1 = (const float*)d_in[2];
    const float* Wc1  = (const float*)d_in[3];
    const float* bnc1 = (const float*)d_in[4];
    const float* Wb   = (const float*)d_in[5];
    const float* bb   = (const float*)d_in[6];
    const float* Wc   = (const float*)d_in[7];
    const float* bc   = (const float*)d_in[8];
    const float* Wd   = (const float*)d_in[9];
    const float* bd   = (const float*)d_in[10];
    const float* alpha= (const float*)d_in[11];
    const float* beta = (const float*)d_in[12];
    const float* Wp2  = (const float*)d_in[13];
    const float* bnp2 = (const float*)d_in[14];
    const float* Wc2  = (const float*)d_in[15];
    const float* bnc2 = (const float*)d_in[16];
    const float* Wout = (const float*)d_in[17];
    const float* bout = (const float*)d_in[18];
    const float* Wp3  = (const float*)d_in[19];
    const float* bp3  = (const float*)d_in[20];
    const float* Wc3  = (const float*)d_in[21];
    const float* bc3  = (const float*)d_in[22];
    float* out = (float*)d_out;

    float *featp1, *featc1, *featp2, *featc2, *energy;
    __half *featp1h, *featc1h, *qh, *kh, *vd, *attn16;
    __half *xpad, *xp2a, *xp2b, *wf1, *wf2, *wqkv;
    cudaGetSymbolAddress((void**)&featp1,  g_featp1);
    cudaGetSymbolAddress((void**)&featc1,  g_featc1);
    cudaGetSymbolAddress((void**)&featp1h, g_featp1h);
    cudaGetSymbolAddress((void**)&featc1h, g_featc1h);
    cudaGetSymbolAddress((void**)&qh,      g_qh);
    cudaGetSymbolAddress((void**)&kh,      g_kh);
    cudaGetSymbolAddress((void**)&vd,      g_vd);
    cudaGetSymbolAddress((void**)&featp2,  g_featp2);
    cudaGetSymbolAddress((void**)&featc2,  g_featc2);
    cudaGetSymbolAddress((void**)&energy,  g_energy);
    cudaGetSymbolAddress((void**)&attn16,  g_attn16);
    cudaGetSymbolAddress((void**)&xpad,    g_xpad);
    cudaGetSymbolAddress((void**)&xp2a,    g_xp2a);
    cudaGetSymbolAddress((void**)&xp2b,    g_xp2b);
    cudaGetSymbolAddress((void**)&wf1,     g_wf16_1);
    cudaGetSymbolAddress((void**)&wf2,     g_wf16_2);
    cudaGetSymbolAddress((void**)&wqkv,    g_wqkv);

    cudaFuncSetAttribute(conv_mma_kernel<512>,
                         cudaFuncAttributeMaxDynamicSharedMemorySize, CONV_SMEM);
    cudaFuncSetAttribute(conv_mma_kernel<128>,
                         cudaFuncAttributeMaxDynamicSharedMemorySize, CONV_SMEM);
    cudaFuncSetAttribute(pam_attn_mma,
                         cudaFuncAttributeMaxDynamicSharedMemorySize, ATT_SMEM);
    cudaFuncSetAttribute(qkv_kernel,
                         cudaFuncAttributeMaxDynamicSharedMemorySize, QKV_SMEM);
    cudaFuncSetAttribute(cam_feat_mma,
                         cudaFuncAttributeMaxDynamicSharedMemorySize, CAMF_SMEM);

    // Packing
    pack_x_kernel<<<dim3(64, BATCH), 256>>>(x, xpad);
    zero_border_h<<<dim3(XP_H, BATCH), 256>>>(xpad, CIN);
    zero_border_h<<<dim3(XP_H, BATCH), 256>>>(xp2a, CI);
    zero_border_h<<<dim3(XP_H, BATCH), 256>>>(xp2b, CI);
    pack_w16<<<dim3(144, 2), 256>>>(Wp1, Wc1, wf1, CIN);
    pack_w16<<<dim3(36, 2), 256>>>(Wp2, Wc2, wf2, CI);
    pack_wqkv<<<1, 256>>>(Wd, Wb, Wc, wqkv);

    // conv1: both 512->128 convs (f32 + fp16 outputs)
    conv_mma_kernel<512><<<dim3(32, BATCH, 2), 256, CONV_SMEM>>>(
        xpad, xpad, wf1, bnp1, bnc1, featp1, featc1, featp1h, featc1h);

    // PAM: fused QKV GEMM, then flash attention
    qkv_kernel<<<dim3(64, BATCH), 320, QKV_SMEM>>>(
        wqkv, featp1h, bd, bb, bc, vd, qh, kh);
    pam_attn_mma<<<dim3(32, BATCH), 256, ATT_SMEM>>>(qh, kh, vd, featp1, alpha, xp2a);

    // CAM
    cam_energy_kernel<<<dim3(64, BATCH), 256>>>(featc1, energy);
    cam_softmax_kernel<<<BATCH * 128, 128>>>(energy, attn16);
    cam_feat_mma<<<dim3(64, BATCH), 256, CAMF_SMEM>>>(
        attn16, featc1h, featc1, beta, xp2b);

    // conv2: both 128->128 convs (fp16 in, f32 out)
    conv_mma_kernel<128><<<dim3(32, BATCH, 2), 256, CONV_SMEM>>>(
        xp2a, xp2b, wf2, bnp2, bnc2, featp2, featc2, nullptr, nullptr);

    // Heads
    final_kernel<<<dim3(16, BATCH), 256>>>(featp2, featc2,
                                           Wout, bout, Wp3, bp3, Wc3, bc3, out);
}

// round 7
// speedup vs baseline: 9.6880x; 1.2256x over previous
#include <cuda_runtime.h>
#include <cuda_bf16.h>
#include <cuda_fp16.h>
#include <math.h>
#include <cstdint>

// ---------------------------------------------------------------------------
// Problem constants
// ---------------------------------------------------------------------------
#define BATCH 8
#define CIN   512
#define CI    128
#define CK    16
#define NC    19
#define NPIX  4096
#define FEAT_ELEMS (BATCH * CI * NPIX)
#define XP_H 66
#define KSPLIT 16

// ---------------------------------------------------------------------------
// Scratch (device globals)
// ---------------------------------------------------------------------------
__device__ float  g_featp1[FEAT_ELEMS];
__device__ float  g_featc1[FEAT_ELEMS];
__device__ __half g_featp1h[FEAT_ELEMS];     // conv1-p fp16; later conv2-p fp16
__device__ __half g_featc1h[FEAT_ELEMS];     // conv1-c fp16 (hi); later conv2-c fp16
__device__ __half g_featc1lo[FEAT_ELEMS];    // conv1-c fp16 residual (lo)
__device__ __half g_qh[BATCH * NPIX * CK];
__device__ __half g_kh[BATCH * NPIX * CK];
__device__ __half g_vd[FEAT_ELEMS];
__device__ float  g_epart[KSPLIT * BATCH * CI * CI];   // energy partials
__device__ __half g_attn16[BATCH * CI * CI];
__device__ __half g_xpad[BATCH * XP_H * XP_H * CIN];
__device__ __half g_xp2a[BATCH * XP_H * XP_H * CI];
__device__ __half g_xp2b[BATCH * XP_H * XP_H * CI];
__device__ __half g_wf16_1[2 * 144 * 4096];
__device__ __half g_wf16_2[2 * 36 * 4096];
__device__ __half g_wqkv[10 * 8 * 32 * 8];

__device__ __forceinline__ float sigmoidf_(float x) {
    return 1.0f / (1.0f + __expf(-x));
}
__device__ __forceinline__ uint32_t smem_u32(const void* p) {
    uint32_t a;
    asm("{ .reg .u64 t; cvta.to.shared.u64 t, %1; cvt.u32.u64 %0, t; }" : "=r"(a) : "l"(p));
    return a;
}
__device__ __forceinline__ void mma_f16(float c[4], const uint32_t a[4], const uint32_t b0, const uint32_t b1) {
    asm volatile(
        "mma.sync.aligned.m16n8k16.row.col.f32.f16.f16.f32 "
        "{%0,%1,%2,%3}, {%4,%5,%6,%7}, {%8,%9}, {%0,%1,%2,%3};"
        : "+f"(c[0]), "+f"(c[1]), "+f"(c[2]), "+f"(c[3])
        : "r"(a[0]), "r"(a[1]), "r"(a[2]), "r"(a[3]), "r"(b0), "r"(b1));
}
__device__ __forceinline__ void ldsm4(uint32_t r[4], uint32_t addr) {
    asm volatile("ldmatrix.sync.aligned.m8n8.x4.shared.b16 {%0,%1,%2,%3}, [%4];"
                 : "=r"(r[0]), "=r"(r[1]), "=r"(r[2]), "=r"(r[3]) : "r"(addr));
}
__device__ __forceinline__ void ldsm4t(uint32_t r[4], uint32_t addr) {
    asm volatile("ldmatrix.sync.aligned.m8n8.x4.trans.shared.b16 {%0,%1,%2,%3}, [%4];"
                 : "=r"(r[0]), "=r"(r[1]), "=r"(r[2]), "=r"(r[3]) : "r"(addr));
}
#define CP_ASYNC16(dst, src) \
    asm volatile("cp.async.ca.shared.global [%0], [%1], 16;" :: "r"(dst), "l"(src))
#define CP_COMMIT() asm volatile("cp.async.commit_group;")
#define CP_WAIT(N)  asm volatile("cp.async.wait_group %0;" :: "n"(N))

__device__ __forceinline__ float fexp(float x) {
    float t = fmaxf(x * 1.4426950408889634f, -126.0f);
    float y = t + 12582912.0f;
    int   k = __float_as_int(y);
    float r = t - (y - 12582912.0f);
    float p = 1.3333558e-3f;
    p = fmaf(p, r, 9.6181291e-3f);
    p = fmaf(p, r, 5.5504109e-2f);
    p = fmaf(p, r, 2.4022651e-1f);
    p = fmaf(p, r, 6.9314718e-1f);
    p = fmaf(p, r, 1.0f);
    return __int_as_float((k + (127 - 0x4B400000)) << 23) * p;
}
__device__ __forceinline__ uint32_t ph2(float x, float y) {
    __half2 h = __floats2half2_rn(x, y);
    return *(uint32_t*)&h;
}

// ---------------------------------------------------------------------------
// Pack x: f32 NCHW -> fp16 NHWC padded
// ---------------------------------------------------------------------------
__global__ void pack_x_kernel(const float* __restrict__ x, __half* __restrict__ xp) {
    const int h = blockIdx.x, b = blockIdx.y, tid = threadIdx.x;
    __shared__ float s[32][65];
    for (int ci0 = 0; ci0 < CIN; ci0 += 32) {
        for (int idx = tid; idx < 32 * 64; idx += 256) {
            int ci_l = idx >> 6, w = idx & 63;
            s[ci_l][w] = x[(((size_t)b * CIN + ci0 + ci_l) * 64 + h) * 64 + w];
        }
        __syncthreads();
        for (int idx = tid; idx < 64 * 32; idx += 256) {
            int w = idx >> 5, ci_l = idx & 31;
            xp[(((size_t)b * XP_H + h + 1) * XP_H + w + 1) * CIN + ci0 + ci_l] =
                __float2half(s[ci_l][w]);
        }
        __syncthreads();
    }
}

__global__ void zero_border_h(__half* __restrict__ xp, int C) {
    const int hp = blockIdx.x, b = blockIdx.y, tid = threadIdx.x;
    __half* row = xp + ((size_t)b * XP_H + hp) * XP_H * C;
    const __half z = __float2half(0.0f);
    if (hp == 0 || hp == XP_H - 1) {
        for (int idx = tid; idx < XP_H * C; idx += 256) row[idx] = z;
    } else {
        for (int idx = tid; idx < C; idx += 256) {
            row[idx] = z;
            row[(size_t)(XP_H - 1) * C + idx] = z;
        }
    }
}

// ---------------------------------------------------------------------------
// Pack conv weights into m16n8k16 fp16 A-fragment order.
// ---------------------------------------------------------------------------
__global__ void pack_w16(const float* __restrict__ W0, const float* __restrict__ W1,
                         __half* __restrict__ wf, int CIN_T) {
    const int cpc = CIN_T / 32;
    const int chunk = blockIdx.x;
    const int kwh = chunk / cpc, cb = chunk % cpc;
    const float* W = blockIdx.y ? W1 : W0;
    __half* dst = wf + ((size_t)blockIdx.y * gridDim.x + chunk) * 4096;
    for (int t = 0; t < 16; t++) {
        int idx = threadIdx.x + t * 256;
        int j = idx & 7, lane = (idx >> 3) & 31, ks = (idx >> 8) & 1, mt = idx >> 9;
        int reg = j >> 1, h = j & 1;
        int co = mt * 16 + (lane >> 2) + (reg & 1) * 8;
        int ci = cb * 32 + ks * 16 + (lane & 3) * 2 + (reg >> 1) * 8 + h;
        dst[idx] = __float2half(W[((size_t)co * CIN_T + ci) * 9 + kwh]);
    }
}

__global__ void pack_wqkv(const float* __restrict__ Wd, const float* __restrict__ Wb,
                          const float* __restrict__ Wc, __half* __restrict__ dst) {
    for (int idx = threadIdx.x; idx < 20480; idx += 256) {
        int j = idx & 7, lane = (idx >> 3) & 31, ks = (idx >> 8) & 7, mt = idx >> 11;
        int reg = j >> 1, h = j & 1;
        int row = mt * 16 + (lane >> 2) + (reg & 1) * 8;
        int col = ks * 16 + (lane & 3) * 2 + (reg >> 1) * 8 + h;
        float w;
        if (row < 128)      w = Wd[row * 128 + col];
        else if (row < 144) w = Wb[(row - 128) * 128 + col];
        else                w = Wc[(row - 144) * 128 + col];
        dst[idx] = __float2half(w);
    }
}

// ---------------------------------------------------------------------------
// conv3x3 implicit GEMM, fp16 m16n8k16, fused BN+ReLU.
// Optional f32 store, optional fp16 store, optional fp16 residual (lo) store.
// ---------------------------------------------------------------------------
#define CONV_SMEM 36864

template<int CIN_T>
__global__ void __launch_bounds__(256, 2) conv_mma_kernel(
        const __half* __restrict__ xpA, const __half* __restrict__ xpB,
        const __half* __restrict__ wfrag,
        const float* __restrict__ bn0, const float* __restrict__ bn1,
        float* __restrict__ out0, float* __restrict__ out1,
        __half* __restrict__ o16_0, __half* __restrict__ o16_1,
        __half* __restrict__ olo_0, __half* __restrict__ olo_1) {
    constexpr int CPC = CIN_T / 32;
    constexpr int NCHUNK = 9 * CPC;
    extern __shared__ __align__(16) char smc[];
    const uint32_t smb = smem_u32(smc);

    const int tid = threadIdx.x, lane = tid & 31, wid = tid >> 5;
    const int warp_m = wid >> 2, warp_n = wid & 3;
    const int b = blockIdx.y, z = blockIdx.z;
    const int pxbase = blockIdx.x * 128;
    const int h0 = pxbase >> 6;
    const __half* xp = z ? xpB : xpA;
    const __half* Wf = wfrag + (size_t)z * NCHUNK * 4096;
    const float* bn = z ? bn1 : bn0;
    float* out = z ? out1 : out0;
    __half* o16 = z ? o16_1 : o16_0;
    __half* olo = z ? olo_1 : olo_0;

    const int g = lane >> 3;

    float acc[4][4][4];
#pragma unroll
    for (int mt = 0; mt < 4; mt++)
#pragma unroll
        for (int nt = 0; nt < 4; nt++)
#pragma unroll
            for (int r = 0; r < 4; r++) acc[mt][nt][r] = 0.0f;

    auto stage = [&](int i, int buf) {
        const int kwh = i / CPC, cb = i % CPC;
        const int kh = kwh / 3, kw = kwh % 3;
        const __half* Asrc = Wf + (size_t)i * 4096;
        const uint32_t Adst = smb + buf * 8192;
#pragma unroll
        for (int t = 0; t < 2; t++) {
            int i16 = tid + t * 256;
            CP_ASYNC16(Adst + i16 * 16, Asrc + i16 * 8);
        }
        const uint32_t Bdst = smb + 16384 + buf * 10240;
#pragma unroll
        for (int t = 0; t < 2; t++) {
            int idx = tid + t * 256;
            int px = idx >> 2, q = idx & 3;
            const __half* src = xp + (((size_t)b * XP_H + h0 + (px >> 6) + kh) * XP_H
                                      + (px & 63) + kw) * CIN_T + cb * 32 + q * 8;
            CP_ASYNC16(Bdst + px * 80 + q * 16, src);
        }
        CP_COMMIT();
    };

    stage(0, 0);
    for (int i = 0; i < NCHUNK; i++) {
        const int buf = i & 1;
        if (i + 1 < NCHUNK) {
            stage(i + 1, buf ^ 1);
            CP_WAIT(1);
        } else {
            CP_WAIT(0);
        }
        __syncthreads();

        const uint32_t Bsm = smb + 16384 + buf * 10240;
        const char* Aptr = smc + buf * 8192;
#pragma unroll
        for (int ks = 0; ks < 2; ks++) {
            uint32_t afr[4][4];
#pragma unroll
            for (int mt = 0; mt < 4; mt++) {
                uint4 v = *(const uint4*)(Aptr + ((((warp_m * 4 + mt) * 2 + ks) * 32 + lane) << 4));
                afr[mt][0] = v.x; afr[mt][1] = v.y; afr[mt][2] = v.z; afr[mt][3] = v.w;
            }
            uint32_t bfr[2][4];
#pragma unroll
            for (int t16 = 0; t16 < 2; t16++) {
                const int n_row = warp_n * 32 + t16 * 16 + (g >> 1) * 8 + (lane & 7);
                ldsm4(bfr[t16], Bsm + n_row * 80 + ks * 32 + (g & 1) * 16);
            }
#pragma unroll
            for (int mt = 0; mt < 4; mt++)
#pragma unroll
                for (int t16 = 0; t16 < 2; t16++) {
                    mma_f16(acc[mt][2 * t16],     afr[mt], bfr[t16][0], bfr[t16][1]);
                    mma_f16(acc[mt][2 * t16 + 1], afr[mt], bfr[t16][2], bfr[t16][3]);
                }
        }
        __syncthreads();
    }

#pragma unroll
    for (int mt = 0; mt < 4; mt++) {
        const int co = warp_m * 64 + mt * 16 + (lane >> 2);
        const float sc0 = bn[co],     sh0 = bn[128 + co];
        const float sc8 = bn[co + 8], sh8 = bn[136 + co];
#pragma unroll
        for (int nt = 0; nt < 4; nt++) {
            const int px = pxbase + warp_n * 32 + nt * 8 + 2 * (lane & 3);
            float2 v0, v1;
            v0.x = fmaxf(acc[mt][nt][0] * sc0 + sh0, 0.0f);
            v0.y = fmaxf(acc[mt][nt][1] * sc0 + sh0, 0.0f);
            v1.x = fmaxf(acc[mt][nt][2] * sc8 + sh8, 0.0f);
            v1.y = fmaxf(acc[mt][nt][3] * sc8 + sh8, 0.0f);
            if (out) {
                *(float2*)(out + ((size_t)b * 128 + co) * NPIX + px) = v0;
                *(float2*)(out + ((size_t)b * 128 + co + 8) * NPIX + px) = v1;
            }
            if (o16) {
                *(uint32_t*)(o16 + ((size_t)b * 128 + co) * NPIX + px) = ph2(v0.x, v0.y);
                *(uint32_t*)(o16 + ((size_t)b * 128 + co + 8) * NPIX + px) = ph2(v1.x, v1.y);
            }
            if (olo) {
                float h0x = __half2float(__float2half(v0.x));
                float h0y = __half2float(__float2half(v0.y));
                float h1x = __half2float(__float2half(v1.x));
                float h1y = __half2float(__float2half(v1.y));
                *(uint32_t*)(olo + ((size_t)b * 128 + co) * NPIX + px) =
                    ph2(v0.x - h0x, v0.y - h0y);
                *(uint32_t*)(olo + ((size_t)b * 128 + co + 8) * NPIX + px) =
                    ph2(v1.x - h1x, v1.y - h1y);
            }
        }
    }
}

// ---------------------------------------------------------------------------
// QKV GEMM: [Wd;Wb;Wc](160x128) @ y16(128x4096) + bias.
// ---------------------------------------------------------------------------
#define QKV_SMEM 59392

__global__ void __launch_bounds__(320, 1) qkv_kernel(
        const __half* __restrict__ wq, const __half* __restrict__ y16,
        const float* __restrict__ bd, const float* __restrict__ bb,
        const float* __restrict__ bc,
        __half* __restrict__ vh, __half* __restrict__ qh, __half* __restrict__ kh) {
    extern __shared__ __align__(16) char smc[];
    const uint32_t smb = smem_u32(smc);
    const int tid = threadIdx.x, lane = tid & 31, wid = tid >> 5;
    const int b = blockIdx.y;
    const int n0 = blockIdx.x * 64;
    const int g = lane >> 3;

#pragma unroll
    for (int t = 0; t < 8; t++) {
        int i = tid + t * 320;
        CP_ASYNC16(smb + i * 16, wq + i * 8);
    }
    for (int idx = tid; idx < 1024; idx += 320) {
        int ch = idx >> 3, seg = idx & 7;
        CP_ASYNC16(smb + 40960 + ch * 144 + seg * 16,
                   y16 + ((size_t)b * 128 + ch) * NPIX + n0 + seg * 8);
    }
    CP_COMMIT();
    CP_WAIT(0);
    __syncthreads();

    const int mt = wid;
    float acc[8][4];
#pragma unroll
    for (int nt = 0; nt < 8; nt++)
#pragma unroll
        for (int r = 0; r < 4; r++) acc[nt][r] = 0.0f;

    const char* Aptr = smc;
    const uint32_t Bsm = smb + 40960;
#pragma unroll
    for (int ks = 0; ks < 8; ks++) {
        uint4 v = *(const uint4*)(Aptr + (((mt * 8 + ks) * 32 + lane) << 4));
        uint32_t afr[4] = {v.x, v.y, v.z, v.w};
#pragma unroll
        for (int t16 = 0; t16 < 4; t16++) {
            uint32_t bfr[4];
            ldsm4t(bfr, Bsm + (ks * 16 + (g & 1) * 8 + (lane & 7)) * 144
                       + (t16 * 16 + (g >> 1) * 8) * 2);
            mma_f16(acc[2 * t16],     afr, bfr[0], bfr[1]);
            mma_f16(acc[2 * t16 + 1], afr, bfr[2], bfr[3]);
        }
    }

    const int r0 = mt * 16 + (lane >> 2);
    if (mt < 8) {
        const float b0 = bd[r0], b8 = bd[r0 + 8];
        __half* v0 = vh + ((size_t)b * 128 + r0) * NPIX;
        __half* v8 = vh + ((size_t)b * 128 + r0 + 8) * NPIX;
#pragma unroll
        for (int nt = 0; nt < 8; nt++) {
            const int n = n0 + nt * 8 + 2 * (lane & 3);
            *(uint32_t*)(v0 + n) = ph2(acc[nt][0] + b0, acc[nt][1] + b0);
            *(uint32_t*)(v8 + n) = ph2(acc[nt][2] + b8, acc[nt][3] + b8);
        }
    } else {
        const bool isq = (mt == 8);
        const float* bias = isq ? bb : bc;
        __half* dst = isq ? qh : kh;
        const int d = lane >> 2;
        const float b0 = bias[d], b8 = bias[d + 8];
#pragma unroll
        for (int nt = 0; nt < 8; nt++) {
            const int n = n0 + nt * 8 + 2 * (lane & 3);
            __half* p0 = dst + ((size_t)b * NPIX + n) * 16;
            p0[d]      = __float2half(acc[nt][0] + b0);
            p0[16 + d] = __float2half(acc[nt][1] + b0);
            p0[d + 8]      = __float2half(acc[nt][2] + b8);
            p0[16 + d + 8] = __float2half(acc[nt][3] + b8);
        }
    }
}

// ---------------------------------------------------------------------------
// PAM flash attention: q-tile 64, 128-thread CTA (4 warps x 16q x 128ch),
// occupancy 3.  SMEM: Q [64][48] @0; K 2x[64][48] @3072; V 2x[128][144] @9216.
// ---------------------------------------------------------------------------
#define ATT_SMEM 46080

__global__ void __launch_bounds__(128, 3) pam_attn_mma(
        const __half* __restrict__ qh, const __half* __restrict__ kh,
        const __half* __restrict__ vd, const float* __restrict__ y,
        const float* __restrict__ alpha, __half* __restrict__ xp2) {
    extern __shared__ __align__(16) char smc[];
    const uint32_t smb = smem_u32(smc);
    const uint32_t Qb  = smb;
    const uint32_t Kb0 = smb + 3072;
    const uint32_t Vb0 = smb + 9216;

    const int tid = threadIdx.x, lane = tid & 31, wid = tid >> 5;
    const int b = blockIdx.y;
    const int n0 = blockIdx.x * 64;
    const int qbase = wid * 16;

    const int g = lane >> 3, r8 = lane & 7;
    const uint32_t qoff = (uint32_t)(((g & 1) * 8 + r8) * 48 + (g >> 1) * 16);
    const uint32_t koff = (uint32_t)(((g >> 1) * 8 + r8) * 48 + (g & 1) * 16);
    const uint32_t voff = (uint32_t)(((g >> 1) * 8 + r8) * 144 + (g & 1) * 16);

    auto stageKV = [&](int t, int buf) {
        const int k0 = t * 64;
        {
            int row = tid >> 1, h = tid & 1;
            CP_ASYNC16(Kb0 + buf * 3072 + row * 48 + h * 16,
                       kh + ((size_t)b * NPIX + k0 + row) * 16 + h * 8);
        }
#pragma unroll
        for (int t4 = 0; t4 < 8; t4++) {
            int idx = tid + t4 * 128;
            int ch = idx >> 3, c = idx & 7;
            CP_ASYNC16(Vb0 + buf * 18432 + ch * 144 + c * 16,
                       vd + ((size_t)b * 128 + ch) * NPIX + k0 + c * 8);
        }
        CP_COMMIT();
    };

    {
        int row = tid >> 1, h = tid & 1;
        CP_ASYNC16(Qb + row * 48 + h * 16,
                   qh + ((size_t)b * NPIX + n0 + row) * 16 + h * 8);
    }
    stageKV(0, 0);

    uint32_t qfr[4];
    float O[16][4];
#pragma unroll
    for (int nc = 0; nc < 16; nc++)
#pragma unroll
        for (int r = 0; r < 4; r++) O[nc][r] = 0.0f;
    float mrun0 = -1e30f, mrun1 = -1e30f, lrun0 = 0.0f, lrun1 = 0.0f;

    for (int t = 0; t < 64; t++) {
        const int buf = t & 1;
        CP_WAIT(0);
        __syncthreads();
        if (t + 1 < 64) stageKV(t + 1, buf ^ 1);
        if (t == 0) ldsm4(qfr, Qb + qbase * 48 + qoff);

        const uint32_t Kb = Kb0 + buf * 3072;
        const uint32_t Vb = Vb0 + buf * 18432;

        float S[8][4];
#pragma unroll
        for (int ks = 0; ks < 4; ks++) {
            uint32_t kb[4];
            ldsm4(kb, Kb + ks * 768 + koff);
#pragma unroll
            for (int r = 0; r < 4; r++) { S[2 * ks][r] = 0.0f; S[2 * ks + 1][r] = 0.0f; }
            mma_f16(S[2 * ks],     qfr, kb[0], kb[1]);
            mma_f16(S[2 * ks + 1], qfr, kb[2], kb[3]);
        }

        float tm0 = -1e30f, tm1 = -1e30f;
#pragma unroll
        for (int nt = 0; nt < 8; nt++) {
            tm0 = fmaxf(tm0, fmaxf(S[nt][0], S[nt][1]));
            tm1 = fmaxf(tm1, fmaxf(S[nt][2], S[nt][3]));
        }
        tm0 = fmaxf(tm0, __shfl_xor_sync(0xffffffffu, tm0, 1));
        tm0 = fmaxf(tm0, __shfl_xor_sync(0xffffffffu, tm0, 2));
        tm1 = fmaxf(tm1, __shfl_xor_sync(0xffffffffu, tm1, 1));
        tm1 = fmaxf(tm1, __shfl_xor_sync(0xffffffffu, tm1, 2));
        const float mn0 = fmaxf(mrun0, tm0), mn1 = fmaxf(mrun1, tm1);
        const float f0 = fexp(mrun0 - mn0), f1 = fexp(mrun1 - mn1);
        mrun0 = mn0; mrun1 = mn1;

        float ts0 = 0.0f, ts1 = 0.0f;
        uint32_t afr[4][4];
#pragma unroll
        for (int j = 0; j < 4; j++) {
            float p00 = fexp(S[2 * j][0] - mn0), p01 = fexp(S[2 * j][1] - mn0);
            float p10 = fexp(S[2 * j][2] - mn1), p11 = fexp(S[2 * j][3] - mn1);
            float q00 = fexp(S[2 * j + 1][0] - mn0), q01 = fexp(S[2 * j + 1][1] - mn0);
            float q10 = fexp(S[2 * j + 1][2] - mn1), q11 = fexp(S[2 * j + 1][3] - mn1);
            ts0 += (p00 + p01) + (q00 + q01);
            ts1 += (p10 + p11) + (q10 + q11);
            afr[j][0] = ph2(p00, p01);
            afr[j][1] = ph2(p10, p11);
            afr[j][2] = ph2(q00, q01);
            afr[j][3] = ph2(q10, q11);
        }
        ts0 += __shfl_xor_sync(0xffffffffu, ts0, 1);
        ts0 += __shfl_xor_sync(0xffffffffu, ts0, 2);
        ts1 += __shfl_xor_sync(0xffffffffu, ts1, 1);
        ts1 += __shfl_xor_sync(0xffffffffu, ts1, 2);
        lrun0 = lrun0 * f0 + ts0;
        lrun1 = lrun1 * f1 + ts1;

#pragma unroll
        for (int nc = 0; nc < 16; nc++) {
            O[nc][0] *= f0; O[nc][1] *= f0;
            O[nc][2] *= f1; O[nc][3] *= f1;
        }

#pragma unroll
        for (int j = 0; j < 4; j++) {
            const uint32_t vb_j = Vb + j * 32 + voff;
#pragma unroll
            for (int p = 0; p < 8; p++) {
                uint32_t vb[4];
                ldsm4(vb, vb_j + p * 2304);
                mma_f16(O[2 * p],     afr[j], vb[0], vb[1]);
                mma_f16(O[2 * p + 1], afr[j], vb[2], vb[3]);
            }
        }
    }

    const float linv0 = 1.0f / lrun0, linv1 = 1.0f / lrun1;
    const float a = alpha[0];
    const int px0 = n0 + qbase + (lane >> 2);
    const int px1 = px0 + 8;
    __half* dst0 = xp2 + (((size_t)b * XP_H + (px0 >> 6) + 1) * XP_H + (px0 & 63) + 1) * CI;
    __half* dst1 = xp2 + (((size_t)b * XP_H + (px1 >> 6) + 1) * XP_H + (px1 & 63) + 1) * CI;
#pragma unroll
    for (int nc = 0; nc < 16; nc++) {
        const int ch = nc * 8 + 2 * (lane & 3);
        const float* y0 = y + ((size_t)b * 128 + ch) * NPIX;
        *(uint32_t*)(dst0 + ch) = ph2(fmaf(a, O[nc][0] * linv0, y0[px0]),
                                      fmaf(a, O[nc][1] * linv0, y0[NPIX + px0]));
        *(uint32_t*)(dst1 + ch) = ph2(fmaf(a, O[nc][2] * linv1, y0[px1]),
                                      fmaf(a, O[nc][3] * linv1, y0[NPIX + px1]));
    }
}

// ---------------------------------------------------------------------------
// CAM gram matrix via fp16 hi/lo split MMA (~f32 accurate).
// grid (KSPLIT, 8b), block 256 (8 warps 2Mx4N, warp tile 64x32).
// Each CTA covers 256 keys (4 chunks of 64); writes partial to epart.
// smem: hi [128][144B] @0 (18432); lo @18432.  Total 36864.
// ---------------------------------------------------------------------------
#define CAME_SMEM 36864

__global__ void __launch_bounds__(256, 2) cam_energy_mma(
        const __half* __restrict__ yhi, const __half* __restrict__ ylo,
        float* __restrict__ epart) {
    extern __shared__ __align__(16) char smc[];
    const uint32_t smb = smem_u32(smc);
    const int tid = threadIdx.x, lane = tid & 31, wid = tid >> 5;
    const int warp_m = wid >> 2, warp_n = wid & 3;
    const int b = blockIdx.y, ksid = blockIdx.x;
    const int g = lane >> 3, r8 = lane & 7;

    float acc[4][4][4];
#pragma unroll
    for (int mt = 0; mt < 4; mt++)
#pragma unroll
        for (int nt = 0; nt < 4; nt++)
#pragma unroll
            for (int r = 0; r < 4; r++) acc[mt][nt][r] = 0.0f;

    for (int chunk = 0; chunk < 4; chunk++) {
        const int k0 = ksid * 256 + chunk * 64;
        __syncthreads();
#pragma unroll
        for (int t = 0; t < 4; t++) {
            int idx = tid + t * 256;
            int ch = idx >> 3, seg = idx & 7;
            CP_ASYNC16(smb + ch * 144 + seg * 16,
                       yhi + ((size_t)b * 128 + ch) * NPIX + k0 + seg * 8);
            CP_ASYNC16(smb + 18432 + ch * 144 + seg * 16,
                       ylo + ((size_t)b * 128 + ch) * NPIX + k0 + seg * 8);
        }
        CP_COMMIT();
        CP_WAIT(0);
        __syncthreads();

#pragma unroll
        for (int ks = 0; ks < 4; ks++) {
            uint32_t ahi[4][4], alo[4][4];
#pragma unroll
            for (int mt = 0; mt < 4; mt++) {
                const uint32_t arow = (warp_m * 64 + mt * 16 + (g & 1) * 8 + r8) * 144
                                      + ks * 32 + (g >> 1) * 16;
                ldsm4(ahi[mt], smb + arow);
                ldsm4(alo[mt], smb + 18432 + arow);
            }
            uint32_t bhi[2][4], blo[2][4];
#pragma unroll
            for (int t16 = 0; t16 < 2; t16++) {
                const uint32_t brow = (warp_n * 32 + t16 * 16 + (g >> 1) * 8 + r8) * 144
                                      + ks * 32 + (g & 1) * 16;
                ldsm4(bhi[t16], smb + brow);
                ldsm4(blo[t16], smb + 18432 + brow);
            }
#pragma unroll
            for (int mt = 0; mt < 4; mt++)
#pragma unroll
                for (int t16 = 0; t16 < 2; t16++) {
                    mma_f16(acc[mt][2 * t16],     ahi[mt], bhi[t16][0], bhi[t16][1]);
                    mma_f16(acc[mt][2 * t16 + 1], ahi[mt], bhi[t16][2], bhi[t16][3]);
                    mma_f16(acc[mt][2 * t16],     ahi[mt], blo[t16][0], blo[t16][1]);
                    mma_f16(acc[mt][2 * t16 + 1], ahi[mt], blo[t16][2], blo[t16][3]);
                    mma_f16(acc[mt][2 * t16],     alo[mt], bhi[t16][0], bhi[t16][1]);
                    mma_f16(acc[mt][2 * t16 + 1], alo[mt], bhi[t16][2], bhi[t16][3]);
                }
        }
    }

    float* ep = epart + (((size_t)ksid * BATCH + b) * 128) * 128;
#pragma unroll
    for (int mt = 0; mt < 4; mt++) {
        const int c0 = warp_m * 64 + mt * 16 + (lane >> 2);
#pragma unroll
        for (int nt = 0; nt < 4; nt++) {
            const int d = warp_n * 32 + nt * 8 + 2 * (lane & 3);
            *(float2*)(ep + (size_t)c0 * 128 + d) = make_float2(acc[mt][nt][0], acc[mt][nt][1]);
            *(float2*)(ep + (size_t)(c0 + 8) * 128 + d) = make_float2(acc[mt][nt][2], acc[mt][nt][3]);
        }
    }
}

// ---------------------------------------------------------------------------
// CAM softmax of (rowmax - E), reducing the KSPLIT partials -> fp16 attn
// ---------------------------------------------------------------------------
__global__ void cam_softmax_kernel(const float* __restrict__ epart,
                                   __half* __restrict__ attn) {
    const int row = blockIdx.x;       // b*128 + c  (1024 rows)
    const int tid = threadIdx.x;
    __shared__ float red[4];

    float e = 0.0f;
#pragma unroll
    for (int s = 0; s < KSPLIT; s++)
        e += epart[((size_t)s * 1024 + row) * 128 + tid];

    float m = e;
#pragma unroll
    for (int off = 16; off; off >>= 1) m = fmaxf(m, __shfl_xor_sync(0xffffffff, m, off));
    if ((tid & 31) == 0) red[tid >> 5] = m;
    __syncthreads();
    float mx = fmaxf(fmaxf(red[0], red[1]), fmaxf(red[2], red[3]));
    float e2 = mx - e;
    __syncthreads();

    float m2 = e2;
#pragma unroll
    for (int off = 16; off; off >>= 1) m2 = fmaxf(m2, __shfl_xor_sync(0xffffffff, m2, off));
    if ((tid & 31) == 0) red[tid >> 5] = m2;
    __syncthreads();
    m2 = fmaxf(fmaxf(red[0], red[1]), fmaxf(red[2], red[3]));
    float p = __expf(e2 - m2);
    __syncthreads();

    float s = p;
#pragma unroll
    for (int off = 16; off; off >>= 1) s += __shfl_xor_sync(0xffffffff, s, off);
    if ((tid & 31) == 0) red[tid >> 5] = s;
    __syncthreads();
    s = red[0] + red[1] + red[2] + red[3];

    attn[(size_t)row * 128 + tid] = __float2half(p / s);
}

// ---------------------------------------------------------------------------
// CAM feature via fp16 MMA -> fp16 padded NHWC conv2 input.
// ---------------------------------------------------------------------------
#define CAMF_SMEM 53248

__global__ void __launch_bounds__(256, 1) cam_feat_mma(
        const __half* __restrict__ attn16, const __half* __restrict__ y16,
        const float* __restrict__ yf, const float* __restrict__ beta,
        __half* __restrict__ xp2) {
    extern __shared__ __align__(16) char smc[];
    const uint32_t smb = smem_u32(smc);
    const int tid = threadIdx.x, lane = tid & 31, wid = tid >> 5;
    const int b = blockIdx.y;
    const int n0 = blockIdx.x * 64;
    const int g = lane >> 3;

#pragma unroll
    for (int t = 0; t < 8; t++) {
        int idx = tid + t * 256;
        int c = idx >> 4, seg = idx & 15;
        CP_ASYNC16(smb + c * 272 + seg * 16,
                   attn16 + ((size_t)b * 128 + c) * 128 + seg * 8);
    }
#pragma unroll
    for (int t = 0; t < 4; t++) {
        int idx = tid + t * 256;
        int ch = idx >> 3, seg = idx & 7;
        CP_ASYNC16(smb + 34816 + ch * 144 + seg * 16,
                   y16 + ((size_t)b * 128 + ch) * NPIX + n0 + seg * 8);
    }
    CP_COMMIT();
    CP_WAIT(0);
    __syncthreads();

    const int mt = wid;
    float acc[8][4];
#pragma unroll
    for (int nt = 0; nt < 8; nt++)
#pragma unroll
        for (int r = 0; r < 4; r++) acc[nt][r] = 0.0f;

    const uint32_t Bsm = smb + 34816;
#pragma unroll
    for (int ks = 0; ks < 8; ks++) {
        uint32_t afr[4];
        ldsm4(afr, smb + (mt * 16 + (g & 1) * 8 + (lane & 7)) * 272
                  + ks * 32 + (g >> 1) * 16);
#pragma unroll
        for (int t16 = 0; t16 < 4; t16++) {
            uint32_t bfr[4];
            ldsm4t(bfr, Bsm + (ks * 16 + (g & 1) * 8 + (lane & 7)) * 144
                       + (t16 * 16 + (g >> 1) * 8) * 2);
            mma_f16(acc[2 * t16],     afr, bfr[0], bfr[1]);
            mma_f16(acc[2 * t16 + 1], afr, bfr[2], bfr[3]);
        }
    }

    const float bet = beta[0];
    const int c0 = mt * 16 + (lane >> 2);
#pragma unroll
    for (int nt = 0; nt < 8; nt++) {
        const int n = n0 + nt * 8 + 2 * (lane & 3);
        const float* y0 = yf + ((size_t)b * 128 + c0) * NPIX;
        const float* y8 = y0 + 8 * NPIX;
        __half* p0 = xp2 + (((size_t)b * XP_H + (n >> 6) + 1) * XP_H + (n & 63) + 1) * CI;
        __half* p1 = p0 + CI;
        p0[c0]     = __float2half(fmaf(bet, acc[nt][0], y0[n]));
        p1[c0]     = __float2half(fmaf(bet, acc[nt][1], y0[n + 1]));
        p0[c0 + 8] = __float2half(fmaf(bet, acc[nt][2], y8[n]));
        p1[c0 + 8] = __float2half(fmaf(bet, acc[nt][3], y8[n + 1]));
    }
}

// ---------------------------------------------------------------------------
// Final heads (fp16 inputs): three 1x1 convs (128->19) + sigmoid.
// ---------------------------------------------------------------------------
__global__ void final_kernel(const __half* __restrict__ fp,
                             const __half* __restrict__ fc,
                             const float* __restrict__ Wout, const float* __restrict__ bout,
                             const float* __restrict__ Wp3, const float* __restrict__ bp3,
                             const float* __restrict__ Wc3, const float* __restrict__ bc3,
                             float* __restrict__ out) {
    const int b  = blockIdx.y;
    const int px = blockIdx.x * 256 + threadIdx.x;

    __shared__ float Wo[19][128];
    __shared__ float Wp[19][128];
    __shared__ float Wc[19][128];
    for (int i = threadIdx.x; i < 19 * 128; i += 256) {
        Wo[i / 128][i % 128] = Wout[i];
        Wp[i / 128][i % 128] = Wp3[i];
        Wc[i / 128][i % 128] = Wc3[i];
    }
    __syncthreads();

    float am[19], ap[19], ac[19];
#pragma unroll
    for (int o = 0; o < 19; o++) { am[o] = bout[o]; ap[o] = bp3[o]; ac[o] = bc3[o]; }

    for (int c = 0; c < 128; c++) {
        float vp = __half2float(fp[((size_t)b * 128 + c) * NPIX + px]);
        float vc = __half2float(fc[((size_t)b * 128 + c) * NPIX + px]);
        float vf = vp + vc;
#pragma unroll
        for (int o = 0; o < 19; o++) {
            am[o] += Wo[o][c] * vf;
            ap[o] += Wp[o][c] * vp;
            ac[o] += Wc[o][c] * vc;
        }
    }

    const size_t SEG = (size_t)BATCH * NC * NPIX;
#pragma unroll
    for (int o = 0; o < 19; o++) {
        size_t base = ((size_t)b * NC + o) * NPIX + px;
        out[base]           = sigmoidf_(am[o]);
        out[SEG + base]     = sigmoidf_(ap[o]);
        out[2 * SEG + base] = sigmoidf_(ac[o]);
    }
}

// ---------------------------------------------------------------------------
// Launch
// ---------------------------------------------------------------------------
extern "C" void kernel_launch(void* const* d_in, const int* in_sizes, int n_in,
                              void* d_out, int out_size) {
    const float* x    = (const float*)d_in[0];
    const float* Wp1  = (const float*)d_in[1];
    const float* bnp1 = (const float*)d_in[2];
    const float* Wc1  = (const float*)d_in[3];
    const float* bnc1 = (const float*)d_in[4];
    const float* Wb   = (const float*)d_in[5];
    const float* bb   = (const float*)d_in[6];
    const float* Wc   = (const float*)d_in[7];
    const float* bc   = (const float*)d_in[8];
    const float* Wd   = (const float*)d_in[9];
    const float* bd   = (const float*)d_in[10];
    const float* alpha= (const float*)d_in[11];
    const float* beta = (const float*)d_in[12];
    const float* Wp2  = (const float*)d_in[13];
    const float* bnp2 = (const float*)d_in[14];
    const float* Wc2  = (const float*)d_in[15];
    const float* bnc2 = (const float*)d_in[16];
    const float* Wout = (const float*)d_in[17];
    const float* bout = (const float*)d_in[18];
    const float* Wp3  = (const float*)d_in[19];
    const float* bp3  = (const float*)d_in[20];
    const float* Wc3  = (const float*)d_in[21];
    const float* bc3  = (const float*)d_in[22];
    float* out = (float*)d_out;

    float *featp1, *featc1, *epart;
    __half *featp1h, *featc1h, *featc1lo, *qh, *kh, *vd, *attn16;
    __half *xpad, *xp2a, *xp2b, *wf1, *wf2, *wqkv;
    cudaGetSymbolAddress((void**)&featp1,   g_featp1);
    cudaGetSymbolAddress((void**)&featc1,   g_featc1);
    cudaGetSymbolAddress((void**)&featp1h,  g_featp1h);
    cudaGetSymbolAddress((void**)&featc1h,  g_featc1h);
    cudaGetSymbolAddress((void**)&featc1lo, g_featc1lo);
    cudaGetSymbolAddress((void**)&qh,       g_qh);
    cudaGetSymbolAddress((void**)&kh,       g_kh);
    cudaGetSymbolAddress((void**)&vd,       g_vd);
    cudaGetSymbolAddress((void**)&epart,    g_epart);
    cudaGetSymbolAddress((void**)&attn16,   g_attn16);
    cudaGetSymbolAddress((void**)&xpad,     g_xpad);
    cudaGetSymbolAddress((void**)&xp2a,     g_xp2a);
    cudaGetSymbolAddress((void**)&xp2b,     g_xp2b);
    cudaGetSymbolAddress((void**)&wf1,      g_wf16_1);
    cudaGetSymbolAddress((void**)&wf2,      g_wf16_2);
    cudaGetSymbolAddress((void**)&wqkv,     g_wqkv);

    cudaFuncSetAttribute(conv_mma_kernel<512>,
                         cudaFuncAttributeMaxDynamicSharedMemorySize, CONV_SMEM);
    cudaFuncSetAttribute(conv_mma_kernel<128>,
                         cudaFuncAttributeMaxDynamicSharedMemorySize, CONV_SMEM);
    cudaFuncSetAttribute(pam_attn_mma,
                         cudaFuncAttributeMaxDynamicSharedMemorySize, ATT_SMEM);
    cudaFuncSetAttribute(pam_attn_mma,
                         cudaFuncAttributePreferredSharedMemoryCarveout, 100);
    cudaFuncSetAttribute(qkv_kernel,
                         cudaFuncAttributeMaxDynamicSharedMemorySize, QKV_SMEM);
    cudaFuncSetAttribute(cam_energy_mma,
                         cudaFuncAttributeMaxDynamicSharedMemorySize, CAME_SMEM);
    cudaFuncSetAttribute(cam_feat_mma,
                         cudaFuncAttributeMaxDynamicSharedMemorySize, CAMF_SMEM);

    // Packing
    pack_x_kernel<<<dim3(64, BATCH), 256>>>(x, xpad);
    zero_border_h<<<dim3(XP_H, BATCH), 256>>>(xpad, CIN);
    zero_border_h<<<dim3(XP_H, BATCH), 256>>>(xp2a, CI);
    zero_border_h<<<dim3(XP_H, BATCH), 256>>>(xp2b, CI);
    pack_w16<<<dim3(144, 2), 256>>>(Wp1, Wc1, wf1, CIN);
    pack_w16<<<dim3(36, 2), 256>>>(Wp2, Wc2, wf2, CI);
    pack_wqkv<<<1, 256>>>(Wd, Wb, Wc, wqkv);

    // conv1: both 512->128 convs (f32 + fp16 hi; lo residual for CAM branch)
    conv_mma_kernel<512><<<dim3(32, BATCH, 2), 256, CONV_SMEM>>>(
        xpad, xpad, wf1, bnp1, bnc1, featp1, featc1, featp1h, featc1h,
        nullptr, featc1lo);

    // PAM
    qkv_kernel<<<dim3(64, BATCH), 320, QKV_SMEM>>>(
        wqkv, featp1h, bd, bb, bc, vd, qh, kh);
    pam_attn_mma<<<dim3(64, BATCH), 128, ATT_SMEM>>>(qh, kh, vd, featp1, alpha, xp2a);

    // CAM
    cam_energy_mma<<<dim3(KSPLIT, BATCH), 256, CAME_SMEM>>>(featc1h, featc1lo, epart);
    cam_softmax_kernel<<<BATCH * 128, 128>>>(epart, attn16);
    cam_feat_mma<<<dim3(64, BATCH), 256, CAMF_SMEM>>>(
        attn16, featc1h, featc1, beta, xp2b);

    // conv2: fp16 in -> fp16 out only (reuse featp1h/featc1h)
    conv_mma_kernel<128><<<dim3(32, BATCH, 2), 256, CONV_SMEM>>>(
        xp2a, xp2b, wf2, bnp2, bnc2, nullptr, nullptr, featp1h, featc1h,
        nullptr, nullptr);

    // Heads
    final_kernel<<<dim3(16, BATCH), 256>>>(featp1h, featc1h,
                                           Wout, bout, Wp3, bp3, Wc3, bc3, out);
}

// round 9
// speedup vs baseline: 11.8404x; 1.2222x over previous
#include <cuda_runtime.h>
#include <cuda_bf16.h>
#include <cuda_fp16.h>
#include <math.h>
#include <cstdint>

// ---------------------------------------------------------------------------
// Problem constants
// ---------------------------------------------------------------------------
#define BATCH 8
#define CIN   512
#define CI    128
#define CK    16
#define NC    19
#define NPIX  4096
#define FEAT_ELEMS (BATCH * CI * NPIX)
#define XP_H 66
#define KSPLIT 16

// ---------------------------------------------------------------------------
// Scratch (device globals)
// ---------------------------------------------------------------------------
__device__ __half g_featp1h[FEAT_ELEMS];     // conv1-p hi; later conv2-p out
__device__ __half g_featp1lo[FEAT_ELEMS];    // conv1-p lo residual
__device__ __half g_featc1h[FEAT_ELEMS];     // conv1-c hi; later conv2-c out
__device__ __half g_featc1lo[FEAT_ELEMS];    // conv1-c lo residual
__device__ __half g_qh[BATCH * NPIX * CK];
__device__ __half g_kh[BATCH * NPIX * CK];
__device__ __half g_vd[FEAT_ELEMS];
__device__ float  g_epart[KSPLIT * BATCH * CI * CI];
__device__ __half g_attn16[BATCH * CI * CI];
__device__ __half g_xpad[BATCH * XP_H * XP_H * CIN];
__device__ __half g_xp2a[BATCH * XP_H * XP_H * CI];
__device__ __half g_xp2b[BATCH * XP_H * XP_H * CI];
__device__ __half g_wf16_1[2 * 144 * 4096];
__device__ __half g_wf16_2[2 * 36 * 4096];
__device__ __half g_wqkv[10 * 8 * 32 * 8];

__device__ __forceinline__ float sigmoidf_(float x) {
    return 1.0f / (1.0f + __expf(-x));
}
__device__ __forceinline__ uint32_t smem_u32(const void* p) {
    uint32_t a;
    asm("{ .reg .u64 t; cvta.to.shared.u64 t, %1; cvt.u32.u64 %0, t; }" : "=r"(a) : "l"(p));
    return a;
}
__device__ __forceinline__ void mma_f16(float c[4], const uint32_t a[4], const uint32_t b0, const uint32_t b1) {
    asm volatile(
        "mma.sync.aligned.m16n8k16.row.col.f32.f16.f16.f32 "
        "{%0,%1,%2,%3}, {%4,%5,%6,%7}, {%8,%9}, {%0,%1,%2,%3};"
        : "+f"(c[0]), "+f"(c[1]), "+f"(c[2]), "+f"(c[3])
        : "r"(a[0]), "r"(a[1]), "r"(a[2]), "r"(a[3]), "r"(b0), "r"(b1));
}
__device__ __forceinline__ void ldsm4(uint32_t r[4], uint32_t addr) {
    asm volatile("ldmatrix.sync.aligned.m8n8.x4.shared.b16 {%0,%1,%2,%3}, [%4];"
                 : "=r"(r[0]), "=r"(r[1]), "=r"(r[2]), "=r"(r[3]) : "r"(addr));
}
__device__ __forceinline__ void ldsm4t(uint32_t r[4], uint32_t addr) {
    asm volatile("ldmatrix.sync.aligned.m8n8.x4.trans.shared.b16 {%0,%1,%2,%3}, [%4];"
                 : "=r"(r[0]), "=r"(r[1]), "=r"(r[2]), "=r"(r[3]) : "r"(addr));
}
#define CP_ASYNC16(dst, src) \
    asm volatile("cp.async.ca.shared.global [%0], [%1], 16;" :: "r"(dst), "l"(src))
#define CP_COMMIT() asm volatile("cp.async.commit_group;")
#define CP_WAIT(N)  asm volatile("cp.async.wait_group %0;" :: "n"(N))

__device__ __forceinline__ uint32_t ph2(float x, float y) {
    __half2 h = __floats2half2_rn(x, y);
    return *(uint32_t*)&h;
}

// ---------------------------------------------------------------------------
// Pack x: f32 NCHW -> fp16 NHWC padded
// ---------------------------------------------------------------------------
__global__ void pack_x_kernel(const float* __restrict__ x, __half* __restrict__ xp) {
    const int h = blockIdx.x, b = blockIdx.y, tid = threadIdx.x;
    __shared__ float s[32][65];
    for (int ci0 = 0; ci0 < CIN; ci0 += 32) {
        for (int idx = tid; idx < 32 * 64; idx += 256) {
            int ci_l = idx >> 6, w = idx & 63;
            s[ci_l][w] = x[(((size_t)b * CIN + ci0 + ci_l) * 64 + h) * 64 + w];
        }
        __syncthreads();
        for (int idx = tid; idx < 64 * 32; idx += 256) {
            int w = idx >> 5, ci_l = idx & 31;
            xp[(((size_t)b * XP_H + h + 1) * XP_H + w + 1) * CIN + ci0 + ci_l] =
                __float2half(s[ci_l][w]);
        }
        __syncthreads();
    }
}

__global__ void zero_border_h(__half* __restrict__ xp, int C) {
    const int hp = blockIdx.x, b = blockIdx.y, tid = threadIdx.x;
    __half* row = xp + ((size_t)b * XP_H + hp) * XP_H * C;
    const __half z = __float2half(0.0f);
    if (hp == 0 || hp == XP_H - 1) {
        for (int idx = tid; idx < XP_H * C; idx += 256) row[idx] = z;
    } else {
        for (int idx = tid; idx < C; idx += 256) {
            row[idx] = z;
            row[(size_t)(XP_H - 1) * C + idx] = z;
        }
    }
}

// ---------------------------------------------------------------------------
// Pack conv weights into m16n8k16 fp16 A-fragment order.
// ---------------------------------------------------------------------------
__global__ void pack_w16(const float* __restrict__ W0, const float* __restrict__ W1,
                         __half* __restrict__ wf, int CIN_T) {
    const int cpc = CIN_T / 32;
    const int chunk = blockIdx.x;
    const int kwh = chunk / cpc, cb = chunk % cpc;
    const float* W = blockIdx.y ? W1 : W0;
    __half* dst = wf + ((size_t)blockIdx.y * gridDim.x + chunk) * 4096;
    for (int t = 0; t < 16; t++) {
        int idx = threadIdx.x + t * 256;
        int j = idx & 7, lane = (idx >> 3) & 31, ks = (idx >> 8) & 1, mt = idx >> 9;
        int reg = j >> 1, h = j & 1;
        int co = mt * 16 + (lane >> 2) + (reg & 1) * 8;
        int ci = cb * 32 + ks * 16 + (lane & 3) * 2 + (reg >> 1) * 8 + h;
        dst[idx] = __float2half(W[((size_t)co * CIN_T + ci) * 9 + kwh]);
    }
}

__global__ void pack_wqkv(const float* __restrict__ Wd, const float* __restrict__ Wb,
                          const float* __restrict__ Wc, __half* __restrict__ dst) {
    for (int idx = threadIdx.x; idx < 20480; idx += 256) {
        int j = idx & 7, lane = (idx >> 3) & 31, ks = (idx >> 8) & 7, mt = idx >> 11;
        int reg = j >> 1, h = j & 1;
        int row = mt * 16 + (lane >> 2) + (reg & 1) * 8;
        int col = ks * 16 + (lane & 3) * 2 + (reg >> 1) * 8 + h;
        float w;
        if (row < 128)      w = Wd[row * 128 + col];
        else if (row < 144) w = Wb[(row - 128) * 128 + col];
        else                w = Wc[(row - 144) * 128 + col];
        dst[idx] = __float2half(w);
    }
}

// ---------------------------------------------------------------------------
// conv3x3 implicit GEMM, fp16 m16n8k16, halo-reuse B staging, fused BN+ReLU.
// CTA: 128 co x 128 px (2 rows).  8 warps 2Mx4N (warp 64co x 32px).
// Per ci-chunk (32 ci): stage 4-row x 66-col halo ONCE; 9 taps read shifted
// windows.  Pixel stride 80B (16B-aligned; rows advance 20 banks -> the 8
// ldmatrix rows tile all 32 banks, conflict-free).  A staged per (cb,kh).
// smem: B 2x21120 @0; A 2x24576 @42240.  Total 91392.
// ---------------------------------------------------------------------------
#define CONV_SMEM 91392
#define BPX 80

template<int CIN_T>
__global__ void __launch_bounds__(256, 2) conv_mma_kernel(
        const __half* __restrict__ xpA, const __half* __restrict__ xpB,
        const __half* __restrict__ wfrag,
        const float* __restrict__ bn0, const float* __restrict__ bn1,
        __half* __restrict__ o16_0, __half* __restrict__ o16_1,
        __half* __restrict__ olo_0, __half* __restrict__ olo_1) {
    constexpr int CPC = CIN_T / 32;
    constexpr int NS = CPC * 3;
    extern __shared__ __align__(16) char smc[];
    const uint32_t smb = smem_u32(smc);
    const uint32_t Boff = smb;
    const uint32_t Aoff = smb + 2 * 21120;

    const int tid = threadIdx.x, lane = tid & 31, wid = tid >> 5;
    const int warp_m = wid >> 2, warp_n = wid & 3;
    const int b = blockIdx.y, z = blockIdx.z;
    const int pxbase = blockIdx.x * 128;
    const int h0 = pxbase >> 6;
    const __half* xp = z ? xpB : xpA;
    const __half* Wf = wfrag + (size_t)z * (9 * CPC) * 4096;
    const float* bn = z ? bn1 : bn0;
    __half* o16 = z ? o16_1 : o16_0;
    __half* olo = z ? olo_1 : olo_0;
    const int g = lane >> 3;

    float acc[4][4][4];
#pragma unroll
    for (int mt = 0; mt < 4; mt++)
#pragma unroll
        for (int nt = 0; nt < 4; nt++)
#pragma unroll
            for (int r = 0; r < 4; r++) acc[mt][nt][r] = 0.0f;

    auto stageA = [&](int s, int buf) {
        const int cb = s / 3, kh = s % 3;
        const uint32_t Ad = Aoff + buf * 24576;
#pragma unroll
        for (int kw = 0; kw < 3; kw++) {
            const __half* src = Wf + (size_t)((kh * 3 + kw) * CPC + cb) * 4096;
#pragma unroll
            for (int t = 0; t < 2; t++) {
                int idx = tid + t * 256;
                CP_ASYNC16(Ad + kw * 8192 + idx * 16, src + idx * 8);
            }
        }
    };
    auto stageB = [&](int cb, int buf) {
        const uint32_t Bd = Boff + buf * 21120;
        const __half* base = xp + ((size_t)(b * XP_H + h0) * XP_H) * CIN_T + cb * 32;
        for (int idx = tid; idx < 1056; idx += 256) {
            int r = idx / 264, rem = idx % 264;
            int c = rem >> 2, q = rem & 3;
            CP_ASYNC16(Bd + (r * 66 + c) * BPX + q * 16,
                       base + ((size_t)r * XP_H + c) * CIN_T + q * 8);
        }
    };

    stageB(0, 0);
    stageA(0, 0);
    CP_COMMIT();

    for (int s = 0; s < NS; s++) {
        const int cb = s / 3, kh = s % 3;
        if (s + 1 < NS) {
            stageA(s + 1, (s + 1) & 1);
            if ((s + 1) % 3 == 0) stageB((s + 1) / 3, ((s + 1) / 3) & 1);
            CP_COMMIT();
            CP_WAIT(1);
        } else {
            CP_WAIT(0);
        }
        __syncthreads();

        const uint32_t Bh = Boff + (cb & 1) * 21120;
        const char* Ap = smc + 2 * 21120 + (s & 1) * 24576;
#pragma unroll
        for (int ks = 0; ks < 2; ks++) {
#pragma unroll
            for (int kw = 0; kw < 3; kw++) {
                uint32_t afr[4][4];
#pragma unroll
                for (int mt = 0; mt < 4; mt++) {
                    uint4 v = *(const uint4*)(Ap + kw * 8192 +
                        ((((warp_m * 4 + mt) * 2 + ks) * 32 + lane) << 4));
                    afr[mt][0] = v.x; afr[mt][1] = v.y; afr[mt][2] = v.z; afr[mt][3] = v.w;
                }
                uint32_t bfr[2][4];
#pragma unroll
                for (int t16 = 0; t16 < 2; t16++) {
                    const int n_row = warp_n * 32 + t16 * 16 + (g >> 1) * 8 + (lane & 7);
                    const int r = n_row >> 6, w = n_row & 63;
                    ldsm4(bfr[t16], Bh + ((r + kh) * 66 + w + kw) * BPX
                                      + ks * 32 + (g & 1) * 16);
                }
#pragma unroll
                for (int mt = 0; mt < 4; mt++)
#pragma unroll
                    for (int t16 = 0; t16 < 2; t16++) {
                        mma_f16(acc[mt][2 * t16],     afr[mt], bfr[t16][0], bfr[t16][1]);
                        mma_f16(acc[mt][2 * t16 + 1], afr[mt], bfr[t16][2], bfr[t16][3]);
                    }
            }
        }
        __syncthreads();
    }

#pragma unroll
    for (int mt = 0; mt < 4; mt++) {
        const int co = warp_m * 64 + mt * 16 + (lane >> 2);
        const float sc0 = bn[co],     sh0 = bn[128 + co];
        const float sc8 = bn[co + 8], sh8 = bn[136 + co];
#pragma unroll
        for (int nt = 0; nt < 4; nt++) {
            const int px = pxbase + warp_n * 32 + nt * 8 + 2 * (lane & 3);
            float v0x = fmaxf(acc[mt][nt][0] * sc0 + sh0, 0.0f);
            float v0y = fmaxf(acc[mt][nt][1] * sc0 + sh0, 0.0f);
            float v1x = fmaxf(acc[mt][nt][2] * sc8 + sh8, 0.0f);
            float v1y = fmaxf(acc[mt][nt][3] * sc8 + sh8, 0.0f);
            *(uint32_t*)(o16 + ((size_t)b * 128 + co) * NPIX + px) = ph2(v0x, v0y);
            *(uint32_t*)(o16 + ((size_t)b * 128 + co + 8) * NPIX + px) = ph2(v1x, v1y);
            if (olo) {
                float r0x = v0x - __half2float(__float2half(v0x));
                float r0y = v0y - __half2float(__float2half(v0y));
                float r1x = v1x - __half2float(__float2half(v1x));
                float r1y = v1y - __half2float(__float2half(v1y));
                *(uint32_t*)(olo + ((size_t)b * 128 + co) * NPIX + px) = ph2(r0x, r0y);
                *(uint32_t*)(olo + ((size_t)b * 128 + co + 8) * NPIX + px) = ph2(r1x, r1y);
            }
        }
    }
}

// ---------------------------------------------------------------------------
// QKV GEMM: [Wd;Wb;Wc](160x128) @ y16(128x4096) + bias.
// ---------------------------------------------------------------------------
#define QKV_SMEM 59392

__global__ void __launch_bounds__(320, 1) qkv_kernel(
        const __half* __restrict__ wq, const __half* __restrict__ y16,
        const float* __restrict__ bd, const float* __restrict__ bb,
        const float* __restrict__ bc,
        __half* __restrict__ vh, __half* __restrict__ qh, __half* __restrict__ kh) {
    extern __shared__ __align__(16) char smc[];
    const uint32_t smb = smem_u32(smc);
    const int tid = threadIdx.x, lane = tid & 31, wid = tid >> 5;
    const int b = blockIdx.y;
    const int n0 = blockIdx.x * 64;
    const int g = lane >> 3;

#pragma unroll
    for (int t = 0; t < 8; t++) {
        int i = tid + t * 320;
        CP_ASYNC16(smb + i * 16, wq + i * 8);
    }
    for (int idx = tid; idx < 1024; idx += 320) {
        int ch = idx >> 3, seg = idx & 7;
        CP_ASYNC16(smb + 40960 + ch * 144 + seg * 16,
                   y16 + ((size_t)b * 128 + ch) * NPIX + n0 + seg * 8);
    }
    CP_COMMIT();
    CP_WAIT(0);
    __syncthreads();

    const int mt = wid;
    float acc[8][4];
#pragma unroll
    for (int nt = 0; nt < 8; nt++)
#pragma unroll
        for (int r = 0; r < 4; r++) acc[nt][r] = 0.0f;

    const char* Aptr = smc;
    const uint32_t Bsm = smb + 40960;
#pragma unroll
    for (int ks = 0; ks < 8; ks++) {
        uint4 v = *(const uint4*)(Aptr + (((mt * 8 + ks) * 32 + lane) << 4));
        uint32_t afr[4] = {v.x, v.y, v.z, v.w};
#pragma unroll
        for (int t16 = 0; t16 < 4; t16++) {
            uint32_t bfr[4];
            ldsm4t(bfr, Bsm + (ks * 16 + (g & 1) * 8 + (lane & 7)) * 144
                       + (t16 * 16 + (g >> 1) * 8) * 2);
            mma_f16(acc[2 * t16],     afr, bfr[0], bfr[1]);
            mma_f16(acc[2 * t16 + 1], afr, bfr[2], bfr[3]);
        }
    }

    const int r0 = mt * 16 + (lane >> 2);
    if (mt < 8) {
        const float b0 = bd[r0], b8 = bd[r0 + 8];
        __half* v0 = vh + ((size_t)b * 128 + r0) * NPIX;
        __half* v8 = vh + ((size_t)b * 128 + r0 + 8) * NPIX;
#pragma unroll
        for (int nt = 0; nt < 8; nt++) {
            const int n = n0 + nt * 8 + 2 * (lane & 3);
            *(uint32_t*)(v0 + n) = ph2(acc[nt][0] + b0, acc[nt][1] + b0);
            *(uint32_t*)(v8 + n) = ph2(acc[nt][2] + b8, acc[nt][3] + b8);
        }
    } else {
        const bool isq = (mt == 8);
        const float* bias = isq ? bb : bc;
        __half* dst = isq ? qh : kh;
        const int d = lane >> 2;
        const float b0 = bias[d], b8 = bias[d + 8];
#pragma unroll
        for (int nt = 0; nt < 8; nt++) {
            const int n = n0 + nt * 8 + 2 * (lane & 3);
            __half* p0 = dst + ((size_t)b * NPIX + n) * 16;
            p0[d]      = __float2half(acc[nt][0] + b0);
            p0[16 + d] = __float2half(acc[nt][1] + b0);
            p0[d + 8]      = __float2half(acc[nt][2] + b8);
            p0[16 + d + 8] = __float2half(acc[nt][3] + b8);
        }
    }
}

// ---------------------------------------------------------------------------
// PAM flash attention: q-tile 64, 128-thread CTA, occ 3.  Residual from hi+lo.
// ---------------------------------------------------------------------------
#define ATT_SMEM 46080

__global__ void __launch_bounds__(128, 3) pam_attn_mma(
        const __half* __restrict__ qh, const __half* __restrict__ kh,
        const __half* __restrict__ vd,
        const __half* __restrict__ yhi, const __half* __restrict__ ylo,
        const float* __restrict__ alpha, __half* __restrict__ xp2) {
    extern __shared__ __align__(16) char smc[];
    const uint32_t smb = smem_u32(smc);
    const uint32_t Qb  = smb;
    const uint32_t Kb0 = smb + 3072;
    const uint32_t Vb0 = smb + 9216;

    const int tid = threadIdx.x, lane = tid & 31, wid = tid >> 5;
    const int b = blockIdx.y;
    const int n0 = blockIdx.x * 64;
    const int qbase = wid * 16;

    const int g = lane >> 3, r8 = lane & 7;
    const uint32_t qoff = (uint32_t)(((g & 1) * 8 + r8) * 48 + (g >> 1) * 16);
    const uint32_t koff = (uint32_t)(((g >> 1) * 8 + r8) * 48 + (g & 1) * 16);
    const uint32_t voff = (uint32_t)(((g >> 1) * 8 + r8) * 144 + (g & 1) * 16);

    auto stageKV = [&](int t, int buf) {
        const int k0 = t * 64;
        {
            int row = tid >> 1, h = tid & 1;
            CP_ASYNC16(Kb0 + buf * 3072 + row * 48 + h * 16,
                       kh + ((size_t)b * NPIX + k0 + row) * 16 + h * 8);
        }
#pragma unroll
        for (int t4 = 0; t4 < 8; t4++) {
            int idx = tid + t4 * 128;
            int ch = idx >> 3, c = idx & 7;
            CP_ASYNC16(Vb0 + buf * 18432 + ch * 144 + c * 16,
                       vd + ((size_t)b * 128 + ch) * NPIX + k0 + c * 8);
        }
        CP_COMMIT();
    };

    {
        int row = tid >> 1, h = tid & 1;
        CP_ASYNC16(Qb + row * 48 + h * 16,
                   qh + ((size_t)b * NPIX + n0 + row) * 16 + h * 8);
    }
    stageKV(0, 0);

    uint32_t qfr[4];
    float O[16][4];
#pragma unroll
    for (int nc = 0; nc < 16; nc++)
#pragma unroll
        for (int r = 0; r < 4; r++) O[nc][r] = 0.0f;
    float mrun0 = -1e30f, mrun1 = -1e30f, lrun0 = 0.0f, lrun1 = 0.0f;

    for (int t = 0; t < 64; t++) {
        const int buf = t & 1;
        CP_WAIT(0);
        __syncthreads();
        if (t + 1 < 64) stageKV(t + 1, buf ^ 1);
        if (t == 0) ldsm4(qfr, Qb + qbase * 48 + qoff);

        const uint32_t Kb = Kb0 + buf * 3072;
        const uint32_t Vb = Vb0 + buf * 18432;

        float S[8][4];
#pragma unroll
        for (int ks = 0; ks < 4; ks++) {
            uint32_t kb[4];
            ldsm4(kb, Kb + ks * 768 + koff);
#pragma unroll
            for (int r = 0; r < 4; r++) { S[2 * ks][r] = 0.0f; S[2 * ks + 1][r] = 0.0f; }
            mma_f16(S[2 * ks],     qfr, kb[0], kb[1]);
            mma_f16(S[2 * ks + 1], qfr, kb[2], kb[3]);
        }

        float tm0 = -1e30f, tm1 = -1e30f;
#pragma unroll
        for (int nt = 0; nt < 8; nt++) {
            tm0 = fmaxf(tm0, fmaxf(S[nt][0], S[nt][1]));
            tm1 = fmaxf(tm1, fmaxf(S[nt][2], S[nt][3]));
        }
        tm0 = fmaxf(tm0, __shfl_xor_sync(0xffffffffu, tm0, 1));
        tm0 = fmaxf(tm0, __shfl_xor_sync(0xffffffffu, tm0, 2));
        tm1 = fmaxf(tm1, __shfl_xor_sync(0xffffffffu, tm1, 1));
        tm1 = fmaxf(tm1, __shfl_xor_sync(0xffffffffu, tm1, 2));
        const float mn0 = fmaxf(mrun0, tm0), mn1 = fmaxf(mrun1, tm1);
        const float f0 = __expf(mrun0 - mn0), f1 = __expf(mrun1 - mn1);
        mrun0 = mn0; mrun1 = mn1;

        float ts0 = 0.0f, ts1 = 0.0f;
        uint32_t afr[4][4];
#pragma unroll
        for (int j = 0; j < 4; j++) {
            float p00 = __expf(S[2 * j][0] - mn0), p01 = __expf(S[2 * j][1] - mn0);
            float p10 = __expf(S[2 * j][2] - mn1), p11 = __expf(S[2 * j][3] - mn1);
            float q00 = __expf(S[2 * j + 1][0] - mn0), q01 = __expf(S[2 * j + 1][1] - mn0);
            float q10 = __expf(S[2 * j + 1][2] - mn1), q11 = __expf(S[2 * j + 1][3] - mn1);
            ts0 += (p00 + p01) + (q00 + q01);
            ts1 += (p10 + p11) + (q10 + q11);
            afr[j][0] = ph2(p00, p01);
            afr[j][1] = ph2(p10, p11);
            afr[j][2] = ph2(q00, q01);
            afr[j][3] = ph2(q10, q11);
        }
        ts0 += __shfl_xor_sync(0xffffffffu, ts0, 1);
        ts0 += __shfl_xor_sync(0xffffffffu, ts0, 2);
        ts1 += __shfl_xor_sync(0xffffffffu, ts1, 1);
        ts1 += __shfl_xor_sync(0xffffffffu, ts1, 2);
        lrun0 = lrun0 * f0 + ts0;
        lrun1 = lrun1 * f1 + ts1;

#pragma unroll
        for (int nc = 0; nc < 16; nc++) {
            O[nc][0] *= f0; O[nc][1] *= f0;
            O[nc][2] *= f1; O[nc][3] *= f1;
        }

#pragma unroll
        for (int j = 0; j < 4; j++) {
            const uint32_t vb_j = Vb + j * 32 + voff;
#pragma unroll
            for (int p = 0; p < 8; p++) {
                uint32_t vb[4];
                ldsm4(vb, vb_j + p * 2304);
                mma_f16(O[2 * p],     afr[j], vb[0], vb[1]);
                mma_f16(O[2 * p + 1], afr[j], vb[2], vb[3]);
            }
        }
    }

    const float linv0 = 1.0f / lrun0, linv1 = 1.0f / lrun1;
    const float a = alpha[0];
    const int px0 = n0 + qbase + (lane >> 2);
    const int px1 = px0 + 8;
    __half* dst0 = xp2 + (((size_t)b * XP_H + (px0 >> 6) + 1) * XP_H + (px0 & 63) + 1) * CI;
    __half* dst1 = xp2 + (((size_t)b * XP_H + (px1 >> 6) + 1) * XP_H + (px1 & 63) + 1) * CI;
#pragma unroll
    for (int nc = 0; nc < 16; nc++) {
        const int ch = nc * 8 + 2 * (lane & 3);
        const __half* hp = yhi + ((size_t)b * 128 + ch) * NPIX;
        const __half* lp = ylo + ((size_t)b * 128 + ch) * NPIX;
        float ya0 = __half2float(hp[px0]) + __half2float(lp[px0]);
        float yb0 = __half2float(hp[NPIX + px0]) + __half2float(lp[NPIX + px0]);
        float ya1 = __half2float(hp[px1]) + __half2float(lp[px1]);
        float yb1 = __half2float(hp[NPIX + px1]) + __half2float(lp[NPIX + px1]);
        *(uint32_t*)(dst0 + ch) = ph2(fmaf(a, O[nc][0] * linv0, ya0),
                                      fmaf(a, O[nc][1] * linv0, yb0));
        *(uint32_t*)(dst1 + ch) = ph2(fmaf(a, O[nc][2] * linv1, ya1),
                                      fmaf(a, O[nc][3] * linv1, yb1));
    }
}

// ---------------------------------------------------------------------------
// CAM gram matrix via fp16 hi/lo split MMA (~f32 accurate), split-K partials.
// ---------------------------------------------------------------------------
#define CAME_SMEM 36864

__global__ void __launch_bounds__(256, 2) cam_energy_mma(
        const __half* __restrict__ yhi, const __half* __restrict__ ylo,
        float* __restrict__ epart) {
    extern __shared__ __align__(16) char smc[];
    const uint32_t smb = smem_u32(smc);
    const int tid = threadIdx.x, lane = tid & 31, wid = tid >> 5;
    const int warp_m = wid >> 2, warp_n = wid & 3;
    const int b = blockIdx.y, ksid = blockIdx.x;
    const int g = lane >> 3, r8 = lane & 7;

    float acc[4][4][4];
#pragma unroll
    for (int mt = 0; mt < 4; mt++)
#pragma unroll
        for (int nt = 0; nt < 4; nt++)
#pragma unroll
            for (int r = 0; r < 4; r++) acc[mt][nt][r] = 0.0f;

    for (int chunk = 0; chunk < 4; chunk++) {
        const int k0 = ksid * 256 + chunk * 64;
        __syncthreads();
#pragma unroll
        for (int t = 0; t < 4; t++) {
            int idx = tid + t * 256;
            int ch = idx >> 3, seg = idx & 7;
            CP_ASYNC16(smb + ch * 144 + seg * 16,
                       yhi + ((size_t)b * 128 + ch) * NPIX + k0 + seg * 8);
            CP_ASYNC16(smb + 18432 + ch * 144 + seg * 16,
                       ylo + ((size_t)b * 128 + ch) * NPIX + k0 + seg * 8);
        }
        CP_COMMIT();
        CP_WAIT(0);
        __syncthreads();

#pragma unroll
        for (int ks = 0; ks < 4; ks++) {
            uint32_t ahi[4][4], alo[4][4];
#pragma unroll
            for (int mt = 0; mt < 4; mt++) {
                const uint32_t arow = (warp_m * 64 + mt * 16 + (g & 1) * 8 + r8) * 144
                                      + ks * 32 + (g >> 1) * 16;
                ldsm4(ahi[mt], smb + arow);
                ldsm4(alo[mt], smb + 18432 + arow);
            }
            uint32_t bhi[2][4], blo[2][4];
#pragma unroll
            for (int t16 = 0; t16 < 2; t16++) {
                const uint32_t brow = (warp_n * 32 + t16 * 16 + (g >> 1) * 8 + r8) * 144
                                      + ks * 32 + (g & 1) * 16;
                ldsm4(bhi[t16], smb + brow);
                ldsm4(blo[t16], smb + 18432 + brow);
            }
#pragma unroll
            for (int mt = 0; mt < 4; mt++)
#pragma unroll
                for (int t16 = 0; t16 < 2; t16++) {
                    mma_f16(acc[mt][2 * t16],     ahi[mt], bhi[t16][0], bhi[t16][1]);
                    mma_f16(acc[mt][2 * t16 + 1], ahi[mt], bhi[t16][2], bhi[t16][3]);
                    mma_f16(acc[mt][2 * t16],     ahi[mt], blo[t16][0], blo[t16][1]);
                    mma_f16(acc[mt][2 * t16 + 1], ahi[mt], blo[t16][2], blo[t16][3]);
                    mma_f16(acc[mt][2 * t16],     alo[mt], bhi[t16][0], bhi[t16][1]);
                    mma_f16(acc[mt][2 * t16 + 1], alo[mt], bhi[t16][2], bhi[t16][3]);
                }
        }
    }

    float* ep = epart + (((size_t)ksid * BATCH + b) * 128) * 128;
#pragma unroll
    for (int mt = 0; mt < 4; mt++) {
        const int c0 = warp_m * 64 + mt * 16 + (lane >> 2);
#pragma unroll
        for (int nt = 0; nt < 4; nt++) {
            const int d = warp_n * 32 + nt * 8 + 2 * (lane & 3);
            *(float2*)(ep + (size_t)c0 * 128 + d) = make_float2(acc[mt][nt][0], acc[mt][nt][1]);
            *(float2*)(ep + (size_t)(c0 + 8) * 128 + d) = make_float2(acc[mt][nt][2], acc[mt][nt][3]);
        }
    }
}

// ---------------------------------------------------------------------------
// CAM softmax of (rowmax - E), reducing the KSPLIT partials -> fp16 attn
// ---------------------------------------------------------------------------
__global__ void cam_softmax_kernel(const float* __restrict__ epart,
                                   __half* __restrict__ attn) {
    const int row = blockIdx.x;
    const int tid = threadIdx.x;
    __shared__ float red[4];

    float e = 0.0f;
#pragma unroll
    for (int s = 0; s < KSPLIT; s++)
        e += epart[((size_t)s * 1024 + row) * 128 + tid];

    float m = e;
#pragma unroll
    for (int off = 16; off; off >>= 1) m = fmaxf(m, __shfl_xor_sync(0xffffffff, m, off));
    if ((tid & 31) == 0) red[tid >> 5] = m;
    __syncthreads();
    float mx = fmaxf(fmaxf(red[0], red[1]), fmaxf(red[2], red[3]));
    float e2 = mx - e;
    __syncthreads();

    float m2 = e2;
#pragma unroll
    for (int off = 16; off; off >>= 1) m2 = fmaxf(m2, __shfl_xor_sync(0xffffffff, m2, off));
    if ((tid & 31) == 0) red[tid >> 5] = m2;
    __syncthreads();
    m2 = fmaxf(fmaxf(red[0], red[1]), fmaxf(red[2], red[3]));
    float p = __expf(e2 - m2);
    __syncthreads();

    float s = p;
#pragma unroll
    for (int off = 16; off; off >>= 1) s += __shfl_xor_sync(0xffffffff, s, off);
    if ((tid & 31) == 0) red[tid >> 5] = s;
    __syncthreads();
    s = red[0] + red[1] + red[2] + red[3];

    attn[(size_t)row * 128 + tid] = __float2half(p / s);
}

// ---------------------------------------------------------------------------
// CAM feature via fp16 MMA -> fp16 padded NHWC; residual from hi+lo.
// ---------------------------------------------------------------------------
#define CAMF_SMEM 53248

__global__ void __launch_bounds__(256, 1) cam_feat_mma(
        const __half* __restrict__ attn16,
        const __half* __restrict__ yhi, const __half* __restrict__ ylo,
        const float* __restrict__ beta, __half* __restrict__ xp2) {
    extern __shared__ __align__(16) char smc[];
    const uint32_t smb = smem_u32(smc);
    const int tid = threadIdx.x, lane = tid & 31, wid = tid >> 5;
    const int b = blockIdx.y;
    const int n0 = blockIdx.x * 64;
    const int g = lane >> 3;

#pragma unroll
    for (int t = 0; t < 8; t++) {
        int idx = tid + t * 256;
        int c = idx >> 4, seg = idx & 15;
        CP_ASYNC16(smb + c * 272 + seg * 16,
                   attn16 + ((size_t)b * 128 + c) * 128 + seg * 8);
    }
#pragma unroll
    for (int t = 0; t < 4; t++) {
        int idx = tid + t * 256;
        int ch = idx >> 3, seg = idx & 7;
        CP_ASYNC16(smb + 34816 + ch * 144 + seg * 16,
                   yhi + ((size_t)b * 128 + ch) * NPIX + n0 + seg * 8);
    }
    CP_COMMIT();
    CP_WAIT(0);
    __syncthreads();

    const int mt = wid;
    float acc[8][4];
#pragma unroll
    for (int nt = 0; nt < 8; nt++)
#pragma unroll
        for (int r = 0; r < 4; r++) acc[nt][r] = 0.0f;

    const uint32_t Bsm = smb + 34816;
#pragma unroll
    for (int ks = 0; ks < 8; ks++) {
        uint32_t afr[4];
        ldsm4(afr, smb + (mt * 16 + (g & 1) * 8 + (lane & 7)) * 272
                  + ks * 32 + (g >> 1) * 16);
#pragma unroll
        for (int t16 = 0; t16 < 4; t16++) {
            uint32_t bfr[4];
            ldsm4t(bfr, Bsm + (ks * 16 + (g & 1) * 8 + (lane & 7)) * 144
                       + (t16 * 16 + (g >> 1) * 8) * 2);
            mma_f16(acc[2 * t16],     afr, bfr[0], bfr[1]);
            mma_f16(acc[2 * t16 + 1], afr, bfr[2], bfr[3]);
        }
    }

    const float bet = beta[0];
    const int c0 = mt * 16 + (lane >> 2);
#pragma unroll
    for (int nt = 0; nt < 8; nt++) {
        const int n = n0 + nt * 8 + 2 * (lane & 3);
        const __half* h0p = yhi + ((size_t)b * 128 + c0) * NPIX;
        const __half* l0p = ylo + ((size_t)b * 128 + c0) * NPIX;
        float y00 = __half2float(h0p[n]) + __half2float(l0p[n]);
        float y01 = __half2float(h0p[n + 1]) + __half2float(l0p[n + 1]);
        float y80 = __half2float(h0p[8 * NPIX + n]) + __half2float(l0p[8 * NPIX + n]);
        float y81 = __half2float(h0p[8 * NPIX + n + 1]) + __half2float(l0p[8 * NPIX + n + 1]);
        __half* p0 = xp2 + (((size_t)b * XP_H + (n >> 6) + 1) * XP_H + (n & 63) + 1) * CI;
        __half* p1 = p0 + CI;
        p0[c0]     = __float2half(fmaf(bet, acc[nt][0], y00));
        p1[c0]     = __float2half(fmaf(bet, acc[nt][1], y01));
        p0[c0 + 8] = __float2half(fmaf(bet, acc[nt][2], y80));
        p1[c0 + 8] = __float2half(fmaf(bet, acc[nt][3], y81));
    }
}

// ---------------------------------------------------------------------------
// Final heads (fp16 inputs): three 1x1 convs (128->19) + sigmoid.
// ---------------------------------------------------------------------------
__global__ void final_kernel(const __half* __restrict__ fp,
                             const __half* __restrict__ fc,
                             const float* __restrict__ Wout, const float* __restrict__ bout,
                             const float* __restrict__ Wp3, const float* __restrict__ bp3,
                             const float* __restrict__ Wc3, const float* __restrict__ bc3,
                             float* __restrict__ out) {
    const int b  = blockIdx.y;
    const int px = blockIdx.x * 256 + threadIdx.x;

    __shared__ float Wo[19][128];
    __shared__ float Wp[19][128];
    __shared__ float Wc[19][128];
    for (int i = threadIdx.x; i < 19 * 128; i += 256) {
        Wo[i / 128][i % 128] = Wout[i];
        Wp[i / 128][i % 128] = Wp3[i];
        Wc[i / 128][i % 128] = Wc3[i];
    }
    __syncthreads();

    float am[19], ap[19], ac[19];
#pragma unroll
    for (int o = 0; o < 19; o++) { am[o] = bout[o]; ap[o] = bp3[o]; ac[o] = bc3[o]; }

    for (int c = 0; c < 128; c++) {
        float vp = __half2float(fp[((size_t)b * 128 + c) * NPIX + px]);
        float vc = __half2float(fc[((size_t)b * 128 + c) * NPIX + px]);
        float vf = vp + vc;
#pragma unroll
        for (int o = 0; o < 19; o++) {
            am[o] += Wo[o][c] * vf;
            ap[o] += Wp[o][c] * vp;
            ac[o] += Wc[o][c] * vc;
        }
    }

    const size_t SEG = (size_t)BATCH * NC * NPIX;
#pragma unroll
    for (int o = 0; o < 19; o++) {
        size_t base = ((size_t)b * NC + o) * NPIX + px;
        out[base]           = sigmoidf_(am[o]);
        out[SEG + base]     = sigmoidf_(ap[o]);
        out[2 * SEG + base] = sigmoidf_(ac[o]);
    }
}

// ---------------------------------------------------------------------------
// Streams / events (created once at program load)
// ---------------------------------------------------------------------------
namespace {
struct StreamInit {
    cudaStream_t s1;
    cudaEvent_t e0, e1, e2, e3;
    StreamInit() {
        cudaStreamCreateWithFlags(&s1, cudaStreamNonBlocking);
        cudaEventCreateWithFlags(&e0, cudaEventDisableTiming);
        cudaEventCreateWithFlags(&e1, cudaEventDisableTiming);
        cudaEventCreateWithFlags(&e2, cudaEventDisableTiming);
        cudaEventCreateWithFlags(&e3, cudaEventDisableTiming);
    }
};
StreamInit g_str;
}

// ---------------------------------------------------------------------------
// Launch
// ---------------------------------------------------------------------------
extern "C" void kernel_launch(void* const* d_in, const int* in_sizes, int n_in,
                              void* d_out, int out_size) {
    const float* x    = (const float*)d_in[0];
    const float* Wp1  = (const float*)d_in[1];
    const float* bnp1 = (const float*)d_in[2];
    const float* Wc1  = (const float*)d_in[3];
    const float* bnc1 = (const float*)d_in[4];
    const float* Wb   = (const float*)d_in[5];
    const float* bb   = (const float*)d_in[6];
    const float* Wc   = (const float*)d_in[7];
    const float* bc   = (const float*)d_in[8];
    const float* Wd   = (const float*)d_in[9];
    const float* bd   = (const float*)d_in[10];
    const float* alpha= (const float*)d_in[11];
    const float* beta = (const float*)d_in[12];
    const float* Wp2  = (const float*)d_in[13];
    const float* bnp2 = (const float*)d_in[14];
    const float* Wc2  = (const float*)d_in[15];
    const float* bnc2 = (const float*)d_in[16];
    const float* Wout = (const float*)d_in[17];
    const float* bout = (const float*)d_in[18];
    const float* Wp3  = (const float*)d_in[19];
    const float* bp3  = (const float*)d_in[20];
    const float* Wc3  = (const float*)d_in[21];
    const float* bc3  = (const float*)d_in[22];
    float* out = (float*)d_out;

    float* epart;
    __half *featp1h, *featp1lo, *featc1h, *featc1lo, *qh, *kh, *vd, *attn16;
    __half *xpad, *xp2a, *xp2b, *wf1, *wf2, *wqkv;
    cudaGetSymbolAddress((void**)&featp1h,  g_featp1h);
    cudaGetSymbolAddress((void**)&featp1lo, g_featp1lo);
    cudaGetSymbolAddress((void**)&featc1h,  g_featc1h);
    cudaGetSymbolAddress((void**)&featc1lo, g_featc1lo);
    cudaGetSymbolAddress((void**)&qh,       g_qh);
    cudaGetSymbolAddress((void**)&kh,       g_kh);
    cudaGetSymbolAddress((void**)&vd,       g_vd);
    cudaGetSymbolAddress((void**)&epart,    g_epart);
    cudaGetSymbolAddress((void**)&attn16,   g_attn16);
    cudaGetSymbolAddress((void**)&xpad,     g_xpad);
    cudaGetSymbolAddress((void**)&xp2a,     g_xp2a);
    cudaGetSymbolAddress((void**)&xp2b,     g_xp2b);
    cudaGetSymbolAddress((void**)&wf1,      g_wf16_1);
    cudaGetSymbolAddress((void**)&wf2,      g_wf16_2);
    cudaGetSymbolAddress((void**)&wqkv,     g_wqkv);

    cudaFuncSetAttribute(conv_mma_kernel<512>,
                         cudaFuncAttributeMaxDynamicSharedMemorySize, CONV_SMEM);
    cudaFuncSetAttribute(conv_mma_kernel<128>,
                         cudaFuncAttributeMaxDynamicSharedMemorySize, CONV_SMEM);
    cudaFuncSetAttribute(pam_attn_mma,
                         cudaFuncAttributeMaxDynamicSharedMemorySize, ATT_SMEM);
    cudaFuncSetAttribute(pam_attn_mma,
                         cudaFuncAttributePreferredSharedMemoryCarveout, 100);
    cudaFuncSetAttribute(qkv_kernel,
                         cudaFuncAttributeMaxDynamicSharedMemorySize, QKV_SMEM);
    cudaFuncSetAttribute(cam_energy_mma,
                         cudaFuncAttributeMaxDynamicSharedMemorySize, CAME_SMEM);
    cudaFuncSetAttribute(cam_feat_mma,
                         cudaFuncAttributeMaxDynamicSharedMemorySize, CAMF_SMEM);

    cudaStream_t s1 = g_str.s1;

    // Fork s1 off the main stream
    cudaEventRecord(g_str.e0, 0);
    cudaStreamWaitEvent(s1, g_str.e0, 0);

    // s0: input packing
    pack_x_kernel<<<dim3(64, BATCH), 256>>>(x, xpad);
    zero_border_h<<<dim3(XP_H, BATCH), 256>>>(xpad, CIN);

    // s1: weight packing + conv2-input border zeros (parallel with pack_x)
    pack_w16<<<dim3(144, 2), 256, 0, s1>>>(Wp1, Wc1, wf1, CIN);
    zero_border_h<<<dim3(XP_H, BATCH), 256, 0, s1>>>(xp2a, CI);
    zero_border_h<<<dim3(XP_H, BATCH), 256, 0, s1>>>(xp2b, CI);
    pack_wqkv<<<1, 256, 0, s1>>>(Wd, Wb, Wc, wqkv);
    cudaEventRecord(g_str.e1, s1);
    pack_w16<<<dim3(36, 2), 256, 0, s1>>>(Wp2, Wc2, wf2, CI);

    // s0: conv1 (both branches) after wf1/zeros ready
    cudaStreamWaitEvent(0, g_str.e1, 0);
    conv_mma_kernel<512><<<dim3(32, BATCH, 2), 256, CONV_SMEM>>>(
        xpad, xpad, wf1, bnp1, bnc1, featp1h, featc1h, featp1lo, featc1lo);
    cudaEventRecord(g_str.e2, 0);

    // s1: CAM chain (parallel with PAM on s0)
    cudaStreamWaitEvent(s1, g_str.e2, 0);
    cam_energy_mma<<<dim3(KSPLIT, BATCH), 256, CAME_SMEM, s1>>>(featc1h, featc1lo, epart);
    cam_softmax_kernel<<<BATCH * 128, 128, 0, s1>>>(epart, attn16);
    cam_feat_mma<<<dim3(64, BATCH), 256, CAMF_SMEM, s1>>>(
        attn16, featc1h, featc1lo, beta, xp2b);
    cudaEventRecord(g_str.e3, s1);

    // s0: PAM chain
    qkv_kernel<<<dim3(64, BATCH), 320, QKV_SMEM>>>(
        wqkv, featp1h, bd, bb, bc, vd, qh, kh);
    pam_attn_mma<<<dim3(64, BATCH), 128, ATT_SMEM>>>(
        qh, kh, vd, featp1h, featp1lo, alpha, xp2a);

    // Join, then conv2 + heads
    cudaStreamWaitEvent(0, g_str.e3, 0);
    conv_mma_kernel<128><<<dim3(32, BATCH, 2), 256, CONV_SMEM>>>(
        xp2a, xp2b, wf2, bnp2, bnc2, featp1h, featc1h, nullptr, nullptr);
    final_kernel<<<dim3(16, BATCH), 256>>>(featp1h, featc1h,
                                           Wout, bout, Wp3, bp3, Wc3, bc3, out);
}

// round 10
// speedup vs baseline: 12.7899x; 1.0802x over previous
#include <cuda_runtime.h>
#include <cuda_bf16.h>
#include <cuda_fp16.h>
#include <math.h>
#include <cstdint>

// ---------------------------------------------------------------------------
// Problem constants
// ---------------------------------------------------------------------------
#define BATCH 8
#define CIN   512
#define CI    128
#define CK    16
#define NC    19
#define NPIX  4096
#define FEAT_ELEMS (BATCH * CI * NPIX)
#define XP_H 66
#define KSPLIT 16

// ---------------------------------------------------------------------------
// Scratch (device globals)
// ---------------------------------------------------------------------------
__device__ __half g_featp1h[FEAT_ELEMS];     // conv1-p hi; later conv2-p out
__device__ __half g_featp1lo[FEAT_ELEMS];    // conv1-p lo residual
__device__ __half g_featc1h[FEAT_ELEMS];     // conv1-c hi; later conv2-c out
__device__ __half g_featc1lo[FEAT_ELEMS];    // conv1-c lo residual
__device__ __half g_qh[BATCH * NPIX * CK];
__device__ __half g_kh[BATCH * NPIX * CK];
__device__ __half g_vd[FEAT_ELEMS];
__device__ float  g_epart[KSPLIT * BATCH * CI * CI];
__device__ __half g_attn16[BATCH * CI * CI];
__device__ __half g_xpad[BATCH * XP_H * XP_H * CIN];
__device__ __half g_xp2a[BATCH * XP_H * XP_H * CI];
__device__ __half g_xp2b[BATCH * XP_H * XP_H * CI];
__device__ __half g_wf16_1[2 * 144 * 4096];
__device__ __half g_wf16_2[2 * 36 * 4096];
__device__ __half g_wqkv[10 * 8 * 32 * 8];
__device__ __half g_wfinal[4 * 16 * 32 * 8];   // [64 rows x 256 k] frag-packed

__device__ __forceinline__ float sigmoidf_(float x) {
    return 1.0f / (1.0f + __expf(-x));
}
__device__ __forceinline__ uint32_t smem_u32(const void* p) {
    uint32_t a;
    asm("{ .reg .u64 t; cvta.to.shared.u64 t, %1; cvt.u32.u64 %0, t; }" : "=r"(a) : "l"(p));
    return a;
}
__device__ __forceinline__ void mma_f16(float c[4], const uint32_t a[4], const uint32_t b0, const uint32_t b1) {
    asm volatile(
        "mma.sync.aligned.m16n8k16.row.col.f32.f16.f16.f32 "
        "{%0,%1,%2,%3}, {%4,%5,%6,%7}, {%8,%9}, {%0,%1,%2,%3};"
        : "+f"(c[0]), "+f"(c[1]), "+f"(c[2]), "+f"(c[3])
        : "r"(a[0]), "r"(a[1]), "r"(a[2]), "r"(a[3]), "r"(b0), "r"(b1));
}
__device__ __forceinline__ void ldsm4(uint32_t r[4], uint32_t addr) {
    asm volatile("ldmatrix.sync.aligned.m8n8.x4.shared.b16 {%0,%1,%2,%3}, [%4];"
                 : "=r"(r[0]), "=r"(r[1]), "=r"(r[2]), "=r"(r[3]) : "r"(addr));
}
__device__ __forceinline__ void ldsm4t(uint32_t r[4], uint32_t addr) {
    asm volatile("ldmatrix.sync.aligned.m8n8.x4.trans.shared.b16 {%0,%1,%2,%3}, [%4];"
                 : "=r"(r[0]), "=r"(r[1]), "=r"(r[2]), "=r"(r[3]) : "r"(addr));
}
#define CP_ASYNC16(dst, src) \
    asm volatile("cp.async.ca.shared.global [%0], [%1], 16;" :: "r"(dst), "l"(src))
#define CP_COMMIT() asm volatile("cp.async.commit_group;")
#define CP_WAIT(N)  asm volatile("cp.async.wait_group %0;" :: "n"(N))

__device__ __forceinline__ uint32_t ph2(float x, float y) {
    __half2 h = __floats2half2_rn(x, y);
    return *(uint32_t*)&h;
}

// ---------------------------------------------------------------------------
// Pack x: f32 NCHW -> fp16 NHWC padded
// ---------------------------------------------------------------------------
__global__ void pack_x_kernel(const float* __restrict__ x, __half* __restrict__ xp) {
    const int h = blockIdx.x, b = blockIdx.y, tid = threadIdx.x;
    __shared__ float s[32][65];
    for (int ci0 = 0; ci0 < CIN; ci0 += 32) {
        for (int idx = tid; idx < 32 * 64; idx += 256) {
            int ci_l = idx >> 6, w = idx & 63;
            s[ci_l][w] = x[(((size_t)b * CIN + ci0 + ci_l) * 64 + h) * 64 + w];
        }
        __syncthreads();
        for (int idx = tid; idx < 64 * 32; idx += 256) {
            int w = idx >> 5, ci_l = idx & 31;
            xp[(((size_t)b * XP_H + h + 1) * XP_H + w + 1) * CIN + ci0 + ci_l] =
                __float2half(s[ci_l][w]);
        }
        __syncthreads();
    }
}

__global__ void zero_border_h(__half* __restrict__ xp, int C) {
    const int hp = blockIdx.x, b = blockIdx.y, tid = threadIdx.x;
    __half* row = xp + ((size_t)b * XP_H + hp) * XP_H * C;
    const __half z = __float2half(0.0f);
    if (hp == 0 || hp == XP_H - 1) {
        for (int idx = tid; idx < XP_H * C; idx += 256) row[idx] = z;
    } else {
        for (int idx = tid; idx < C; idx += 256) {
            row[idx] = z;
            row[(size_t)(XP_H - 1) * C + idx] = z;
        }
    }
}

// ---------------------------------------------------------------------------
// Pack conv weights into m16n8k16 fp16 A-fragment order.
// ---------------------------------------------------------------------------
__global__ void pack_w16(const float* __restrict__ W0, const float* __restrict__ W1,
                         __half* __restrict__ wf, int CIN_T) {
    const int cpc = CIN_T / 32;
    const int chunk = blockIdx.x;
    const int kwh = chunk / cpc, cb = chunk % cpc;
    const float* W = blockIdx.y ? W1 : W0;
    __half* dst = wf + ((size_t)blockIdx.y * gridDim.x + chunk) * 4096;
    for (int t = 0; t < 16; t++) {
        int idx = threadIdx.x + t * 256;
        int j = idx & 7, lane = (idx >> 3) & 31, ks = (idx >> 8) & 1, mt = idx >> 9;
        int reg = j >> 1, h = j & 1;
        int co = mt * 16 + (lane >> 2) + (reg & 1) * 8;
        int ci = cb * 32 + ks * 16 + (lane & 3) * 2 + (reg >> 1) * 8 + h;
        dst[idx] = __float2half(W[((size_t)co * CIN_T + ci) * 9 + kwh]);
    }
}

__global__ void pack_wqkv(const float* __restrict__ Wd, const float* __restrict__ Wb,
                          const float* __restrict__ Wc, __half* __restrict__ dst) {
    for (int idx = threadIdx.x; idx < 20480; idx += 256) {
        int j = idx & 7, lane = (idx >> 3) & 31, ks = (idx >> 8) & 7, mt = idx >> 11;
        int reg = j >> 1, h = j & 1;
        int row = mt * 16 + (lane >> 2) + (reg & 1) * 8;
        int col = ks * 16 + (lane & 3) * 2 + (reg >> 1) * 8 + h;
        float w;
        if (row < 128)      w = Wd[row * 128 + col];
        else if (row < 144) w = Wb[(row - 128) * 128 + col];
        else                w = Wc[(row - 144) * 128 + col];
        dst[idx] = __float2half(w);
    }
}

// Pack the fused final-head weight block matrix [64 x 256]:
//   rows 0-18:  [Wout | Wout]   rows 19-37: [Wp3 | 0]   rows 38-56: [0 | Wc3]
__global__ void pack_wfinal(const float* __restrict__ Wout, const float* __restrict__ Wp3,
                            const float* __restrict__ Wc3, __half* __restrict__ dst) {
    for (int idx = threadIdx.x; idx < 16384; idx += 256) {
        int j = idx & 7, lane = (idx >> 3) & 31, ks = (idx >> 8) & 15, mt = idx >> 12;
        int reg = j >> 1, h = j & 1;
        int row = mt * 16 + (lane >> 2) + (reg & 1) * 8;
        int col = ks * 16 + (lane & 3) * 2 + (reg >> 1) * 8 + h;
        float w = 0.0f;
        if (col < 128) {
            if (row < 19)      w = Wout[row * 128 + col];
            else if (row < 38) w = Wp3[(row - 19) * 128 + col];
        } else {
            int c = col - 128;
            if (row < 19)      w = Wout[row * 128 + c];
            else if (row >= 38 && row < 57) w = Wc3[(row - 38) * 128 + c];
        }
        dst[idx] = __float2half(w);
    }
}

// ---------------------------------------------------------------------------
// conv3x3 implicit GEMM, fp16 m16n8k16, halo-reuse B staging, fused BN+ReLU.
// smem: B 2x21120 @0; A 2x24576 @42240.  Total 91392.  Pixel stride 80B.
// ---------------------------------------------------------------------------
#define CONV_SMEM 91392
#define BPX 80

template<int CIN_T>
__global__ void __launch_bounds__(256, 2) conv_mma_kernel(
        const __half* __restrict__ xpA, const __half* __restrict__ xpB,
        const __half* __restrict__ wfrag,
        const float* __restrict__ bn0, const float* __restrict__ bn1,
        __half* __restrict__ o16_0, __half* __restrict__ o16_1,
        __half* __restrict__ olo_0, __half* __restrict__ olo_1) {
    constexpr int CPC = CIN_T / 32;
    constexpr int NS = CPC * 3;
    extern __shared__ __align__(16) char smc[];
    const uint32_t smb = smem_u32(smc);
    const uint32_t Boff = smb;
    const uint32_t Aoff = smb + 2 * 21120;

    const int tid = threadIdx.x, lane = tid & 31, wid = tid >> 5;
    const int warp_m = wid >> 2, warp_n = wid & 3;
    const int b = blockIdx.y, z = blockIdx.z;
    const int pxbase = blockIdx.x * 128;
    const int h0 = pxbase >> 6;
    const __half* xp = z ? xpB : xpA;
    const __half* Wf = wfrag + (size_t)z * (9 * CPC) * 4096;
    const float* bn = z ? bn1 : bn0;
    __half* o16 = z ? o16_1 : o16_0;
    __half* olo = z ? olo_1 : olo_0;
    const int g = lane >> 3;

    float acc[4][4][4];
#pragma unroll
    for (int mt = 0; mt < 4; mt++)
#pragma unroll
        for (int nt = 0; nt < 4; nt++)
#pragma unroll
            for (int r = 0; r < 4; r++) acc[mt][nt][r] = 0.0f;

    auto stageA = [&](int s, int buf) {
        const int cb = s / 3, kh = s % 3;
        const uint32_t Ad = Aoff + buf * 24576;
#pragma unroll
        for (int kw = 0; kw < 3; kw++) {
            const __half* src = Wf + (size_t)((kh * 3 + kw) * CPC + cb) * 4096;
#pragma unroll
            for (int t = 0; t < 2; t++) {
                int idx = tid + t * 256;
                CP_ASYNC16(Ad + kw * 8192 + idx * 16, src + idx * 8);
            }
        }
    };
    auto stageB = [&](int cb, int buf) {
        const uint32_t Bd = Boff + buf * 21120;
        const __half* base = xp + ((size_t)(b * XP_H + h0) * XP_H) * CIN_T + cb * 32;
        for (int idx = tid; idx < 1056; idx += 256) {
            int r = idx / 264, rem = idx % 264;
            int c = rem >> 2, q = rem & 3;
            CP_ASYNC16(Bd + (r * 66 + c) * BPX + q * 16,
                       base + ((size_t)r * XP_H + c) * CIN_T + q * 8);
        }
    };

    stageB(0, 0);
    stageA(0, 0);
    CP_COMMIT();

    for (int s = 0; s < NS; s++) {
        const int cb = s / 3, kh = s % 3;
        if (s + 1 < NS) {
            stageA(s + 1, (s + 1) & 1);
            if ((s + 1) % 3 == 0) stageB((s + 1) / 3, ((s + 1) / 3) & 1);
            CP_COMMIT();
            CP_WAIT(1);
        } else {
            CP_WAIT(0);
        }
        __syncthreads();

        const uint32_t Bh = Boff + (cb & 1) * 21120;
        const char* Ap = smc + 2 * 21120 + (s & 1) * 24576;
#pragma unroll
        for (int ks = 0; ks < 2; ks++) {
#pragma unroll
            for (int kw = 0; kw < 3; kw++) {
                uint32_t afr[4][4];
#pragma unroll
                for (int mt = 0; mt < 4; mt++) {
                    uint4 v = *(const uint4*)(Ap + kw * 8192 +
                        ((((warp_m * 4 + mt) * 2 + ks) * 32 + lane) << 4));
                    afr[mt][0] = v.x; afr[mt][1] = v.y; afr[mt][2] = v.z; afr[mt][3] = v.w;
                }
                uint32_t bfr[2][4];
#pragma unroll
                for (int t16 = 0; t16 < 2; t16++) {
                    const int n_row = warp_n * 32 + t16 * 16 + (g >> 1) * 8 + (lane & 7);
                    const int r = n_row >> 6, w = n_row & 63;
                    ldsm4(bfr[t16], Bh + ((r + kh) * 66 + w + kw) * BPX
                                      + ks * 32 + (g & 1) * 16);
                }
#pragma unroll
                for (int mt = 0; mt < 4; mt++)
#pragma unroll
                    for (int t16 = 0; t16 < 2; t16++) {
                        mma_f16(acc[mt][2 * t16],     afr[mt], bfr[t16][0], bfr[t16][1]);
                        mma_f16(acc[mt][2 * t16 + 1], afr[mt], bfr[t16][2], bfr[t16][3]);
                    }
            }
        }
        __syncthreads();
    }

#pragma unroll
    for (int mt = 0; mt < 4; mt++) {
        const int co = warp_m * 64 + mt * 16 + (lane >> 2);
        const float sc0 = bn[co],     sh0 = bn[128 + co];
        const float sc8 = bn[co + 8], sh8 = bn[136 + co];
#pragma unroll
        for (int nt = 0; nt < 4; nt++) {
            const int px = pxbase + warp_n * 32 + nt * 8 + 2 * (lane & 3);
            float v0x = fmaxf(acc[mt][nt][0] * sc0 + sh0, 0.0f);
            float v0y = fmaxf(acc[mt][nt][1] * sc0 + sh0, 0.0f);
            float v1x = fmaxf(acc[mt][nt][2] * sc8 + sh8, 0.0f);
            float v1y = fmaxf(acc[mt][nt][3] * sc8 + sh8, 0.0f);
            *(uint32_t*)(o16 + ((size_t)b * 128 + co) * NPIX + px) = ph2(v0x, v0y);
            *(uint32_t*)(o16 + ((size_t)b * 128 + co + 8) * NPIX + px) = ph2(v1x, v1y);
            if (olo) {
                float r0x = v0x - __half2float(__float2half(v0x));
                float r0y = v0y - __half2float(__float2half(v0y));
                float r1x = v1x - __half2float(__float2half(v1x));
                float r1y = v1y - __half2float(__float2half(v1y));
                *(uint32_t*)(olo + ((size_t)b * 128 + co) * NPIX + px) = ph2(r0x, r0y);
                *(uint32_t*)(olo + ((size_t)b * 128 + co + 8) * NPIX + px) = ph2(r1x, r1y);
            }
        }
    }
}

// ---------------------------------------------------------------------------
// QKV GEMM: [Wd;Wb;Wc](160x128) @ y16(128x4096) + bias.
// ---------------------------------------------------------------------------
#define QKV_SMEM 59392

__global__ void __launch_bounds__(320, 1) qkv_kernel(
        const __half* __restrict__ wq, const __half* __restrict__ y16,
        const float* __restrict__ bd, const float* __restrict__ bb,
        const float* __restrict__ bc,
        __half* __restrict__ vh, __half* __restrict__ qh, __half* __restrict__ kh) {
    extern __shared__ __align__(16) char smc[];
    const uint32_t smb = smem_u32(smc);
    const int tid = threadIdx.x, lane = tid & 31, wid = tid >> 5;
    const int b = blockIdx.y;
    const int n0 = blockIdx.x * 64;
    const int g = lane >> 3;

#pragma unroll
    for (int t = 0; t < 8; t++) {
        int i = tid + t * 320;
        CP_ASYNC16(smb + i * 16, wq + i * 8);
    }
    for (int idx = tid; idx < 1024; idx += 320) {
        int ch = idx >> 3, seg = idx & 7;
        CP_ASYNC16(smb + 40960 + ch * 144 + seg * 16,
                   y16 + ((size_t)b * 128 + ch) * NPIX + n0 + seg * 8);
    }
    CP_COMMIT();
    CP_WAIT(0);
    __syncthreads();

    const int mt = wid;
    float acc[8][4];
#pragma unroll
    for (int nt = 0; nt < 8; nt++)
#pragma unroll
        for (int r = 0; r < 4; r++) acc[nt][r] = 0.0f;

    const char* Aptr = smc;
    const uint32_t Bsm = smb + 40960;
#pragma unroll
    for (int ks = 0; ks < 8; ks++) {
        uint4 v = *(const uint4*)(Aptr + (((mt * 8 + ks) * 32 + lane) << 4));
        uint32_t afr[4] = {v.x, v.y, v.z, v.w};
#pragma unroll
        for (int t16 = 0; t16 < 4; t16++) {
            uint32_t bfr[4];
            ldsm4t(bfr, Bsm + (ks * 16 + (g & 1) * 8 + (lane & 7)) * 144
                       + (t16 * 16 + (g >> 1) * 8) * 2);
            mma_f16(acc[2 * t16],     afr, bfr[0], bfr[1]);
            mma_f16(acc[2 * t16 + 1], afr, bfr[2], bfr[3]);
        }
    }

    const int r0 = mt * 16 + (lane >> 2);
    if (mt < 8) {
        const float b0 = bd[r0], b8 = bd[r0 + 8];
        __half* v0 = vh + ((size_t)b * 128 + r0) * NPIX;
        __half* v8 = vh + ((size_t)b * 128 + r0 + 8) * NPIX;
#pragma unroll
        for (int nt = 0; nt < 8; nt++) {
            const int n = n0 + nt * 8 + 2 * (lane & 3);
            *(uint32_t*)(v0 + n) = ph2(acc[nt][0] + b0, acc[nt][1] + b0);
            *(uint32_t*)(v8 + n) = ph2(acc[nt][2] + b8, acc[nt][3] + b8);
        }
    } else {
        const bool isq = (mt == 8);
        const float* bias = isq ? bb : bc;
        __half* dst = isq ? qh : kh;
        const int d = lane >> 2;
        const float b0 = bias[d], b8 = bias[d + 8];
#pragma unroll
        for (int nt = 0; nt < 8; nt++) {
            const int n = n0 + nt * 8 + 2 * (lane & 3);
            __half* p0 = dst + ((size_t)b * NPIX + n) * 16;
            p0[d]      = __float2half(acc[nt][0] + b0);
            p0[16 + d] = __float2half(acc[nt][1] + b0);
            p0[d + 8]      = __float2half(acc[nt][2] + b8);
            p0[16 + d + 8] = __float2half(acc[nt][3] + b8);
        }
    }
}

// ---------------------------------------------------------------------------
// PAM flash attention: q-tile 64, 128-thread CTA, occ 3.  Residual from hi+lo.
// ---------------------------------------------------------------------------
#define ATT_SMEM 46080

__global__ void __launch_bounds__(128, 3) pam_attn_mma(
        const __half* __restrict__ qh, const __half* __restrict__ kh,
        const __half* __restrict__ vd,
        const __half* __restrict__ yhi, const __half* __restrict__ ylo,
        const float* __restrict__ alpha, __half* __restrict__ xp2) {
    extern __shared__ __align__(16) char smc[];
    const uint32_t smb = smem_u32(smc);
    const uint32_t Qb  = smb;
    const uint32_t Kb0 = smb + 3072;
    const uint32_t Vb0 = smb + 9216;

    const int tid = threadIdx.x, lane = tid & 31, wid = tid >> 5;
    const int b = blockIdx.y;
    const int n0 = blockIdx.x * 64;
    const int qbase = wid * 16;

    const int g = lane >> 3, r8 = lane & 7;
    const uint32_t qoff = (uint32_t)(((g & 1) * 8 + r8) * 48 + (g >> 1) * 16);
    const uint32_t koff = (uint32_t)(((g >> 1) * 8 + r8) * 48 + (g & 1) * 16);
    const uint32_t voff = (uint32_t)(((g >> 1) * 8 + r8) * 144 + (g & 1) * 16);

    auto stageKV = [&](int t, int buf) {
        const int k0 = t * 64;
        {
            int row = tid >> 1, h = tid & 1;
            CP_ASYNC16(Kb0 + buf * 3072 + row * 48 + h * 16,
                       kh + ((size_t)b * NPIX + k0 + row) * 16 + h * 8);
        }
#pragma unroll
        for (int t4 = 0; t4 < 8; t4++) {
            int idx = tid + t4 * 128;
            int ch = idx >> 3, c = idx & 7;
            CP_ASYNC16(Vb0 + buf * 18432 + ch * 144 + c * 16,
                       vd + ((size_t)b * 128 + ch) * NPIX + k0 + c * 8);
        }
        CP_COMMIT();
    };

    {
        int row = tid >> 1, h = tid & 1;
        CP_ASYNC16(Qb + row * 48 + h * 16,
                   qh + ((size_t)b * NPIX + n0 + row) * 16 + h * 8);
    }
    stageKV(0, 0);

    uint32_t qfr[4];
    float O[16][4];
#pragma unroll
    for (int nc = 0; nc < 16; nc++)
#pragma unroll
        for (int r = 0; r < 4; r++) O[nc][r] = 0.0f;
    float mrun0 = -1e30f, mrun1 = -1e30f, lrun0 = 0.0f, lrun1 = 0.0f;

    for (int t = 0; t < 64; t++) {
        const int buf = t & 1;
        CP_WAIT(0);
        __syncthreads();
        if (t + 1 < 64) stageKV(t + 1, buf ^ 1);
        if (t == 0) ldsm4(qfr, Qb + qbase * 48 + qoff);

        const uint32_t Kb = Kb0 + buf * 3072;
        const uint32_t Vb = Vb0 + buf * 18432;

        float S[8][4];
#pragma unroll
        for (int ks = 0; ks < 4; ks++) {
            uint32_t kb[4];
            ldsm4(kb, Kb + ks * 768 + koff);
#pragma unroll
            for (int r = 0; r < 4; r++) { S[2 * ks][r] = 0.0f; S[2 * ks + 1][r] = 0.0f; }
            mma_f16(S[2 * ks],     qfr, kb[0], kb[1]);
            mma_f16(S[2 * ks + 1], qfr, kb[2], kb[3]);
        }

        float tm0 = -1e30f, tm1 = -1e30f;
#pragma unroll
        for (int nt = 0; nt < 8; nt++) {
            tm0 = fmaxf(tm0, fmaxf(S[nt][0], S[nt][1]));
            tm1 = fmaxf(tm1, fmaxf(S[nt][2], S[nt][3]));
        }
        tm0 = fmaxf(tm0, __shfl_xor_sync(0xffffffffu, tm0, 1));
        tm0 = fmaxf(tm0, __shfl_xor_sync(0xffffffffu, tm0, 2));
        tm1 = fmaxf(tm1, __shfl_xor_sync(0xffffffffu, tm1, 1));
        tm1 = fmaxf(tm1, __shfl_xor_sync(0xffffffffu, tm1, 2));
        const float mn0 = fmaxf(mrun0, tm0), mn1 = fmaxf(mrun1, tm1);
        const float f0 = __expf(mrun0 - mn0), f1 = __expf(mrun1 - mn1);
        mrun0 = mn0; mrun1 = mn1;

        float ts0 = 0.0f, ts1 = 0.0f;
        uint32_t afr[4][4];
#pragma unroll
        for (int j = 0; j < 4; j++) {
            float p00 = __expf(S[2 * j][0] - mn0), p01 = __expf(S[2 * j][1] - mn0);
            float p10 = __expf(S[2 * j][2] - mn1), p11 = __expf(S[2 * j][3] - mn1);
            float q00 = __expf(S[2 * j + 1][0] - mn0), q01 = __expf(S[2 * j + 1][1] - mn0);
            float q10 = __expf(S[2 * j + 1][2] - mn1), q11 = __expf(S[2 * j + 1][3] - mn1);
            ts0 += (p00 + p01) + (q00 + q01);
            ts1 += (p10 + p11) + (q10 + q11);
            afr[j][0] = ph2(p00, p01);
            afr[j][1] = ph2(p10, p11);
            afr[j][2] = ph2(q00, q01);
            afr[j][3] = ph2(q10, q11);
        }
        ts0 += __shfl_xor_sync(0xffffffffu, ts0, 1);
        ts0 += __shfl_xor_sync(0xffffffffu, ts0, 2);
        ts1 += __shfl_xor_sync(0xffffffffu, ts1, 1);
        ts1 += __shfl_xor_sync(0xffffffffu, ts1, 2);
        lrun0 = lrun0 * f0 + ts0;
        lrun1 = lrun1 * f1 + ts1;

#pragma unroll
        for (int nc = 0; nc < 16; nc++) {
            O[nc][0] *= f0; O[nc][1] *= f0;
            O[nc][2] *= f1; O[nc][3] *= f1;
        }

#pragma unroll
        for (int j = 0; j < 4; j++) {
            const uint32_t vb_j = Vb + j * 32 + voff;
#pragma unroll
            for (int p = 0; p < 8; p++) {
                uint32_t vb[4];
                ldsm4(vb, vb_j + p * 2304);
                mma_f16(O[2 * p],     afr[j], vb[0], vb[1]);
                mma_f16(O[2 * p + 1], afr[j], vb[2], vb[3]);
            }
        }
    }

    const float linv0 = 1.0f / lrun0, linv1 = 1.0f / lrun1;
    const float a = alpha[0];
    const int px0 = n0 + qbase + (lane >> 2);
    const int px1 = px0 + 8;
    __half* dst0 = xp2 + (((size_t)b * XP_H + (px0 >> 6) + 1) * XP_H + (px0 & 63) + 1) * CI;
    __half* dst1 = xp2 + (((size_t)b * XP_H + (px1 >> 6) + 1) * XP_H + (px1 & 63) + 1) * CI;
#pragma unroll
    for (int nc = 0; nc < 16; nc++) {
        const int ch = nc * 8 + 2 * (lane & 3);
        const __half* hp = yhi + ((size_t)b * 128 + ch) * NPIX;
        const __half* lp = ylo + ((size_t)b * 128 + ch) * NPIX;
        float ya0 = __half2float(hp[px0]) + __half2float(lp[px0]);
        float yb0 = __half2float(hp[NPIX + px0]) + __half2float(lp[NPIX + px0]);
        float ya1 = __half2float(hp[px1]) + __half2float(lp[px1]);
        float yb1 = __half2float(hp[NPIX + px1]) + __half2float(lp[NPIX + px1]);
        *(uint32_t*)(dst0 + ch) = ph2(fmaf(a, O[nc][0] * linv0, ya0),
                                      fmaf(a, O[nc][1] * linv0, yb0));
        *(uint32_t*)(dst1 + ch) = ph2(fmaf(a, O[nc][2] * linv1, ya1),
                                      fmaf(a, O[nc][3] * linv1, yb1));
    }
}

// ---------------------------------------------------------------------------
// CAM gram matrix via fp16 hi/lo split MMA, split-K partials.
// ---------------------------------------------------------------------------
#define CAME_SMEM 36864

__global__ void __launch_bounds__(256, 2) cam_energy_mma(
        const __half* __restrict__ yhi, const __half* __restrict__ ylo,
        float* __restrict__ epart) {
    extern __shared__ __align__(16) char smc[];
    const uint32_t smb = smem_u32(smc);
    const int tid = threadIdx.x, lane = tid & 31, wid = tid >> 5;
    const int warp_m = wid >> 2, warp_n = wid & 3;
    const int b = blockIdx.y, ksid = blockIdx.x;
    const int g = lane >> 3, r8 = lane & 7;

    float acc[4][4][4];
#pragma unroll
    for (int mt = 0; mt < 4; mt++)
#pragma unroll
        for (int nt = 0; nt < 4; nt++)
#pragma unroll
            for (int r = 0; r < 4; r++) acc[mt][nt][r] = 0.0f;

    for (int chunk = 0; chunk < 4; chunk++) {
        const int k0 = ksid * 256 + chunk * 64;
        __syncthreads();
#pragma unroll
        for (int t = 0; t < 4; t++) {
            int idx = tid + t * 256;
            int ch = idx >> 3, seg = idx & 7;
            CP_ASYNC16(smb + ch * 144 + seg * 16,
                       yhi + ((size_t)b * 128 + ch) * NPIX + k0 + seg * 8);
            CP_ASYNC16(smb + 18432 + ch * 144 + seg * 16,
                       ylo + ((size_t)b * 128 + ch) * NPIX + k0 + seg * 8);
        }
        CP_COMMIT();
        CP_WAIT(0);
        __syncthreads();

#pragma unroll
        for (int ks = 0; ks < 4; ks++) {
            uint32_t ahi[4][4], alo[4][4];
#pragma unroll
            for (int mt = 0; mt < 4; mt++) {
                const uint32_t arow = (warp_m * 64 + mt * 16 + (g & 1) * 8 + r8) * 144
                                      + ks * 32 + (g >> 1) * 16;
                ldsm4(ahi[mt], smb + arow);
                ldsm4(alo[mt], smb + 18432 + arow);
            }
            uint32_t bhi[2][4], blo[2][4];
#pragma unroll
            for (int t16 = 0; t16 < 2; t16++) {
                const uint32_t brow = (warp_n * 32 + t16 * 16 + (g >> 1) * 8 + r8) * 144
                                      + ks * 32 + (g & 1) * 16;
                ldsm4(bhi[t16], smb + brow);
                ldsm4(blo[t16], smb + 18432 + brow);
            }
#pragma unroll
            for (int mt = 0; mt < 4; mt++)
#pragma unroll
                for (int t16 = 0; t16 < 2; t16++) {
                    mma_f16(acc[mt][2 * t16],     ahi[mt], bhi[t16][0], bhi[t16][1]);
                    mma_f16(acc[mt][2 * t16 + 1], ahi[mt], bhi[t16][2], bhi[t16][3]);
                    mma_f16(acc[mt][2 * t16],     ahi[mt], blo[t16][0], blo[t16][1]);
                    mma_f16(acc[mt][2 * t16 + 1], ahi[mt], blo[t16][2], blo[t16][3]);
                    mma_f16(acc[mt][2 * t16],     alo[mt], bhi[t16][0], bhi[t16][1]);
                    mma_f16(acc[mt][2 * t16 + 1], alo[mt], bhi[t16][2], bhi[t16][3]);
                }
        }
    }

    float* ep = epart + (((size_t)ksid * BATCH + b) * 128) * 128;
#pragma unroll
    for (int mt = 0; mt < 4; mt++) {
        const int c0 = warp_m * 64 + mt * 16 + (lane >> 2);
#pragma unroll
        for (int nt = 0; nt < 4; nt++) {
            const int d = warp_n * 32 + nt * 8 + 2 * (lane & 3);
            *(float2*)(ep + (size_t)c0 * 128 + d) = make_float2(acc[mt][nt][0], acc[mt][nt][1]);
            *(float2*)(ep + (size_t)(c0 + 8) * 128 + d) = make_float2(acc[mt][nt][2], acc[mt][nt][3]);
        }
    }
}

// ---------------------------------------------------------------------------
// CAM softmax of (rowmax - E), reducing the KSPLIT partials -> fp16 attn
// ---------------------------------------------------------------------------
__global__ void cam_softmax_kernel(const float* __restrict__ epart,
                                   __half* __restrict__ attn) {
    const int row = blockIdx.x;
    const int tid = threadIdx.x;
    __shared__ float red[4];

    float e = 0.0f;
#pragma unroll
    for (int s = 0; s < KSPLIT; s++)
        e += epart[((size_t)s * 1024 + row) * 128 + tid];

    float m = e;
#pragma unroll
    for (int off = 16; off; off >>= 1) m = fmaxf(m, __shfl_xor_sync(0xffffffff, m, off));
    if ((tid & 31) == 0) red[tid >> 5] = m;
    __syncthreads();
    float mx = fmaxf(fmaxf(red[0], red[1]), fmaxf(red[2], red[3]));
    float e2 = mx - e;
    __syncthreads();

    float m2 = e2;
#pragma unroll
    for (int off = 16; off; off >>= 1) m2 = fmaxf(m2, __shfl_xor_sync(0xffffffff, m2, off));
    if ((tid & 31) == 0) red[tid >> 5] = m2;
    __syncthreads();
    m2 = fmaxf(fmaxf(red[0], red[1]), fmaxf(red[2], red[3]));
    float p = __expf(e2 - m2);
    __syncthreads();

    float s = p;
#pragma unroll
    for (int off = 16; off; off >>= 1) s += __shfl_xor_sync(0xffffffff, s, off);
    if ((tid & 31) == 0) red[tid >> 5] = s;
    __syncthreads();
    s = red[0] + red[1] + red[2] + red[3];

    attn[(size_t)row * 128 + tid] = __float2half(p / s);
}

// ---------------------------------------------------------------------------
// CAM feature via fp16 MMA -> fp16 padded NHWC; residual from hi+lo.
// ---------------------------------------------------------------------------
#define CAMF_SMEM 53248

__global__ void __launch_bounds__(256, 1) cam_feat_mma(
        const __half* __restrict__ attn16,
        const __half* __restrict__ yhi, const __half* __restrict__ ylo,
        const float* __restrict__ beta, __half* __restrict__ xp2) {
    extern __shared__ __align__(16) char smc[];
    const uint32_t smb = smem_u32(smc);
    const int tid = threadIdx.x, lane = tid & 31, wid = tid >> 5;
    const int b = blockIdx.y;
    const int n0 = blockIdx.x * 64;
    const int g = lane >> 3;

#pragma unroll
    for (int t = 0; t < 8; t++) {
        int idx = tid + t * 256;
        int c = idx >> 4, seg = idx & 15;
        CP_ASYNC16(smb + c * 272 + seg * 16,
                   attn16 + ((size_t)b * 128 + c) * 128 + seg * 8);
    }
#pragma unroll
    for (int t = 0; t < 4; t++) {
        int idx = tid + t * 256;
        int ch = idx >> 3, seg = idx & 7;
        CP_ASYNC16(smb + 34816 + ch * 144 + seg * 16,
                   yhi + ((size_t)b * 128 + ch) * NPIX + n0 + seg * 8);
    }
    CP_COMMIT();
    CP_WAIT(0);
    __syncthreads();

    const int mt = wid;
    float acc[8][4];
#pragma unroll
    for (int nt = 0; nt < 8; nt++)
#pragma unroll
        for (int r = 0; r < 4; r++) acc[nt][r] = 0.0f;

    const uint32_t Bsm = smb + 34816;
#pragma unroll
    for (int ks = 0; ks < 8; ks++) {
        uint32_t afr[4];
        ldsm4(afr, smb + (mt * 16 + (g & 1) * 8 + (lane & 7)) * 272
                  + ks * 32 + (g >> 1) * 16);
#pragma unroll
        for (int t16 = 0; t16 < 4; t16++) {
            uint32_t bfr[4];
            ldsm4t(bfr, Bsm + (ks * 16 + (g & 1) * 8 + (lane & 7)) * 144
                       + (t16 * 16 + (g >> 1) * 8) * 2);
            mma_f16(acc[2 * t16],     afr, bfr[0], bfr[1]);
            mma_f16(acc[2 * t16 + 1], afr, bfr[2], bfr[3]);
        }
    }

    const float bet = beta[0];
    const int c0 = mt * 16 + (lane >> 2);
#pragma unroll
    for (int nt = 0; nt < 8; nt++) {
        const int n = n0 + nt * 8 + 2 * (lane & 3);
        const __half* h0p = yhi + ((size_t)b * 128 + c0) * NPIX;
        const __half* l0p = ylo + ((size_t)b * 128 + c0) * NPIX;
        float y00 = __half2float(h0p[n]) + __half2float(l0p[n]);
        float y01 = __half2float(h0p[n + 1]) + __half2float(l0p[n + 1]);
        float y80 = __half2float(h0p[8 * NPIX + n]) + __half2float(l0p[8 * NPIX + n]);
        float y81 = __half2float(h0p[8 * NPIX + n + 1]) + __half2float(l0p[8 * NPIX + n + 1]);
        __half* p0 = xp2 + (((size_t)b * XP_H + (n >> 6) + 1) * XP_H + (n & 63) + 1) * CI;
        __half* p1 = p0 + CI;
        p0[c0]     = __float2half(fmaf(bet, acc[nt][0], y00));
        p1[c0]     = __float2half(fmaf(bet, acc[nt][1], y01));
        p0[c0 + 8] = __float2half(fmaf(bet, acc[nt][2], y80));
        p1[c0 + 8] = __float2half(fmaf(bet, acc[nt][3], y81));
    }
}

// ---------------------------------------------------------------------------
// Final heads via one fused fp16 MMA:  A[64x256] @ [fp;fc](256 x 64px tile).
// grid (64 n-tiles, 8 b), block 128 (4 warps, one m16 tile each).
// smem: A 32768 @0; B [256ch][72h] @32768 (36864).  Total 69632.
// ---------------------------------------------------------------------------
#define FIN_SMEM 69632

__global__ void __launch_bounds__(128, 2) final_mma(
        const __half* __restrict__ wfin,
        const __half* __restrict__ fp, const __half* __restrict__ fc,
        const float* __restrict__ bout, const float* __restrict__ bp3,
        const float* __restrict__ bc3, float* __restrict__ out) {
    extern __shared__ __align__(16) char smc[];
    const uint32_t smb = smem_u32(smc);
    const int tid = threadIdx.x, lane = tid & 31, wid = tid >> 5;
    const int b = blockIdx.y;
    const int n0 = blockIdx.x * 64;
    const int g = lane >> 3;

    // Stage A: 16384 halves = 2048 x 16B
#pragma unroll
    for (int t = 0; t < 16; t++) {
        int i = tid + t * 128;
        CP_ASYNC16(smb + i * 16, wfin + i * 8);
    }
    // Stage B: 256 ch x 64 px (rows 0-127 fp, 128-255 fc), stride 144B
#pragma unroll
    for (int t = 0; t < 16; t++) {
        int idx = tid + t * 128;
        int ch = idx >> 3, seg = idx & 7;
        const __half* src = (ch < 128)
            ? fp + ((size_t)b * 128 + ch) * NPIX + n0 + seg * 8
            : fc + ((size_t)b * 128 + (ch - 128)) * NPIX + n0 + seg * 8;
        CP_ASYNC16(smb + 32768 + ch * 144 + seg * 16, src);
    }
    CP_COMMIT();
    CP_WAIT(0);
    __syncthreads();

    const int mt = wid;
    float acc[8][4];
#pragma unroll
    for (int nt = 0; nt < 8; nt++)
#pragma unroll
        for (int r = 0; r < 4; r++) acc[nt][r] = 0.0f;

    const char* Aptr = smc;
    const uint32_t Bsm = smb + 32768;
#pragma unroll
    for (int ks = 0; ks < 16; ks++) {
        uint4 v = *(const uint4*)(Aptr + (((mt * 16 + ks) * 32 + lane) << 4));
        uint32_t afr[4] = {v.x, v.y, v.z, v.w};
#pragma unroll
        for (int t16 = 0; t16 < 4; t16++) {
            uint32_t bfr[4];
            ldsm4t(bfr, Bsm + (ks * 16 + (g & 1) * 8 + (lane & 7)) * 144
                       + (t16 * 16 + (g >> 1) * 8) * 2);
            mma_f16(acc[2 * t16],     afr, bfr[0], bfr[1]);
            mma_f16(acc[2 * t16 + 1], afr, bfr[2], bfr[3]);
        }
    }

    const size_t SEG = (size_t)BATCH * NC * NPIX;
    auto emit = [&](int row, int px, float v) {
        if (row >= 57) return;
        float bias;
        size_t base;
        if (row < 19)      { bias = bout[row]; base = ((size_t)b * NC + row) * NPIX; }
        else if (row < 38) { bias = bp3[row - 19]; base = SEG + ((size_t)b * NC + row - 19) * NPIX; }
        else               { bias = bc3[row - 38]; base = 2 * SEG + ((size_t)b * NC + row - 38) * NPIX; }
        out[base + px] = sigmoidf_(v + bias);
    };

    const int r0 = mt * 16 + (lane >> 2);
#pragma unroll
    for (int nt = 0; nt < 8; nt++) {
        const int px = n0 + nt * 8 + 2 * (lane & 3);
        emit(r0,     px,     acc[nt][0]);
        emit(r0,     px + 1, acc[nt][1]);
        emit(r0 + 8, px,     acc[nt][2]);
        emit(r0 + 8, px + 1, acc[nt][3]);
    }
}

// ---------------------------------------------------------------------------
// Streams / events (created once at program load)
// ---------------------------------------------------------------------------
namespace {
struct StreamInit {
    cudaStream_t s1;
    cudaEvent_t e0, e1, e2, e3, e4;
    StreamInit() {
        cudaStreamCreateWithFlags(&s1, cudaStreamNonBlocking);
        cudaEventCreateWithFlags(&e0, cudaEventDisableTiming);
        cudaEventCreateWithFlags(&e1, cudaEventDisableTiming);
        cudaEventCreateWithFlags(&e2, cudaEventDisableTiming);
        cudaEventCreateWithFlags(&e3, cudaEventDisableTiming);
        cudaEventCreateWithFlags(&e4, cudaEventDisableTiming);
    }
};
StreamInit g_str;
}

// ---------------------------------------------------------------------------
// Launch
// ---------------------------------------------------------------------------
extern "C" void kernel_launch(void* const* d_in, const int* in_sizes, int n_in,
                              void* d_out, int out_size) {
    const float* x    = (const float*)d_in[0];
    const float* Wp1  = (const float*)d_in[1];
    const float* bnp1 = (const float*)d_in[2];
    const float* Wc1  = (const float*)d_in[3];
    const float* bnc1 = (const float*)d_in[4];
    const float* Wb   = (const float*)d_in[5];
    const float* bb   = (const float*)d_in[6];
    const float* Wc   = (const float*)d_in[7];
    const float* bc   = (const float*)d_in[8];
    const float* Wd   = (const float*)d_in[9];
    const float* bd   = (const float*)d_in[10];
    const float* alpha= (const float*)d_in[11];
    const float* beta = (const float*)d_in[12];
    const float* Wp2  = (const float*)d_in[13];
    const float* bnp2 = (const float*)d_in[14];
    const float* Wc2  = (const float*)d_in[15];
    const float* bnc2 = (const float*)d_in[16];
    const float* Wout = (const float*)d_in[17];
    const float* bout = (const float*)d_in[18];
    const float* Wp3  = (const float*)d_in[19];
    const float* bp3  = (const float*)d_in[20];
    const float* Wc3  = (const float*)d_in[21];
    const float* bc3  = (const float*)d_in[22];
    float* out = (float*)d_out;

    float* epart;
    __half *featp1h, *featp1lo, *featc1h, *featc1lo, *qh, *kh, *vd, *attn16;
    __half *xpad, *xp2a, *xp2b, *wf1, *wf2, *wqkv, *wfin;
    cudaGetSymbolAddress((void**)&featp1h,  g_featp1h);
    cudaGetSymbolAddress((void**)&featp1lo, g_featp1lo);
    cudaGetSymbolAddress((void**)&featc1h,  g_featc1h);
    cudaGetSymbolAddress((void**)&featc1lo, g_featc1lo);
    cudaGetSymbolAddress((void**)&qh,       g_qh);
    cudaGetSymbolAddress((void**)&kh,       g_kh);
    cudaGetSymbolAddress((void**)&vd,       g_vd);
    cudaGetSymbolAddress((void**)&epart,    g_epart);
    cudaGetSymbolAddress((void**)&attn16,   g_attn16);
    cudaGetSymbolAddress((void**)&xpad,     g_xpad);
    cudaGetSymbolAddress((void**)&xp2a,     g_xp2a);
    cudaGetSymbolAddress((void**)&xp2b,     g_xp2b);
    cudaGetSymbolAddress((void**)&wf1,      g_wf16_1);
    cudaGetSymbolAddress((void**)&wf2,      g_wf16_2);
    cudaGetSymbolAddress((void**)&wqkv,     g_wqkv);
    cudaGetSymbolAddress((void**)&wfin,     g_wfinal);

    cudaFuncSetAttribute(conv_mma_kernel<512>,
                         cudaFuncAttributeMaxDynamicSharedMemorySize, CONV_SMEM);
    cudaFuncSetAttribute(conv_mma_kernel<128>,
                         cudaFuncAttributeMaxDynamicSharedMemorySize, CONV_SMEM);
    cudaFuncSetAttribute(pam_attn_mma,
                         cudaFuncAttributeMaxDynamicSharedMemorySize, ATT_SMEM);
    cudaFuncSetAttribute(pam_attn_mma,
                         cudaFuncAttributePreferredSharedMemoryCarveout, 100);
    cudaFuncSetAttribute(qkv_kernel,
                         cudaFuncAttributeMaxDynamicSharedMemorySize, QKV_SMEM);
    cudaFuncSetAttribute(cam_energy_mma,
                         cudaFuncAttributeMaxDynamicSharedMemorySize, CAME_SMEM);
    cudaFuncSetAttribute(cam_feat_mma,
                         cudaFuncAttributeMaxDynamicSharedMemorySize, CAMF_SMEM);
    cudaFuncSetAttribute(final_mma,
                         cudaFuncAttributeMaxDynamicSharedMemorySize, FIN_SMEM);

    cudaStream_t s1 = g_str.s1;

    // Fork s1 off the main stream
    cudaEventRecord(g_str.e0, 0);
    cudaStreamWaitEvent(s1, g_str.e0, 0);

    // s0: interior packing
    pack_x_kernel<<<dim3(64, BATCH), 256>>>(x, xpad);

    // s1: all borders + weight packing (parallel with pack_x)
    zero_border_h<<<dim3(XP_H, BATCH), 256, 0, s1>>>(xpad, CIN);
    pack_w16<<<dim3(144, 2), 256, 0, s1>>>(Wp1, Wc1, wf1, CIN);
    zero_border_h<<<dim3(XP_H, BATCH), 256, 0, s1>>>(xp2a, CI);
    zero_border_h<<<dim3(XP_H, BATCH), 256, 0, s1>>>(xp2b, CI);
    pack_wqkv<<<1, 256, 0, s1>>>(Wd, Wb, Wc, wqkv);
    cudaEventRecord(g_str.e1, s1);
    pack_w16<<<dim3(36, 2), 256, 0, s1>>>(Wp2, Wc2, wf2, CI);
    pack_wfinal<<<1, 256, 0, s1>>>(Wout, Wp3, Wc3, wfin);
    cudaEventRecord(g_str.e4, s1);

    // s0: conv1 (both branches) after wf1/borders ready
    cudaStreamWaitEvent(0, g_str.e1, 0);
    conv_mma_kernel<512><<<dim3(32, BATCH, 2), 256, CONV_SMEM>>>(
        xpad, xpad, wf1, bnp1, bnc1, featp1h, featc1h, featp1lo, featc1lo);
    cudaEventRecord(g_str.e2, 0);

    // s1: CAM chain + conv2-CAM (parallel with PAM on s0)
    cudaStreamWaitEvent(s1, g_str.e2, 0);
    cam_energy_mma<<<dim3(KSPLIT, BATCH), 256, CAME_SMEM, s1>>>(featc1h, featc1lo, epart);
    cam_softmax_kernel<<<BATCH * 128, 128, 0, s1>>>(epart, attn16);
    cam_feat_mma<<<dim3(64, BATCH), 256, CAMF_SMEM, s1>>>(
        attn16, featc1h, featc1lo, beta, xp2b);
    conv_mma_kernel<128><<<dim3(32, BATCH, 1), 256, CONV_SMEM, s1>>>(
        xp2b, xp2b, wf2 + 36 * 4096, bnc2, bnc2, featc1h, featc1h, nullptr, nullptr);
    cudaEventRecord(g_str.e3, s1);

    // s0: PAM chain + conv2-PAM
    qkv_kernel<<<dim3(64, BATCH), 320, QKV_SMEM>>>(
        wqkv, featp1h, bd, bb, bc, vd, qh, kh);
    pam_attn_mma<<<dim3(64, BATCH), 128, ATT_SMEM>>>(
        qh, kh, vd, featp1h, featp1lo, alpha, xp2a);
    cudaStreamWaitEvent(0, g_str.e4, 0);
    conv_mma_kernel<128><<<dim3(32, BATCH, 1), 256, CONV_SMEM>>>(
        xp2a, xp2a, wf2, bnp2, bnp2, featp1h, featp1h, nullptr, nullptr);

    // Join, then fused final heads
    cudaStreamWaitEvent(0, g_str.e3, 0);
    final_mma<<<dim3(64, BATCH), 128, FIN_SMEM>>>(
        wfin, featp1h, featc1h, bout, bp3, bc3, out);
}

// round 11
// speedup vs baseline: 14.0731x; 1.1003x over previous
#include <cuda_runtime.h>
#include <cuda_bf16.h>
#include <cuda_fp16.h>
#include <math.h>
#include <cstdint>

// ---------------------------------------------------------------------------
// Problem constants
// ---------------------------------------------------------------------------
#define BATCH 8
#define CIN   512
#define CI    128
#define CK    16
#define NC    19
#define NPIX  4096
#define FEAT_ELEMS (BATCH * CI * NPIX)
#define XP_H 66
#define KSPLIT 16

// ---------------------------------------------------------------------------
// Scratch (device globals)
// ---------------------------------------------------------------------------
__device__ __half g_featp1h[FEAT_ELEMS];     // conv1-p hi; later conv2-p out
__device__ __half g_featp1lo[FEAT_ELEMS];    // conv1-p lo residual
__device__ __half g_featc1h[FEAT_ELEMS];     // conv1-c hi; later conv2-c out
__device__ __half g_featc1lo[FEAT_ELEMS];    // conv1-c lo residual
__device__ __half g_qh[BATCH * NPIX * CK];
__device__ __half g_kh[BATCH * NPIX * CK];
__device__ __half g_vd[FEAT_ELEMS];
__device__ float  g_epart[KSPLIT * BATCH * CI * CI];
__device__ __half g_attn16[BATCH * CI * CI];
__device__ __half g_xpad[BATCH * XP_H * XP_H * CIN];
__device__ __half g_xp2a[BATCH * XP_H * XP_H * CI];
__device__ __half g_xp2b[BATCH * XP_H * XP_H * CI];
__device__ __half g_wf16_1[2 * 144 * 4096];
__device__ __half g_wf16_2[2 * 36 * 4096];
__device__ __half g_wqkv[10 * 8 * 32 * 8];
__device__ __half g_wfinal[4 * 16 * 32 * 8];   // [64 rows x 256 k] frag-packed

__device__ __forceinline__ float sigmoidf_(float x) {
    return 1.0f / (1.0f + __expf(-x));
}
__device__ __forceinline__ uint32_t smem_u32(const void* p) {
    uint32_t a;
    asm("{ .reg .u64 t; cvta.to.shared.u64 t, %1; cvt.u32.u64 %0, t; }" : "=r"(a) : "l"(p));
    return a;
}
__device__ __forceinline__ void mma_f16(float c[4], const uint32_t a[4], const uint32_t b0, const uint32_t b1) {
    asm volatile(
        "mma.sync.aligned.m16n8k16.row.col.f32.f16.f16.f32 "
        "{%0,%1,%2,%3}, {%4,%5,%6,%7}, {%8,%9}, {%0,%1,%2,%3};"
        : "+f"(c[0]), "+f"(c[1]), "+f"(c[2]), "+f"(c[3])
        : "r"(a[0]), "r"(a[1]), "r"(a[2]), "r"(a[3]), "r"(b0), "r"(b1));
}
__device__ __forceinline__ void ldsm4(uint32_t r[4], uint32_t addr) {
    asm volatile("ldmatrix.sync.aligned.m8n8.x4.shared.b16 {%0,%1,%2,%3}, [%4];"
                 : "=r"(r[0]), "=r"(r[1]), "=r"(r[2]), "=r"(r[3]) : "r"(addr));
}
__device__ __forceinline__ void ldsm4t(uint32_t r[4], uint32_t addr) {
    asm volatile("ldmatrix.sync.aligned.m8n8.x4.trans.shared.b16 {%0,%1,%2,%3}, [%4];"
                 : "=r"(r[0]), "=r"(r[1]), "=r"(r[2]), "=r"(r[3]) : "r"(addr));
}
#define CP_ASYNC16(dst, src) \
    asm volatile("cp.async.ca.shared.global [%0], [%1], 16;" :: "r"(dst), "l"(src))
#define CP_COMMIT() asm volatile("cp.async.commit_group;")
#define CP_WAIT(N)  asm volatile("cp.async.wait_group %0;" :: "n"(N))

__device__ __forceinline__ uint32_t ph2(float x, float y) {
    __half2 h = __floats2half2_rn(x, y);
    return *(uint32_t*)&h;
}

// ---------------------------------------------------------------------------
// Pack x: f32 NCHW -> fp16 NHWC padded
// ---------------------------------------------------------------------------
__global__ void pack_x_kernel(const float* __restrict__ x, __half* __restrict__ xp) {
    const int h = blockIdx.x, b = blockIdx.y, tid = threadIdx.x;
    __shared__ float s[32][65];
    for (int ci0 = 0; ci0 < CIN; ci0 += 32) {
        for (int idx = tid; idx < 32 * 64; idx += 256) {
            int ci_l = idx >> 6, w = idx & 63;
            s[ci_l][w] = x[(((size_t)b * CIN + ci0 + ci_l) * 64 + h) * 64 + w];
        }
        __syncthreads();
        for (int idx = tid; idx < 64 * 32; idx += 256) {
            int w = idx >> 5, ci_l = idx & 31;
            xp[(((size_t)b * XP_H + h + 1) * XP_H + w + 1) * CIN + ci0 + ci_l] =
                __float2half(s[ci_l][w]);
        }
        __syncthreads();
    }
}

__global__ void zero_border_h(__half* __restrict__ xp, int C) {
    const int hp = blockIdx.x, b = blockIdx.y, tid = threadIdx.x;
    __half* row = xp + ((size_t)b * XP_H + hp) * XP_H * C;
    const __half z = __float2half(0.0f);
    if (hp == 0 || hp == XP_H - 1) {
        for (int idx = tid; idx < XP_H * C; idx += 256) row[idx] = z;
    } else {
        for (int idx = tid; idx < C; idx += 256) {
            row[idx] = z;
            row[(size_t)(XP_H - 1) * C + idx] = z;
        }
    }
}

// ---------------------------------------------------------------------------
// Pack conv weights into m16n8k16 fp16 A-fragment order.
// ---------------------------------------------------------------------------
__global__ void pack_w16(const float* __restrict__ W0, const float* __restrict__ W1,
                         __half* __restrict__ wf, int CIN_T) {
    const int cpc = CIN_T / 32;
    const int chunk = blockIdx.x;
    const int kwh = chunk / cpc, cb = chunk % cpc;
    const float* W = blockIdx.y ? W1 : W0;
    __half* dst = wf + ((size_t)blockIdx.y * gridDim.x + chunk) * 4096;
    for (int t = 0; t < 16; t++) {
        int idx = threadIdx.x + t * 256;
        int j = idx & 7, lane = (idx >> 3) & 31, ks = (idx >> 8) & 1, mt = idx >> 9;
        int reg = j >> 1, h = j & 1;
        int co = mt * 16 + (lane >> 2) + (reg & 1) * 8;
        int ci = cb * 32 + ks * 16 + (lane & 3) * 2 + (reg >> 1) * 8 + h;
        dst[idx] = __float2half(W[((size_t)co * CIN_T + ci) * 9 + kwh]);
    }
}

__global__ void pack_wqkv(const float* __restrict__ Wd, const float* __restrict__ Wb,
                          const float* __restrict__ Wc, __half* __restrict__ dst) {
    for (int idx = threadIdx.x; idx < 20480; idx += 256) {
        int j = idx & 7, lane = (idx >> 3) & 31, ks = (idx >> 8) & 7, mt = idx >> 11;
        int reg = j >> 1, h = j & 1;
        int row = mt * 16 + (lane >> 2) + (reg & 1) * 8;
        int col = ks * 16 + (lane & 3) * 2 + (reg >> 1) * 8 + h;
        float w;
        if (row < 128)      w = Wd[row * 128 + col];
        else if (row < 144) w = Wb[(row - 128) * 128 + col];
        else                w = Wc[(row - 144) * 128 + col];
        dst[idx] = __float2half(w);
    }
}

// Pack the fused final-head weight block matrix [64 x 256]:
//   rows 0-18:  [Wout | Wout]   rows 19-37: [Wp3 | 0]   rows 38-56: [0 | Wc3]
__global__ void pack_wfinal(const float* __restrict__ Wout, const float* __restrict__ Wp3,
                            const float* __restrict__ Wc3, __half* __restrict__ dst) {
    for (int idx = threadIdx.x; idx < 16384; idx += 256) {
        int j = idx & 7, lane = (idx >> 3) & 31, ks = (idx >> 8) & 15, mt = idx >> 12;
        int reg = j >> 1, h = j & 1;
        int row = mt * 16 + (lane >> 2) + (reg & 1) * 8;
        int col = ks * 16 + (lane & 3) * 2 + (reg >> 1) * 8 + h;
        float w = 0.0f;
        if (col < 128) {
            if (row < 19)      w = Wout[row * 128 + col];
            else if (row < 38) w = Wp3[(row - 19) * 128 + col];
        } else {
            int c = col - 128;
            if (row < 19)      w = Wout[row * 128 + c];
            else if (row >= 38 && row < 57) w = Wc3[(row - 38) * 128 + c];
        }
        dst[idx] = __float2half(w);
    }
}

// ---------------------------------------------------------------------------
// conv3x3 implicit GEMM, fp16 m16n8k16, halo-reuse B staging, fused BN+ReLU.
// smem: B 2x21120 @0; A 2x24576 @42240.  Total 91392.  Pixel stride 80B.
// Launched with grid.z = 1 (single branch; pointers select branch).
// ---------------------------------------------------------------------------
#define CONV_SMEM 91392
#define BPX 80

template<int CIN_T>
__global__ void __launch_bounds__(256, 2) conv_mma_kernel(
        const __half* __restrict__ xpA, const __half* __restrict__ xpB,
        const __half* __restrict__ wfrag,
        const float* __restrict__ bn0, const float* __restrict__ bn1,
        __half* __restrict__ o16_0, __half* __restrict__ o16_1,
        __half* __restrict__ olo_0, __half* __restrict__ olo_1) {
    constexpr int CPC = CIN_T / 32;
    constexpr int NS = CPC * 3;
    extern __shared__ __align__(16) char smc[];
    const uint32_t smb = smem_u32(smc);
    const uint32_t Boff = smb;
    const uint32_t Aoff = smb + 2 * 21120;

    const int tid = threadIdx.x, lane = tid & 31, wid = tid >> 5;
    const int warp_m = wid >> 2, warp_n = wid & 3;
    const int b = blockIdx.y, z = blockIdx.z;
    const int pxbase = blockIdx.x * 128;
    const int h0 = pxbase >> 6;
    const __half* xp = z ? xpB : xpA;
    const __half* Wf = wfrag + (size_t)z * (9 * CPC) * 4096;
    const float* bn = z ? bn1 : bn0;
    __half* o16 = z ? o16_1 : o16_0;
    __half* olo = z ? olo_1 : olo_0;
    const int g = lane >> 3;

    float acc[4][4][4];
#pragma unroll
    for (int mt = 0; mt < 4; mt++)
#pragma unroll
        for (int nt = 0; nt < 4; nt++)
#pragma unroll
            for (int r = 0; r < 4; r++) acc[mt][nt][r] = 0.0f;

    auto stageA = [&](int s, int buf) {
        const int cb = s / 3, kh = s % 3;
        const uint32_t Ad = Aoff + buf * 24576;
#pragma unroll
        for (int kw = 0; kw < 3; kw++) {
            const __half* src = Wf + (size_t)((kh * 3 + kw) * CPC + cb) * 4096;
#pragma unroll
            for (int t = 0; t < 2; t++) {
                int idx = tid + t * 256;
                CP_ASYNC16(Ad + kw * 8192 + idx * 16, src + idx * 8);
            }
        }
    };
    auto stageB = [&](int cb, int buf) {
        const uint32_t Bd = Boff + buf * 21120;
        const __half* base = xp + ((size_t)(b * XP_H + h0) * XP_H) * CIN_T + cb * 32;
        for (int idx = tid; idx < 1056; idx += 256) {
            int r = idx / 264, rem = idx % 264;
            int c = rem >> 2, q = rem & 3;
            CP_ASYNC16(Bd + (r * 66 + c) * BPX + q * 16,
                       base + ((size_t)r * XP_H + c) * CIN_T + q * 8);
        }
    };

    stageB(0, 0);
    stageA(0, 0);
    CP_COMMIT();

    for (int s = 0; s < NS; s++) {
        const int cb = s / 3, kh = s % 3;
        if (s + 1 < NS) {
            stageA(s + 1, (s + 1) & 1);
            if ((s + 1) % 3 == 0) stageB((s + 1) / 3, ((s + 1) / 3) & 1);
            CP_COMMIT();
            CP_WAIT(1);
        } else {
            CP_WAIT(0);
        }
        __syncthreads();

        const uint32_t Bh = Boff + (cb & 1) * 21120;
        const char* Ap = smc + 2 * 21120 + (s & 1) * 24576;
#pragma unroll
        for (int ks = 0; ks < 2; ks++) {
#pragma unroll
            for (int kw = 0; kw < 3; kw++) {
                uint32_t afr[4][4];
#pragma unroll
                for (int mt = 0; mt < 4; mt++) {
                    uint4 v = *(const uint4*)(Ap + kw * 8192 +
                        ((((warp_m * 4 + mt) * 2 + ks) * 32 + lane) << 4));
                    afr[mt][0] = v.x; afr[mt][1] = v.y; afr[mt][2] = v.z; afr[mt][3] = v.w;
                }
                uint32_t bfr[2][4];
#pragma unroll
                for (int t16 = 0; t16 < 2; t16++) {
                    const int n_row = warp_n * 32 + t16 * 16 + (g >> 1) * 8 + (lane & 7);
                    const int r = n_row >> 6, w = n_row & 63;
                    ldsm4(bfr[t16], Bh + ((r + kh) * 66 + w + kw) * BPX
                                      + ks * 32 + (g & 1) * 16);
                }
#pragma unroll
                for (int mt = 0; mt < 4; mt++)
#pragma unroll
                    for (int t16 = 0; t16 < 2; t16++) {
                        mma_f16(acc[mt][2 * t16],     afr[mt], bfr[t16][0], bfr[t16][1]);
                        mma_f16(acc[mt][2 * t16 + 1], afr[mt], bfr[t16][2], bfr[t16][3]);
                    }
            }
        }
        __syncthreads();
    }

#pragma unroll
    for (int mt = 0; mt < 4; mt++) {
        const int co = warp_m * 64 + mt * 16 + (lane >> 2);
        const float sc0 = bn[co],     sh0 = bn[128 + co];
        const float sc8 = bn[co + 8], sh8 = bn[136 + co];
#pragma unroll
        for (int nt = 0; nt < 4; nt++) {
            const int px = pxbase + warp_n * 32 + nt * 8 + 2 * (lane & 3);
            float v0x = fmaxf(acc[mt][nt][0] * sc0 + sh0, 0.0f);
            float v0y = fmaxf(acc[mt][nt][1] * sc0 + sh0, 0.0f);
            float v1x = fmaxf(acc[mt][nt][2] * sc8 + sh8, 0.0f);
            float v1y = fmaxf(acc[mt][nt][3] * sc8 + sh8, 0.0f);
            *(uint32_t*)(o16 + ((size_t)b * 128 + co) * NPIX + px) = ph2(v0x, v0y);
            *(uint32_t*)(o16 + ((size_t)b * 128 + co + 8) * NPIX + px) = ph2(v1x, v1y);
            if (olo) {
                float r0x = v0x - __half2float(__float2half(v0x));
                float r0y = v0y - __half2float(__float2half(v0y));
                float r1x = v1x - __half2float(__float2half(v1x));
                float r1y = v1y - __half2float(__float2half(v1y));
                *(uint32_t*)(olo + ((size_t)b * 128 + co) * NPIX + px) = ph2(r0x, r0y);
                *(uint32_t*)(olo + ((size_t)b * 128 + co + 8) * NPIX + px) = ph2(r1x, r1y);
            }
        }
    }
}

// ---------------------------------------------------------------------------
// QKV GEMM: [Wd;Wb;Wc](160x128) @ y16(128x4096) + bias.
// ---------------------------------------------------------------------------
#define QKV_SMEM 59392

__global__ void __launch_bounds__(320, 1) qkv_kernel(
        const __half* __restrict__ wq, const __half* __restrict__ y16,
        const float* __restrict__ bd, const float* __restrict__ bb,
        const float* __restrict__ bc,
        __half* __restrict__ vh, __half* __restrict__ qh, __half* __restrict__ kh) {
    extern __shared__ __align__(16) char smc[];
    const uint32_t smb = smem_u32(smc);
    const int tid = threadIdx.x, lane = tid & 31, wid = tid >> 5;
    const int b = blockIdx.y;
    const int n0 = blockIdx.x * 64;
    const int g = lane >> 3;

#pragma unroll
    for (int t = 0; t < 8; t++) {
        int i = tid + t * 320;
        CP_ASYNC16(smb + i * 16, wq + i * 8);
    }
    for (int idx = tid; idx < 1024; idx += 320) {
        int ch = idx >> 3, seg = idx & 7;
        CP_ASYNC16(smb + 40960 + ch * 144 + seg * 16,
                   y16 + ((size_t)b * 128 + ch) * NPIX + n0 + seg * 8);
    }
    CP_COMMIT();
    CP_WAIT(0);
    __syncthreads();

    const int mt = wid;
    float acc[8][4];
#pragma unroll
    for (int nt = 0; nt < 8; nt++)
#pragma unroll
        for (int r = 0; r < 4; r++) acc[nt][r] = 0.0f;

    const char* Aptr = smc;
    const uint32_t Bsm = smb + 40960;
#pragma unroll
    for (int ks = 0; ks < 8; ks++) {
        uint4 v = *(const uint4*)(Aptr + (((mt * 8 + ks) * 32 + lane) << 4));
        uint32_t afr[4] = {v.x, v.y, v.z, v.w};
#pragma unroll
        for (int t16 = 0; t16 < 4; t16++) {
            uint32_t bfr[4];
            ldsm4t(bfr, Bsm + (ks * 16 + (g & 1) * 8 + (lane & 7)) * 144
                       + (t16 * 16 + (g >> 1) * 8) * 2);
            mma_f16(acc[2 * t16],     afr, bfr[0], bfr[1]);
            mma_f16(acc[2 * t16 + 1], afr, bfr[2], bfr[3]);
        }
    }

    const int r0 = mt * 16 + (lane >> 2);
    if (mt < 8) {
        const float b0 = bd[r0], b8 = bd[r0 + 8];
        __half* v0 = vh + ((size_t)b * 128 + r0) * NPIX;
        __half* v8 = vh + ((size_t)b * 128 + r0 + 8) * NPIX;
#pragma unroll
        for (int nt = 0; nt < 8; nt++) {
            const int n = n0 + nt * 8 + 2 * (lane & 3);
            *(uint32_t*)(v0 + n) = ph2(acc[nt][0] + b0, acc[nt][1] + b0);
            *(uint32_t*)(v8 + n) = ph2(acc[nt][2] + b8, acc[nt][3] + b8);
        }
    } else {
        const bool isq = (mt == 8);
        const float* bias = isq ? bb : bc;
        __half* dst = isq ? qh : kh;
        const int d = lane >> 2;
        const float b0 = bias[d], b8 = bias[d + 8];
#pragma unroll
        for (int nt = 0; nt < 8; nt++) {
            const int n = n0 + nt * 8 + 2 * (lane & 3);
            __half* p0 = dst + ((size_t)b * NPIX + n) * 16;
            p0[d]      = __float2half(acc[nt][0] + b0);
            p0[16 + d] = __float2half(acc[nt][1] + b0);
            p0[d + 8]      = __float2half(acc[nt][2] + b8);
            p0[16 + d + 8] = __float2half(acc[nt][3] + b8);
        }
    }
}

// ---------------------------------------------------------------------------
// PAM flash attention: q-tile 64, 128-thread CTA, occ 3.  Residual from hi+lo.
// ---------------------------------------------------------------------------
#define ATT_SMEM 46080

__global__ void __launch_bounds__(128, 3) pam_attn_mma(
        const __half* __restrict__ qh, const __half* __restrict__ kh,
        const __half* __restrict__ vd,
        const __half* __restrict__ yhi, const __half* __restrict__ ylo,
        const float* __restrict__ alpha, __half* __restrict__ xp2) {
    extern __shared__ __align__(16) char smc[];
    const uint32_t smb = smem_u32(smc);
    const uint32_t Qb  = smb;
    const uint32_t Kb0 = smb + 3072;
    const uint32_t Vb0 = smb + 9216;

    const int tid = threadIdx.x, lane = tid & 31, wid = tid >> 5;
    const int b = blockIdx.y;
    const int n0 = blockIdx.x * 64;
    const int qbase = wid * 16;

    const int g = lane >> 3, r8 = lane & 7;
    const uint32_t qoff = (uint32_t)(((g & 1) * 8 + r8) * 48 + (g >> 1) * 16);
    const uint32_t koff = (uint32_t)(((g >> 1) * 8 + r8) * 48 + (g & 1) * 16);
    const uint32_t voff = (uint32_t)(((g >> 1) * 8 + r8) * 144 + (g & 1) * 16);

    auto stageKV = [&](int t, int buf) {
        const int k0 = t * 64;
        {
            int row = tid >> 1, h = tid & 1;
            CP_ASYNC16(Kb0 + buf * 3072 + row * 48 + h * 16,
                       kh + ((size_t)b * NPIX + k0 + row) * 16 + h * 8);
        }
#pragma unroll
        for (int t4 = 0; t4 < 8; t4++) {
            int idx = tid + t4 * 128;
            int ch = idx >> 3, c = idx & 7;
            CP_ASYNC16(Vb0 + buf * 18432 + ch * 144 + c * 16,
                       vd + ((size_t)b * 128 + ch) * NPIX + k0 + c * 8);
        }
        CP_COMMIT();
    };

    {
        int row = tid >> 1, h = tid & 1;
        CP_ASYNC16(Qb + row * 48 + h * 16,
                   qh + ((size_t)b * NPIX + n0 + row) * 16 + h * 8);
    }
    stageKV(0, 0);

    uint32_t qfr[4];
    float O[16][4];
#pragma unroll
    for (int nc = 0; nc < 16; nc++)
#pragma unroll
        for (int r = 0; r < 4; r++) O[nc][r] = 0.0f;
    float mrun0 = -1e30f, mrun1 = -1e30f, lrun0 = 0.0f, lrun1 = 0.0f;

    for (int t = 0; t < 64; t++) {
        const int buf = t & 1;
        CP_WAIT(0);
        __syncthreads();
        if (t + 1 < 64) stageKV(t + 1, buf ^ 1);
        if (t == 0) ldsm4(qfr, Qb + qbase * 48 + qoff);

        const uint32_t Kb = Kb0 + buf * 3072;
        const uint32_t Vb = Vb0 + buf * 18432;

        float S[8][4];
#pragma unroll
        for (int ks = 0; ks < 4; ks++) {
            uint32_t kb[4];
            ldsm4(kb, Kb + ks * 768 + koff);
#pragma unroll
            for (int r = 0; r < 4; r++) { S[2 * ks][r] = 0.0f; S[2 * ks + 1][r] = 0.0f; }
            mma_f16(S[2 * ks],     qfr, kb[0], kb[1]);
            mma_f16(S[2 * ks + 1], qfr, kb[2], kb[3]);
        }

        float tm0 = -1e30f, tm1 = -1e30f;
#pragma unroll
        for (int nt = 0; nt < 8; nt++) {
            tm0 = fmaxf(tm0, fmaxf(S[nt][0], S[nt][1]));
            tm1 = fmaxf(tm1, fmaxf(S[nt][2], S[nt][3]));
        }
        tm0 = fmaxf(tm0, __shfl_xor_sync(0xffffffffu, tm0, 1));
        tm0 = fmaxf(tm0, __shfl_xor_sync(0xffffffffu, tm0, 2));
        tm1 = fmaxf(tm1, __shfl_xor_sync(0xffffffffu, tm1, 1));
        tm1 = fmaxf(tm1, __shfl_xor_sync(0xffffffffu, tm1, 2));
        const float mn0 = fmaxf(mrun0, tm0), mn1 = fmaxf(mrun1, tm1);
        const float f0 = __expf(mrun0 - mn0), f1 = __expf(mrun1 - mn1);
        mrun0 = mn0; mrun1 = mn1;

        float ts0 = 0.0f, ts1 = 0.0f;
        uint32_t afr[4][4];
#pragma unroll
        for (int j = 0; j < 4; j++) {
            float p00 = __expf(S[2 * j][0] - mn0), p01 = __expf(S[2 * j][1] - mn0);
            float p10 = __expf(S[2 * j][2] - mn1), p11 = __expf(S[2 * j][3] - mn1);
            float q00 = __expf(S[2 * j + 1][0] - mn0), q01 = __expf(S[2 * j + 1][1] - mn0);
            float q10 = __expf(S[2 * j + 1][2] - mn1), q11 = __expf(S[2 * j + 1][3] - mn1);
            ts0 += (p00 + p01) + (q00 + q01);
            ts1 += (p10 + p11) + (q10 + q11);
            afr[j][0] = ph2(p00, p01);
            afr[j][1] = ph2(p10, p11);
            afr[j][2] = ph2(q00, q01);
            afr[j][3] = ph2(q10, q11);
        }
        ts0 += __shfl_xor_sync(0xffffffffu, ts0, 1);
        ts0 += __shfl_xor_sync(0xffffffffu, ts0, 2);
        ts1 += __shfl_xor_sync(0xffffffffu, ts1, 1);
        ts1 += __shfl_xor_sync(0xffffffffu, ts1, 2);
        lrun0 = lrun0 * f0 + ts0;
        lrun1 = lrun1 * f1 + ts1;

#pragma unroll
        for (int nc = 0; nc < 16; nc++) {
            O[nc][0] *= f0; O[nc][1] *= f0;
            O[nc][2] *= f1; O[nc][3] *= f1;
        }

#pragma unroll
        for (int j = 0; j < 4; j++) {
            const uint32_t vb_j = Vb + j * 32 + voff;
#pragma unroll
            for (int p = 0; p < 8; p++) {
                uint32_t vb[4];
                ldsm4(vb, vb_j + p * 2304);
                mma_f16(O[2 * p],     afr[j], vb[0], vb[1]);
                mma_f16(O[2 * p + 1], afr[j], vb[2], vb[3]);
            }
        }
    }

    const float linv0 = 1.0f / lrun0, linv1 = 1.0f / lrun1;
    const float a = alpha[0];
    const int px0 = n0 + qbase + (lane >> 2);
    const int px1 = px0 + 8;
    __half* dst0 = xp2 + (((size_t)b * XP_H + (px0 >> 6) + 1) * XP_H + (px0 & 63) + 1) * CI;
    __half* dst1 = xp2 + (((size_t)b * XP_H + (px1 >> 6) + 1) * XP_H + (px1 & 63) + 1) * CI;
#pragma unroll
    for (int nc = 0; nc < 16; nc++) {
        const int ch = nc * 8 + 2 * (lane & 3);
        const __half* hp = yhi + ((size_t)b * 128 + ch) * NPIX;
        const __half* lp = ylo + ((size_t)b * 128 + ch) * NPIX;
        float ya0 = __half2float(hp[px0]) + __half2float(lp[px0]);
        float yb0 = __half2float(hp[NPIX + px0]) + __half2float(lp[NPIX + px0]);
        float ya1 = __half2float(hp[px1]) + __half2float(lp[px1]);
        float yb1 = __half2float(hp[NPIX + px1]) + __half2float(lp[NPIX + px1]);
        *(uint32_t*)(dst0 + ch) = ph2(fmaf(a, O[nc][0] * linv0, ya0),
                                      fmaf(a, O[nc][1] * linv0, yb0));
        *(uint32_t*)(dst1 + ch) = ph2(fmaf(a, O[nc][2] * linv1, ya1),
                                      fmaf(a, O[nc][3] * linv1, yb1));
    }
}

// ---------------------------------------------------------------------------
// CAM gram matrix via fp16 hi/lo split MMA, split-K partials.
// ---------------------------------------------------------------------------
#define CAME_SMEM 36864

__global__ void __launch_bounds__(256, 2) cam_energy_mma(
        const __half* __restrict__ yhi, const __half* __restrict__ ylo,
        float* __restrict__ epart) {
    extern __shared__ __align__(16) char smc[];
    const uint32_t smb = smem_u32(smc);
    const int tid = threadIdx.x, lane = tid & 31, wid = tid >> 5;
    const int warp_m = wid >> 2, warp_n = wid & 3;
    const int b = blockIdx.y, ksid = blockIdx.x;
    const int g = lane >> 3, r8 = lane & 7;

    float acc[4][4][4];
#pragma unroll
    for (int mt = 0; mt < 4; mt++)
#pragma unroll
        for (int nt = 0; nt < 4; nt++)
#pragma unroll
            for (int r = 0; r < 4; r++) acc[mt][nt][r] = 0.0f;

    for (int chunk = 0; chunk < 4; chunk++) {
        const int k0 = ksid * 256 + chunk * 64;
        __syncthreads();
#pragma unroll
        for (int t = 0; t < 4; t++) {
            int idx = tid + t * 256;
            int ch = idx >> 3, seg = idx & 7;
            CP_ASYNC16(smb + ch * 144 + seg * 16,
                       yhi + ((size_t)b * 128 + ch) * NPIX + k0 + seg * 8);
            CP_ASYNC16(smb + 18432 + ch * 144 + seg * 16,
                       ylo + ((size_t)b * 128 + ch) * NPIX + k0 + seg * 8);
        }
        CP_COMMIT();
        CP_WAIT(0);
        __syncthreads();

#pragma unroll
        for (int ks = 0; ks < 4; ks++) {
            uint32_t ahi[4][4], alo[4][4];
#pragma unroll
            for (int mt = 0; mt < 4; mt++) {
                const uint32_t arow = (warp_m * 64 + mt * 16 + (g & 1) * 8 + r8) * 144
                                      + ks * 32 + (g >> 1) * 16;
                ldsm4(ahi[mt], smb + arow);
                ldsm4(alo[mt], smb + 18432 + arow);
            }
            uint32_t bhi[2][4], blo[2][4];
#pragma unroll
            for (int t16 = 0; t16 < 2; t16++) {
                const uint32_t brow = (warp_n * 32 + t16 * 16 + (g >> 1) * 8 + r8) * 144
                                      + ks * 32 + (g & 1) * 16;
                ldsm4(bhi[t16], smb + brow);
                ldsm4(blo[t16], smb + 18432 + brow);
            }
#pragma unroll
            for (int mt = 0; mt < 4; mt++)
#pragma unroll
                for (int t16 = 0; t16 < 2; t16++) {
                    mma_f16(acc[mt][2 * t16],     ahi[mt], bhi[t16][0], bhi[t16][1]);
                    mma_f16(acc[mt][2 * t16 + 1], ahi[mt], bhi[t16][2], bhi[t16][3]);
                    mma_f16(acc[mt][2 * t16],     ahi[mt], blo[t16][0], blo[t16][1]);
                    mma_f16(acc[mt][2 * t16 + 1], ahi[mt], blo[t16][2], blo[t16][3]);
                    mma_f16(acc[mt][2 * t16],     alo[mt], bhi[t16][0], bhi[t16][1]);
                    mma_f16(acc[mt][2 * t16 + 1], alo[mt], bhi[t16][2], bhi[t16][3]);
                }
        }
    }

    float* ep = epart + (((size_t)ksid * BATCH + b) * 128) * 128;
#pragma unroll
    for (int mt = 0; mt < 4; mt++) {
        const int c0 = warp_m * 64 + mt * 16 + (lane >> 2);
#pragma unroll
        for (int nt = 0; nt < 4; nt++) {
            const int d = warp_n * 32 + nt * 8 + 2 * (lane & 3);
            *(float2*)(ep + (size_t)c0 * 128 + d) = make_float2(acc[mt][nt][0], acc[mt][nt][1]);
            *(float2*)(ep + (size_t)(c0 + 8) * 128 + d) = make_float2(acc[mt][nt][2], acc[mt][nt][3]);
        }
    }
}

// ---------------------------------------------------------------------------
// CAM softmax of (rowmax - E), reducing the KSPLIT partials -> fp16 attn
// ---------------------------------------------------------------------------
__global__ void cam_softmax_kernel(const float* __restrict__ epart,
                                   __half* __restrict__ attn) {
    const int row = blockIdx.x;
    const int tid = threadIdx.x;
    __shared__ float red[4];

    float e = 0.0f;
#pragma unroll
    for (int s = 0; s < KSPLIT; s++)
        e += epart[((size_t)s * 1024 + row) * 128 + tid];

    float m = e;
#pragma unroll
    for (int off = 16; off; off >>= 1) m = fmaxf(m, __shfl_xor_sync(0xffffffff, m, off));
    if ((tid & 31) == 0) red[tid >> 5] = m;
    __syncthreads();
    float mx = fmaxf(fmaxf(red[0], red[1]), fmaxf(red[2], red[3]));
    float e2 = mx - e;
    __syncthreads();

    float m2 = e2;
#pragma unroll
    for (int off = 16; off; off >>= 1) m2 = fmaxf(m2, __shfl_xor_sync(0xffffffff, m2, off));
    if ((tid & 31) == 0) red[tid >> 5] = m2;
    __syncthreads();
    m2 = fmaxf(fmaxf(red[0], red[1]), fmaxf(red[2], red[3]));
    float p = __expf(e2 - m2);
    __syncthreads();

    float s = p;
#pragma unroll
    for (int off = 16; off; off >>= 1) s += __shfl_xor_sync(0xffffffff, s, off);
    if ((tid & 31) == 0) red[tid >> 5] = s;
    __syncthreads();
    s = red[0] + red[1] + red[2] + red[3];

    attn[(size_t)row * 128 + tid] = __float2half(p / s);
}

// ---------------------------------------------------------------------------
// CAM feature via fp16 MMA -> fp16 padded NHWC; residual from hi+lo.
// ---------------------------------------------------------------------------
#define CAMF_SMEM 53248

__global__ void __launch_bounds__(256, 1) cam_feat_mma(
        const __half* __restrict__ attn16,
        const __half* __restrict__ yhi, const __half* __restrict__ ylo,
        const float* __restrict__ beta, __half* __restrict__ xp2) {
    extern __shared__ __align__(16) char smc[];
    const uint32_t smb = smem_u32(smc);
    const int tid = threadIdx.x, lane = tid & 31, wid = tid >> 5;
    const int b = blockIdx.y;
    const int n0 = blockIdx.x * 64;
    const int g = lane >> 3;

#pragma unroll
    for (int t = 0; t < 8; t++) {
        int idx = tid + t * 256;
        int c = idx >> 4, seg = idx & 15;
        CP_ASYNC16(smb + c * 272 + seg * 16,
                   attn16 + ((size_t)b * 128 + c) * 128 + seg * 8);
    }
#pragma unroll
    for (int t = 0; t < 4; t++) {
        int idx = tid + t * 256;
        int ch = idx >> 3, seg = idx & 7;
        CP_ASYNC16(smb + 34816 + ch * 144 + seg * 16,
                   yhi + ((size_t)b * 128 + ch) * NPIX + n0 + seg * 8);
    }
    CP_COMMIT();
    CP_WAIT(0);
    __syncthreads();

    const int mt = wid;
    float acc[8][4];
#pragma unroll
    for (int nt = 0; nt < 8; nt++)
#pragma unroll
        for (int r = 0; r < 4; r++) acc[nt][r] = 0.0f;

    const uint32_t Bsm = smb + 34816;
#pragma unroll
    for (int ks = 0; ks < 8; ks++) {
        uint32_t afr[4];
        ldsm4(afr, smb + (mt * 16 + (g & 1) * 8 + (lane & 7)) * 272
                  + ks * 32 + (g >> 1) * 16);
#pragma unroll
        for (int t16 = 0; t16 < 4; t16++) {
            uint32_t bfr[4];
            ldsm4t(bfr, Bsm + (ks * 16 + (g & 1) * 8 + (lane & 7)) * 144
                       + (t16 * 16 + (g >> 1) * 8) * 2);
            mma_f16(acc[2 * t16],     afr, bfr[0], bfr[1]);
            mma_f16(acc[2 * t16 + 1], afr, bfr[2], bfr[3]);
        }
    }

    const float bet = beta[0];
    const int c0 = mt * 16 + (lane >> 2);
#pragma unroll
    for (int nt = 0; nt < 8; nt++) {
        const int n = n0 + nt * 8 + 2 * (lane & 3);
        const __half* h0p = yhi + ((size_t)b * 128 + c0) * NPIX;
        const __half* l0p = ylo + ((size_t)b * 128 + c0) * NPIX;
        float y00 = __half2float(h0p[n]) + __half2float(l0p[n]);
        float y01 = __half2float(h0p[n + 1]) + __half2float(l0p[n + 1]);
        float y80 = __half2float(h0p[8 * NPIX + n]) + __half2float(l0p[8 * NPIX + n]);
        float y81 = __half2float(h0p[8 * NPIX + n + 1]) + __half2float(l0p[8 * NPIX + n + 1]);
        __half* p0 = xp2 + (((size_t)b * XP_H + (n >> 6) + 1) * XP_H + (n & 63) + 1) * CI;
        __half* p1 = p0 + CI;
        p0[c0]     = __float2half(fmaf(bet, acc[nt][0], y00));
        p1[c0]     = __float2half(fmaf(bet, acc[nt][1], y01));
        p0[c0 + 8] = __float2half(fmaf(bet, acc[nt][2], y80));
        p1[c0 + 8] = __float2half(fmaf(bet, acc[nt][3], y81));
    }
}

// ---------------------------------------------------------------------------
// Final heads via one fused fp16 MMA:  A[64x256] @ [fp;fc](256 x 64px tile).
// ---------------------------------------------------------------------------
#define FIN_SMEM 69632

__global__ void __launch_bounds__(128, 2) final_mma(
        const __half* __restrict__ wfin,
        const __half* __restrict__ fp, const __half* __restrict__ fc,
        const float* __restrict__ bout, const float* __restrict__ bp3,
        const float* __restrict__ bc3, float* __restrict__ out) {
    extern __shared__ __align__(16) char smc[];
    const uint32_t smb = smem_u32(smc);
    const int tid = threadIdx.x, lane = tid & 31, wid = tid >> 5;
    const int b = blockIdx.y;
    const int n0 = blockIdx.x * 64;
    const int g = lane >> 3;

#pragma unroll
    for (int t = 0; t < 16; t++) {
        int i = tid + t * 128;
        CP_ASYNC16(smb + i * 16, wfin + i * 8);
    }
#pragma unroll
    for (int t = 0; t < 16; t++) {
        int idx = tid + t * 128;
        int ch = idx >> 3, seg = idx & 7;
        const __half* src = (ch < 128)
            ? fp + ((size_t)b * 128 + ch) * NPIX + n0 + seg * 8
            : fc + ((size_t)b * 128 + (ch - 128)) * NPIX + n0 + seg * 8;
        CP_ASYNC16(smb + 32768 + ch * 144 + seg * 16, src);
    }
    CP_COMMIT();
    CP_WAIT(0);
    __syncthreads();

    const int mt = wid;
    float acc[8][4];
#pragma unroll
    for (int nt = 0; nt < 8; nt++)
#pragma unroll
        for (int r = 0; r < 4; r++) acc[nt][r] = 0.0f;

    const char* Aptr = smc;
    const uint32_t Bsm = smb + 32768;
#pragma unroll
    for (int ks = 0; ks < 16; ks++) {
        uint4 v = *(const uint4*)(Aptr + (((mt * 16 + ks) * 32 + lane) << 4));
        uint32_t afr[4] = {v.x, v.y, v.z, v.w};
#pragma unroll
        for (int t16 = 0; t16 < 4; t16++) {
            uint32_t bfr[4];
            ldsm4t(bfr, Bsm + (ks * 16 + (g & 1) * 8 + (lane & 7)) * 144
                       + (t16 * 16 + (g >> 1) * 8) * 2);
            mma_f16(acc[2 * t16],     afr, bfr[0], bfr[1]);
            mma_f16(acc[2 * t16 + 1], afr, bfr[2], bfr[3]);
        }
    }

    const size_t SEG = (size_t)BATCH * NC * NPIX;
    auto emit = [&](int row, int px, float v) {
        if (row >= 57) return;
        float bias;
        size_t base;
        if (row < 19)      { bias = bout[row]; base = ((size_t)b * NC + row) * NPIX; }
        else if (row < 38) { bias = bp3[row - 19]; base = SEG + ((size_t)b * NC + row - 19) * NPIX; }
        else               { bias = bc3[row - 38]; base = 2 * SEG + ((size_t)b * NC + row - 38) * NPIX; }
        out[base + px] = sigmoidf_(v + bias);
    };

    const int r0 = mt * 16 + (lane >> 2);
#pragma unroll
    for (int nt = 0; nt < 8; nt++) {
        const int px = n0 + nt * 8 + 2 * (lane & 3);
        emit(r0,     px,     acc[nt][0]);
        emit(r0,     px + 1, acc[nt][1]);
        emit(r0 + 8, px,     acc[nt][2]);
        emit(r0 + 8, px + 1, acc[nt][3]);
    }
}

// ---------------------------------------------------------------------------
// Streams / events (created once at program load)
// ---------------------------------------------------------------------------
namespace {
struct StreamInit {
    cudaStream_t s1;
    cudaEvent_t e0, e1, e2, e3, e4, e5;
    StreamInit() {
        cudaStreamCreateWithFlags(&s1, cudaStreamNonBlocking);
        cudaEventCreateWithFlags(&e0, cudaEventDisableTiming);
        cudaEventCreateWithFlags(&e1, cudaEventDisableTiming);
        cudaEventCreateWithFlags(&e2, cudaEventDisableTiming);
        cudaEventCreateWithFlags(&e3, cudaEventDisableTiming);
        cudaEventCreateWithFlags(&e4, cudaEventDisableTiming);
        cudaEventCreateWithFlags(&e5, cudaEventDisableTiming);
    }
};
StreamInit g_str;
}

// ---------------------------------------------------------------------------
// Launch
// ---------------------------------------------------------------------------
extern "C" void kernel_launch(void* const* d_in, const int* in_sizes, int n_in,
                              void* d_out, int out_size) {
    const float* x    = (const float*)d_in[0];
    const float* Wp1  = (const float*)d_in[1];
    const float* bnp1 = (const float*)d_in[2];
    const float* Wc1  = (const float*)d_in[3];
    const float* bnc1 = (const float*)d_in[4];
    const float* Wb   = (const float*)d_in[5];
    const float* bb   = (const float*)d_in[6];
    const float* Wc   = (const float*)d_in[7];
    const float* bc   = (const float*)d_in[8];
    const float* Wd   = (const float*)d_in[9];
    const float* bd   = (const float*)d_in[10];
    const float* alpha= (const float*)d_in[11];
    const float* beta = (const float*)d_in[12];
    const float* Wp2  = (const float*)d_in[13];
    const float* bnp2 = (const float*)d_in[14];
    const float* Wc2  = (const float*)d_in[15];
    const float* bnc2 = (const float*)d_in[16];
    const float* Wout = (const float*)d_in[17];
    const float* bout = (const float*)d_in[18];
    const float* Wp3  = (const float*)d_in[19];
    const float* bp3  = (const float*)d_in[20];
    const float* Wc3  = (const float*)d_in[21];
    const float* bc3  = (const float*)d_in[22];
    float* out = (float*)d_out;

    float* epart;
    __half *featp1h, *featp1lo, *featc1h, *featc1lo, *qh, *kh, *vd, *attn16;
    __half *xpad, *xp2a, *xp2b, *wf1, *wf2, *wqkv, *wfin;
    cudaGetSymbolAddress((void**)&featp1h,  g_featp1h);
    cudaGetSymbolAddress((void**)&featp1lo, g_featp1lo);
    cudaGetSymbolAddress((void**)&featc1h,  g_featc1h);
    cudaGetSymbolAddress((void**)&featc1lo, g_featc1lo);
    cudaGetSymbolAddress((void**)&qh,       g_qh);
    cudaGetSymbolAddress((void**)&kh,       g_kh);
    cudaGetSymbolAddress((void**)&vd,       g_vd);
    cudaGetSymbolAddress((void**)&epart,    g_epart);
    cudaGetSymbolAddress((void**)&attn16,   g_attn16);
    cudaGetSymbolAddress((void**)&xpad,     g_xpad);
    cudaGetSymbolAddress((void**)&xp2a,     g_xp2a);
    cudaGetSymbolAddress((void**)&xp2b,     g_xp2b);
    cudaGetSymbolAddress((void**)&wf1,      g_wf16_1);
    cudaGetSymbolAddress((void**)&wf2,      g_wf16_2);
    cudaGetSymbolAddress((void**)&wqkv,     g_wqkv);
    cudaGetSymbolAddress((void**)&wfin,     g_wfinal);

    cudaFuncSetAttribute(conv_mma_kernel<512>,
                         cudaFuncAttributeMaxDynamicSharedMemorySize, CONV_SMEM);
    cudaFuncSetAttribute(conv_mma_kernel<128>,
                         cudaFuncAttributeMaxDynamicSharedMemorySize, CONV_SMEM);
    cudaFuncSetAttribute(pam_attn_mma,
                         cudaFuncAttributeMaxDynamicSharedMemorySize, ATT_SMEM);
    cudaFuncSetAttribute(pam_attn_mma,
                         cudaFuncAttributePreferredSharedMemoryCarveout, 100);
    cudaFuncSetAttribute(qkv_kernel,
                         cudaFuncAttributeMaxDynamicSharedMemorySize, QKV_SMEM);
    cudaFuncSetAttribute(cam_energy_mma,
                         cudaFuncAttributeMaxDynamicSharedMemorySize, CAME_SMEM);
    cudaFuncSetAttribute(cam_feat_mma,
                         cudaFuncAttributeMaxDynamicSharedMemorySize, CAMF_SMEM);
    cudaFuncSetAttribute(final_mma,
                         cudaFuncAttributeMaxDynamicSharedMemorySize, FIN_SMEM);

    cudaStream_t s1 = g_str.s1;

    // Fork s1 off the main stream
    cudaEventRecord(g_str.e0, 0);
    cudaStreamWaitEvent(s1, g_str.e0, 0);

    // s0: interior packing
    pack_x_kernel<<<dim3(64, BATCH), 256>>>(x, xpad);
    cudaEventRecord(g_str.e5, 0);   // pack_x done

    // s1: borders + weight packing (parallel with pack_x)
    zero_border_h<<<dim3(XP_H, BATCH), 256, 0, s1>>>(xpad, CIN);
    pack_w16<<<dim3(144, 2), 256, 0, s1>>>(Wp1, Wc1, wf1, CIN);
    cudaEventRecord(g_str.e1, s1);  // xpad border + wf1 ready
    zero_border_h<<<dim3(XP_H, BATCH), 256, 0, s1>>>(xp2a, CI);
    zero_border_h<<<dim3(XP_H, BATCH), 256, 0, s1>>>(xp2b, CI);
    pack_wqkv<<<1, 256, 0, s1>>>(Wd, Wb, Wc, wqkv);
    pack_w16<<<dim3(36, 2), 256, 0, s1>>>(Wp2, Wc2, wf2, CI);
    pack_wfinal<<<1, 256, 0, s1>>>(Wout, Wp3, Wc3, wfin);
    cudaEventRecord(g_str.e4, s1);  // wqkv/wf2/wfinal/xp2 borders ready

    // s0: conv1-PAM FIRST (alone at full chip rate)
    cudaStreamWaitEvent(0, g_str.e1, 0);
    conv_mma_kernel<512><<<dim3(32, BATCH, 1), 256, CONV_SMEM>>>(
        xpad, xpad, wf1, bnp1, bnp1, featp1h, featp1h, featp1lo, featp1lo);
    cudaEventRecord(g_str.e2, 0);   // conv1-PAM done

    // s1: conv1-CAM + entire CAM chain (runs concurrent with the PAM chain)
    cudaStreamWaitEvent(s1, g_str.e2, 0);
    cudaStreamWaitEvent(s1, g_str.e5, 0);
    conv_mma_kernel<512><<<dim3(32, BATCH, 1), 256, CONV_SMEM, s1>>>(
        xpad, xpad, wf1 + 144 * 4096, bnc1, bnc1, featc1h, featc1h, featc1lo, featc1lo);
    cam_energy_mma<<<dim3(KSPLIT, BATCH), 256, CAME_SMEM, s1>>>(featc1h, featc1lo, epart);
    cam_softmax_kernel<<<BATCH * 128, 128, 0, s1>>>(epart, attn16);
    cam_feat_mma<<<dim3(64, BATCH), 256, CAMF_SMEM, s1>>>(
        attn16, featc1h, featc1lo, beta, xp2b);
    conv_mma_kernel<128><<<dim3(32, BATCH, 1), 256, CONV_SMEM, s1>>>(
        xp2b, xp2b, wf2 + 36 * 4096, bnc2, bnc2, featc1h, featc1h, nullptr, nullptr);
    cudaEventRecord(g_str.e3, s1);  // CAM branch fully done

    // s0: PAM chain (qkv needs wqkv -> wait e4)
    cudaStreamWaitEvent(0, g_str.e4, 0);
    qkv_kernel<<<dim3(64, BATCH), 320, QKV_SMEM>>>(
        wqkv, featp1h, bd, bb, bc, vd, qh, kh);
    pam_attn_mma<<<dim3(64, BATCH), 128, ATT_SMEM>>>(
        qh, kh, vd, featp1h, featp1lo, alpha, xp2a);
    conv_mma_kernel<128><<<dim3(32, BATCH, 1), 256, CONV_SMEM>>>(
        xp2a, xp2a, wf2, bnp2, bnp2, featp1h, featp1h, nullptr, nullptr);

    // Join, then fused final heads
    cudaStreamWaitEvent(0, g_str.e3, 0);
    final_mma<<<dim3(64, BATCH), 128, FIN_SMEM>>>(
        wfin, featp1h, featc1h, bout, bp3, bc3, out);
}